// round 1
// baseline (speedup 1.0000x reference)
#include <cuda_runtime.h>
#include <math.h>

#define HIDDEN 768
#define NTOK   4096
#define QDIM   1024
#define VOCAB  30522
#define NANG   20

// Scratch (device globals: allocation-free per harness rules)
__device__ float g_H[NTOK * HIDDEN];      // post-GELU dense output
__device__ float g_probs[NTOK * QDIM];    // quantum probabilities

// ---------------------------------------------------------------------------
// Tiled fp32 GEMM: C[M,N] = A[M,K] @ B[K,N] + bias (optionally GELU).
// BM=BN=64, BK=16, 256 threads (16x16), 4x4 micro-tile per thread.
// M and K must be multiples of 64/16 (true here); N bounds-checked.
// ---------------------------------------------------------------------------
template <bool DOGELU>
__global__ void sgemm_kernel(const float* __restrict__ A,
                             const float* __restrict__ B,
                             const float* __restrict__ bias,
                             float* __restrict__ C,
                             int M, int N, int K) {
    constexpr int BM = 64, BN = 64, BK = 16;
    __shared__ __align__(16) float As[BK][BM + 4];  // +4 pad keeps 16B alignment, kills conflicts
    __shared__ __align__(16) float Bs[BK][BN];

    const int tx = threadIdx.x, ty = threadIdx.y;
    const int tid = ty * 16 + tx;
    const int m0 = blockIdx.y * BM;
    const int n0 = blockIdx.x * BN;

    float acc[4][4] = {};

    for (int k0 = 0; k0 < K; k0 += BK) {
        // Load A tile 64x16 (transposed into As[k][m])
        #pragma unroll
        for (int e = 0; e < 4; e++) {
            int lin = e * 256 + tid;
            int c = lin & 15, r = lin >> 4;
            As[c][r] = A[(size_t)(m0 + r) * K + k0 + c];
        }
        // Load B tile 16x64 (coalesced along N)
        #pragma unroll
        for (int e = 0; e < 4; e++) {
            int lin = e * 256 + tid;
            int c = lin & 63, r = lin >> 6;
            int col = n0 + c;
            Bs[r][c] = (col < N) ? B[(size_t)(k0 + r) * N + col] : 0.0f;
        }
        __syncthreads();

        #pragma unroll
        for (int kk = 0; kk < BK; kk++) {
            float4 av = *(const float4*)&As[kk][ty * 4];
            float4 bv = *(const float4*)&Bs[kk][tx * 4];
            float a[4] = {av.x, av.y, av.z, av.w};
            float b[4] = {bv.x, bv.y, bv.z, bv.w};
            #pragma unroll
            for (int i = 0; i < 4; i++)
                #pragma unroll
                for (int j = 0; j < 4; j++)
                    acc[i][j] += a[i] * b[j];
        }
        __syncthreads();
    }

    #pragma unroll
    for (int i = 0; i < 4; i++) {
        int row = m0 + ty * 4 + i;
        #pragma unroll
        for (int j = 0; j < 4; j++) {
            int col = n0 + tx * 4 + j;
            if (col < N) {
                float v = acc[i][j] + bias[col];
                if (DOGELU)
                    v = 0.5f * v * (1.0f + erff(v * 0.70710678118654752f));
                C[(size_t)row * N + col] = v;
            }
        }
    }
}

// ---------------------------------------------------------------------------
// Per-token: LayerNorm -> ent GEMM (768->20) -> sigmoid*2pi -> quantum
// state-vector simulation (2 layers x (10 RX + 10 CNOT)) -> probs.
// One block per token, 256 threads. State (1024 complex fp32) lives in smem.
// Qubit q maps to bit position (9-q).
// ---------------------------------------------------------------------------
__global__ void token_quantum_kernel(const float* __restrict__ ln_w,
                                     const float* __restrict__ ln_b,
                                     const float* __restrict__ ent_w,
                                     const float* __restrict__ ent_b) {
    const int t   = blockIdx.x;
    const int tid = threadIdx.x;
    const int lane = tid & 31;
    const int wrp  = tid >> 5;

    __shared__ float hn[HIDDEN];
    __shared__ float red[16];
    __shared__ float ang[NANG];
    __shared__ float sre[QDIM];
    __shared__ float smi[QDIM];

    const float* hrow = g_H + (size_t)t * HIDDEN;

    // ---- mean ----
    float lsum = 0.0f;
    for (int k = tid; k < HIDDEN; k += 256) {
        float v = hrow[k];
        hn[k] = v;
        lsum += v;
    }
    #pragma unroll
    for (int o = 16; o; o >>= 1) lsum += __shfl_xor_sync(0xffffffffu, lsum, o);
    if (lane == 0) red[wrp] = lsum;
    __syncthreads();
    float mean = 0.0f;
    #pragma unroll
    for (int w = 0; w < 8; w++) mean += red[w];
    mean *= (1.0f / HIDDEN);

    // ---- variance ----
    float lsq = 0.0f;
    for (int k = tid; k < HIDDEN; k += 256) {
        float d = hn[k] - mean;
        lsq += d * d;
    }
    #pragma unroll
    for (int o = 16; o; o >>= 1) lsq += __shfl_xor_sync(0xffffffffu, lsq, o);
    if (lane == 0) red[8 + wrp] = lsq;
    __syncthreads();
    float var = 0.0f;
    #pragma unroll
    for (int w = 0; w < 8; w++) var += red[8 + w];
    var *= (1.0f / HIDDEN);
    float rstd = rsqrtf(var + 1e-12f);

    // ---- normalize ----
    for (int k = tid; k < HIDDEN; k += 256)
        hn[k] = ln_w[k] * ((hn[k] - mean) * rstd) + ln_b[k];
    __syncthreads();

    // ---- ent projection (768 -> 20) + sigmoid * 2pi ----
    for (int j = wrp; j < NANG; j += 8) {
        float acc = 0.0f;
        for (int k = lane; k < HIDDEN; k += 32)
            acc += hn[k] * ent_w[(size_t)k * NANG + j];
        #pragma unroll
        for (int o = 16; o; o >>= 1) acc += __shfl_xor_sync(0xffffffffu, acc, o);
        if (lane == 0) {
            float z = acc + ent_b[j];
            ang[j] = 6.28318530717958647692f / (1.0f + expf(-z));
        }
    }
    __syncthreads();

    // ---- init |0...0> ----
    for (int i = tid; i < QDIM; i += 256) {
        sre[i] = (i == 0) ? 1.0f : 0.0f;
        smi[i] = 0.0f;
    }
    __syncthreads();

    // ---- 2 layers ----
    #pragma unroll 1
    for (int l = 0; l < 2; l++) {
        // RX gates
        #pragma unroll 1
        for (int q = 0; q < 10; q++) {
            float th = ang[l * 10 + q] * 0.5f;
            float sth, cth;
            sincosf(th, &sth, &cth);
            int pos = 9 - q;
            int lowmask = (1 << pos) - 1;
            #pragma unroll
            for (int pp = 0; pp < 2; pp++) {
                int p = tid + pp * 256;
                int i0 = ((p & ~lowmask) << 1) | (p & lowmask);
                int i1 = i0 | (1 << pos);
                float a0r = sre[i0], a0i = smi[i0];
                float a1r = sre[i1], a1i = smi[i1];
                // b0 = c*a0 - i*s*a1 ; b1 = c*a1 - i*s*a0
                sre[i0] = cth * a0r + sth * a1i;
                smi[i0] = cth * a0i - sth * a1r;
                sre[i1] = cth * a1r + sth * a0i;
                smi[i1] = cth * a1i - sth * a0r;
            }
            __syncthreads();
        }
        // CNOT ring: control q, target (q+1)%10. Involution: swap i <-> i^tmask
        // for indices with ctrl bit set; enumerate ctrl=1,target=0 (256 indices).
        #pragma unroll 1
        for (int q = 0; q < 10; q++) {
            int tq   = (q + 1) % 10;
            int cpos = 9 - q;
            int tpos = 9 - tq;
            int lo = cpos < tpos ? cpos : tpos;
            int hi = cpos > tpos ? cpos : tpos;
            int x = tid;
            x = ((x >> lo) << (lo + 1)) | (x & ((1 << lo) - 1));
            x = ((x >> hi) << (hi + 1)) | (x & ((1 << hi) - 1));
            int i  = x | (1 << cpos);       // ctrl=1, target=0
            int j2 = i | (1 << tpos);       // partner
            float tr = sre[i]; sre[i] = sre[j2]; sre[j2] = tr;
            float ti = smi[i]; smi[i] = smi[j2]; smi[j2] = ti;
            __syncthreads();
        }
    }

    // ---- probs ----
    float* prow = g_probs + (size_t)t * QDIM;
    for (int i = tid; i < QDIM; i += 256) {
        float r = sre[i], im = smi[i];
        prow[i] = r * r + im * im;
    }
}

// ---------------------------------------------------------------------------
extern "C" void kernel_launch(void* const* d_in, const int* in_sizes, int n_in,
                              void* d_out, int out_size) {
    const float* hidden  = (const float*)d_in[0];
    const float* dense_w = (const float*)d_in[1];
    const float* dense_b = (const float*)d_in[2];
    const float* ln_w    = (const float*)d_in[3];
    const float* ln_b    = (const float*)d_in[4];
    const float* ent_w   = (const float*)d_in[5];
    const float* ent_b   = (const float*)d_in[6];
    const float* proj_w  = (const float*)d_in[7];
    const float* proj_b  = (const float*)d_in[8];
    float* out = (float*)d_out;

    float* Hptr = nullptr;
    float* Pptr = nullptr;
    cudaGetSymbolAddress((void**)&Hptr, g_H);
    cudaGetSymbolAddress((void**)&Pptr, g_probs);

    dim3 blk(16, 16);

    // 1) dense + GELU : (4096x768) @ (768x768)
    sgemm_kernel<true><<<dim3(HIDDEN / 64, NTOK / 64), blk>>>(
        hidden, dense_w, dense_b, Hptr, NTOK, HIDDEN, HIDDEN);

    // 2) LN + ent + sigmoid + quantum sim -> probs
    token_quantum_kernel<<<NTOK, 256>>>(ln_w, ln_b, ent_w, ent_b);

    // 3) proj : (4096x1024) @ (1024x30522) + bias
    sgemm_kernel<false><<<dim3((VOCAB + 63) / 64, NTOK / 64), blk>>>(
        Pptr, proj_w, proj_b, out, NTOK, VOCAB, QDIM);
}

// round 5
// speedup vs baseline: 2.8105x; 2.8105x over previous
#include <cuda_runtime.h>
#include <cuda_bf16.h>
#include <math.h>
#include <stdint.h>

#define HIDDEN 768
#define NTOK   4096
#define QDIM   1024
#define VOCAB  30522
#define VOCAB_PAD 30720
#define NANG   20

// ---------------- device scratch (allocation-free) ----------------
__device__ float         g_H[NTOK * HIDDEN];           // post-GELU dense output
__device__ __nv_bfloat16 g_A_hi[NTOK * QDIM];          // probs hi
__device__ __nv_bfloat16 g_A_lo[NTOK * QDIM];          // probs lo
__device__ __nv_bfloat16 g_Wt_hi[VOCAB_PAD * QDIM];    // proj_w^T hi (K-major)
__device__ __nv_bfloat16 g_Wt_lo[VOCAB_PAD * QDIM];    // proj_w^T lo

// ---------------- portable PTX helpers (no sm_103a features) ----------------
static __device__ __forceinline__ uint32_t smem_u32(const void* p) {
    uint32_t a;
    asm("{ .reg .u64 t; cvta.to.shared.u64 t, %1; cvt.u32.u64 %0, t; }" : "=r"(a) : "l"(p));
    return a;
}
static __device__ __forceinline__ void cp_async16(uint32_t dst, const void* src) {
    asm volatile("cp.async.cg.shared.global [%0], [%1], 16;" :: "r"(dst), "l"(src) : "memory");
}
static __device__ __forceinline__ void cp_commit() {
    asm volatile("cp.async.commit_group;" ::: "memory");
}
static __device__ __forceinline__ void cp_wait1() {
    asm volatile("cp.async.wait_group 1;" ::: "memory");
}
static __device__ __forceinline__ void ldsm_x4(uint32_t* r, uint32_t addr) {
    asm volatile("ldmatrix.sync.aligned.m8n8.x4.shared.b16 {%0,%1,%2,%3}, [%4];"
                 : "=r"(r[0]), "=r"(r[1]), "=r"(r[2]), "=r"(r[3]) : "r"(addr));
}
static __device__ __forceinline__ void ldsm_x2(uint32_t* r, uint32_t addr) {
    asm volatile("ldmatrix.sync.aligned.m8n8.x2.shared.b16 {%0,%1}, [%2];"
                 : "=r"(r[0]), "=r"(r[1]) : "r"(addr));
}
static __device__ __forceinline__ void mma_bf16(float* d, const uint32_t* a, const uint32_t* b) {
    asm volatile(
        "mma.sync.aligned.m16n8k16.row.col.f32.bf16.bf16.f32 "
        "{%0,%1,%2,%3}, {%4,%5,%6,%7}, {%8,%9}, {%0,%1,%2,%3};"
        : "+f"(d[0]), "+f"(d[1]), "+f"(d[2]), "+f"(d[3])
        : "r"(a[0]), "r"(a[1]), "r"(a[2]), "r"(a[3]), "r"(b[0]), "r"(b[1]));
}

// ---------------------------------------------------------------------------
// fp32 tiled GEMM + GELU (dense layer): C = GELU(A@B + bias)
// ---------------------------------------------------------------------------
__global__ void dense_gelu_kernel(const float* __restrict__ A,
                                  const float* __restrict__ B,
                                  const float* __restrict__ bias,
                                  float* __restrict__ C,
                                  int M, int N, int K) {
    constexpr int BK = 16;
    __shared__ __align__(16) float As[BK][64 + 4];
    __shared__ __align__(16) float Bs[BK][64];

    const int tx = threadIdx.x, ty = threadIdx.y;
    const int tid = ty * 16 + tx;
    const int m0 = blockIdx.y * 64;
    const int n0 = blockIdx.x * 64;

    float acc[4][4] = {};

    for (int k0 = 0; k0 < K; k0 += BK) {
        #pragma unroll
        for (int e = 0; e < 4; e++) {
            int lin = e * 256 + tid;
            int c = lin & 15, r = lin >> 4;
            As[c][r] = A[(size_t)(m0 + r) * K + k0 + c];
        }
        #pragma unroll
        for (int e = 0; e < 4; e++) {
            int lin = e * 256 + tid;
            int c = lin & 63, r = lin >> 6;
            Bs[r][c] = B[(size_t)(k0 + r) * N + n0 + c];
        }
        __syncthreads();
        #pragma unroll
        for (int kk = 0; kk < BK; kk++) {
            float4 av = *(const float4*)&As[kk][ty * 4];
            float4 bv = *(const float4*)&Bs[kk][tx * 4];
            float a[4] = {av.x, av.y, av.z, av.w};
            float b[4] = {bv.x, bv.y, bv.z, bv.w};
            #pragma unroll
            for (int i = 0; i < 4; i++)
                #pragma unroll
                for (int j = 0; j < 4; j++)
                    acc[i][j] += a[i] * b[j];
        }
        __syncthreads();
    }
    #pragma unroll
    for (int i = 0; i < 4; i++) {
        int row = m0 + ty * 4 + i;
        #pragma unroll
        for (int j = 0; j < 4; j++) {
            int col = n0 + tx * 4 + j;
            float v = acc[i][j] + bias[col];
            v = 0.5f * v * (1.0f + erff(v * 0.70710678118654752f));
            C[(size_t)row * N + col] = v;
        }
    }
}

// ---------------------------------------------------------------------------
// Per-token LN -> ent -> sigmoid -> quantum sim -> probs (written as bf16 hi/lo)
// ---------------------------------------------------------------------------
__global__ void token_quantum_kernel(const float* __restrict__ ln_w,
                                     const float* __restrict__ ln_b,
                                     const float* __restrict__ ent_w,
                                     const float* __restrict__ ent_b) {
    const int t = blockIdx.x;
    const int tid = threadIdx.x;
    const int lane = tid & 31;
    const int wrp = tid >> 5;

    __shared__ float hn[HIDDEN];
    __shared__ float red[16];
    __shared__ float ang[NANG];
    __shared__ float sre[QDIM];
    __shared__ float smi[QDIM];

    const float* hrow = g_H + (size_t)t * HIDDEN;

    float lsum = 0.0f;
    for (int k = tid; k < HIDDEN; k += 256) {
        float v = hrow[k];
        hn[k] = v;
        lsum += v;
    }
    #pragma unroll
    for (int o = 16; o; o >>= 1) lsum += __shfl_xor_sync(0xffffffffu, lsum, o);
    if (lane == 0) red[wrp] = lsum;
    __syncthreads();
    float mean = 0.0f;
    #pragma unroll
    for (int w = 0; w < 8; w++) mean += red[w];
    mean *= (1.0f / HIDDEN);

    float lsq = 0.0f;
    for (int k = tid; k < HIDDEN; k += 256) {
        float d = hn[k] - mean;
        lsq += d * d;
    }
    #pragma unroll
    for (int o = 16; o; o >>= 1) lsq += __shfl_xor_sync(0xffffffffu, lsq, o);
    if (lane == 0) red[8 + wrp] = lsq;
    __syncthreads();
    float var = 0.0f;
    #pragma unroll
    for (int w = 0; w < 8; w++) var += red[8 + w];
    var *= (1.0f / HIDDEN);
    float rstd = rsqrtf(var + 1e-12f);

    for (int k = tid; k < HIDDEN; k += 256)
        hn[k] = ln_w[k] * ((hn[k] - mean) * rstd) + ln_b[k];
    __syncthreads();

    for (int j = wrp; j < NANG; j += 8) {
        float acc = 0.0f;
        for (int k = lane; k < HIDDEN; k += 32)
            acc += hn[k] * ent_w[(size_t)k * NANG + j];
        #pragma unroll
        for (int o = 16; o; o >>= 1) acc += __shfl_xor_sync(0xffffffffu, acc, o);
        if (lane == 0) {
            float z = acc + ent_b[j];
            ang[j] = 6.28318530717958647692f / (1.0f + expf(-z));
        }
    }
    __syncthreads();

    for (int i = tid; i < QDIM; i += 256) {
        sre[i] = (i == 0) ? 1.0f : 0.0f;
        smi[i] = 0.0f;
    }
    __syncthreads();

    #pragma unroll 1
    for (int l = 0; l < 2; l++) {
        #pragma unroll 1
        for (int q = 0; q < 10; q++) {
            float th = ang[l * 10 + q] * 0.5f;
            float sth, cth;
            sincosf(th, &sth, &cth);
            int pos = 9 - q;
            int lowmask = (1 << pos) - 1;
            #pragma unroll
            for (int pp = 0; pp < 2; pp++) {
                int p = tid + pp * 256;
                int i0 = ((p & ~lowmask) << 1) | (p & lowmask);
                int i1 = i0 | (1 << pos);
                float a0r = sre[i0], a0i = smi[i0];
                float a1r = sre[i1], a1i = smi[i1];
                sre[i0] = cth * a0r + sth * a1i;
                smi[i0] = cth * a0i - sth * a1r;
                sre[i1] = cth * a1r + sth * a0i;
                smi[i1] = cth * a1i - sth * a0r;
            }
            __syncthreads();
        }
        #pragma unroll 1
        for (int q = 0; q < 10; q++) {
            int tq = (q + 1) % 10;
            int cpos = 9 - q;
            int tpos = 9 - tq;
            int lo = cpos < tpos ? cpos : tpos;
            int hi = cpos > tpos ? cpos : tpos;
            int x = tid;
            x = ((x >> lo) << (lo + 1)) | (x & ((1 << lo) - 1));
            x = ((x >> hi) << (hi + 1)) | (x & ((1 << hi) - 1));
            int i = x | (1 << cpos);
            int j2 = i | (1 << tpos);
            float tr = sre[i]; sre[i] = sre[j2]; sre[j2] = tr;
            float ti = smi[i]; smi[i] = smi[j2]; smi[j2] = ti;
            __syncthreads();
        }
    }

    for (int i = tid; i < QDIM; i += 256) {
        float r = sre[i], im = smi[i];
        float p = r * r + im * im;
        __nv_bfloat16 h = __float2bfloat16(p);
        g_A_hi[(size_t)t * QDIM + i] = h;
        g_A_lo[(size_t)t * QDIM + i] = __float2bfloat16(p - __bfloat162float(h));
    }
}

// ---------------------------------------------------------------------------
// W [1024, 30522] fp32 -> Wt_hi/lo [30720, 1024] bf16 (transpose + split)
// ---------------------------------------------------------------------------
__global__ void conv_w_kernel(const float* __restrict__ W) {
    __shared__ float tile[32][33];
    int n0 = blockIdx.x * 32;
    int k0 = blockIdx.y * 32;
    int tx = threadIdx.x, ty = threadIdx.y;
    #pragma unroll
    for (int i = 0; i < 4; i++) {
        int k = k0 + ty + 8 * i;
        int n = n0 + tx;
        tile[ty + 8 * i][tx] = (n < VOCAB) ? W[(size_t)k * VOCAB + n] : 0.0f;
    }
    __syncthreads();
    #pragma unroll
    for (int i = 0; i < 4; i++) {
        int n = n0 + ty + 8 * i;
        int k = k0 + tx;
        float v = tile[tx][ty + 8 * i];
        __nv_bfloat16 h = __float2bfloat16(v);
        g_Wt_hi[(size_t)n * QDIM + k] = h;
        g_Wt_lo[(size_t)n * QDIM + k] = __float2bfloat16(v - __bfloat162float(h));
    }
}

// ---------------------------------------------------------------------------
// Proj GEMM via mma.sync bf16 (3-term split): out = P @ W + b
// BM=128, BN=128, BK=32; 8 warps (2x4), warp tile 64x32; 2-stage cp.async.
// Smem rows: 32 bf16 = 64B data padded to 80B stride -> conflict-free ldmatrix.
// ---------------------------------------------------------------------------
#define BM 128
#define BN 128
#define BKE 32
#define NCHUNK (QDIM / BKE)
#define ROWB 80
#define AHI 0
#define ALO (128 * ROWB)
#define BHI (2 * 128 * ROWB)
#define BLO (3 * 128 * ROWB)
#define STAGE (4 * 128 * ROWB)
#define PROJ_SMEM (2 * STAGE)

__global__ void __launch_bounds__(256, 1)
proj_kernel(const float* __restrict__ bias, float* __restrict__ out) {
    extern __shared__ char dynsm[];
    const uint32_t smem0 = smem_u32(dynsm);

    const int tid = threadIdx.x;
    const int lane = tid & 31;
    const int wid = tid >> 5;
    const int warp_m = wid & 1;   // 0..1
    const int warp_n = wid >> 1;  // 0..3
    const int m0 = blockIdx.x * BM;
    const int n0 = blockIdx.y * BN;

    const __nv_bfloat16* Ahg = g_A_hi + (size_t)m0 * QDIM;
    const __nv_bfloat16* Alg = g_A_lo + (size_t)m0 * QDIM;
    const __nv_bfloat16* Bhg = g_Wt_hi + (size_t)n0 * QDIM;
    const __nv_bfloat16* Blg = g_Wt_lo + (size_t)n0 * QDIM;

    // Issue cp.async loads for chunk c into stage s.
    auto load_stage = [&](int c, int s) {
        const int k0 = c * BKE;
        const uint32_t sb = smem0 + s * STAGE;
        #pragma unroll
        for (int it = 0; it < 2; it++) {
            int idx = it * 256 + tid;          // 0..511
            int row = idx >> 2, ch = idx & 3;  // 4 x 16B per row
            size_t go = (size_t)row * QDIM + k0 + ch * 8;
            uint32_t so = row * ROWB + ch * 16;
            cp_async16(sb + AHI + so, Ahg + go);
            cp_async16(sb + ALO + so, Alg + go);
            cp_async16(sb + BHI + so, Bhg + go);
            cp_async16(sb + BLO + so, Blg + go);
        }
        cp_commit();
    };

    float acc[4][4][4];
    #pragma unroll
    for (int i = 0; i < 4; i++)
        #pragma unroll
        for (int j = 0; j < 4; j++)
            #pragma unroll
            for (int e = 0; e < 4; e++) acc[i][j][e] = 0.0f;

    load_stage(0, 0);
    load_stage(1, 1);

    const int l16 = lane & 15;
    const int ach = lane >> 4;          // 0..1 : k-half selector for A ldmatrix
    const int bch = (lane >> 3) & 1;    // k-half selector for B ldmatrix
    const int arow = warp_m * 64 + l16;
    const int brow = warp_n * 32 + (lane & 7);

    for (int c = 0; c < NCHUNK; c++) {
        cp_wait1();
        __syncthreads();
        const uint32_t sb = smem0 + (c & 1) * STAGE;

        #pragma unroll
        for (int ks = 0; ks < 2; ks++) {
            uint32_t ahi[4][4], alo[4][4], bhi[4][2], blo[4][2];
            #pragma unroll
            for (int mi = 0; mi < 4; mi++) {
                uint32_t ao = (arow + mi * 16) * ROWB + (ks * 2 + ach) * 16;
                ldsm_x4(ahi[mi], sb + AHI + ao);
                ldsm_x4(alo[mi], sb + ALO + ao);
            }
            #pragma unroll
            for (int ni = 0; ni < 4; ni++) {
                uint32_t bo = (brow + ni * 8) * ROWB + (ks * 2 + bch) * 16;
                ldsm_x2(bhi[ni], sb + BHI + bo);
                ldsm_x2(blo[ni], sb + BLO + bo);
            }
            #pragma unroll
            for (int mi = 0; mi < 4; mi++)
                #pragma unroll
                for (int ni = 0; ni < 4; ni++) {
                    mma_bf16(acc[mi][ni], ahi[mi], bhi[ni]);
                    mma_bf16(acc[mi][ni], ahi[mi], blo[ni]);
                    mma_bf16(acc[mi][ni], alo[mi], bhi[ni]);
                }
        }
        __syncthreads();
        if (c + 2 < NCHUNK) load_stage(c + 2, (c & 1));
        else cp_commit();  // keep group counting consistent for cp_wait1
    }

    // ---- epilogue ----
    const int qr = lane >> 2;        // 0..7
    const int qc = (lane & 3) * 2;   // 0,2,4,6
    #pragma unroll
    for (int mi = 0; mi < 4; mi++) {
        #pragma unroll
        for (int ni = 0; ni < 4; ni++) {
            int row = m0 + warp_m * 64 + mi * 16 + qr;
            int col = n0 + warp_n * 32 + ni * 8 + qc;
            #pragma unroll
            for (int h = 0; h < 2; h++) {  // h=0: row, h=1: row+8
                int r = row + h * 8;
                float v0 = acc[mi][ni][h * 2 + 0];
                float v1 = acc[mi][ni][h * 2 + 1];
                if (col + 1 < VOCAB) {
                    float2 o;
                    o.x = v0 + bias[col];
                    o.y = v1 + bias[col + 1];
                    *(float2*)(out + (size_t)r * VOCAB + col) = o;
                } else if (col < VOCAB) {
                    out[(size_t)r * VOCAB + col] = v0 + bias[col];
                }
            }
        }
    }
}

// ---------------------------------------------------------------------------
extern "C" void kernel_launch(void* const* d_in, const int* in_sizes, int n_in,
                              void* d_out, int out_size) {
    const float* hidden  = (const float*)d_in[0];
    const float* dense_w = (const float*)d_in[1];
    const float* dense_b = (const float*)d_in[2];
    const float* ln_w    = (const float*)d_in[3];
    const float* ln_b    = (const float*)d_in[4];
    const float* ent_w   = (const float*)d_in[5];
    const float* ent_b   = (const float*)d_in[6];
    const float* proj_w  = (const float*)d_in[7];
    const float* proj_b  = (const float*)d_in[8];
    float* out = (float*)d_out;

    float* Hptr = nullptr;
    cudaGetSymbolAddress((void**)&Hptr, g_H);

    cudaFuncSetAttribute(proj_kernel, cudaFuncAttributeMaxDynamicSharedMemorySize, PROJ_SMEM);

    // 0) W transpose + bf16 split
    conv_w_kernel<<<dim3((VOCAB + 31) / 32, QDIM / 32), dim3(32, 8)>>>(proj_w);

    // 1) dense + GELU
    dense_gelu_kernel<<<dim3(HIDDEN / 64, NTOK / 64), dim3(16, 16)>>>(
        hidden, dense_w, dense_b, Hptr, NTOK, HIDDEN, HIDDEN);

    // 2) LN + ent + sigmoid + quantum sim -> probs (bf16 hi/lo)
    token_quantum_kernel<<<NTOK, 256>>>(ln_w, ln_b, ent_w, ent_b);

    // 3) proj via mma.sync split-bf16 (grid: M fastest for W reuse in L2)
    proj_kernel<<<dim3(NTOK / BM, (VOCAB + BN - 1) / BN), 256, PROJ_SMEM>>>(proj_b, out);
}

// round 7
// speedup vs baseline: 2.8326x; 1.0079x over previous
#include <cuda_runtime.h>
#include <cuda_bf16.h>
#include <math.h>
#include <stdint.h>

#define HIDDEN 768
#define NTOK   4096
#define QDIM   1024
#define VOCAB  30522
#define VOCAB_PAD 30720
#define NANG   20

// ---------------- device scratch (allocation-free) ----------------
__device__ float         g_H[NTOK * HIDDEN];           // post-GELU dense output
__device__ __nv_bfloat16 g_A_hi[NTOK * QDIM];          // probs hi
__device__ __nv_bfloat16 g_A_lo[NTOK * QDIM];          // probs lo
__device__ __nv_bfloat16 g_Wt_hi[VOCAB_PAD * QDIM];    // proj_w^T hi (K-major)
__device__ __nv_bfloat16 g_Wt_lo[VOCAB_PAD * QDIM];    // proj_w^T lo

// ---------------- portable PTX helpers (no sm_103a features) ----------------
static __device__ __forceinline__ uint32_t smem_u32(const void* p) {
    uint32_t a;
    asm("{ .reg .u64 t; cvta.to.shared.u64 t, %1; cvt.u32.u64 %0, t; }" : "=r"(a) : "l"(p));
    return a;
}
static __device__ __forceinline__ void cp_async16(uint32_t dst, const void* src) {
    asm volatile("cp.async.cg.shared.global [%0], [%1], 16;" :: "r"(dst), "l"(src) : "memory");
}
static __device__ __forceinline__ void cp_commit() {
    asm volatile("cp.async.commit_group;" ::: "memory");
}
static __device__ __forceinline__ void cp_wait2() {
    asm volatile("cp.async.wait_group 2;" ::: "memory");
}
static __device__ __forceinline__ void ldsm_x4(uint32_t* r, uint32_t addr) {
    asm volatile("ldmatrix.sync.aligned.m8n8.x4.shared.b16 {%0,%1,%2,%3}, [%4];"
                 : "=r"(r[0]), "=r"(r[1]), "=r"(r[2]), "=r"(r[3]) : "r"(addr));
}
static __device__ __forceinline__ void ldsm_x2(uint32_t* r, uint32_t addr) {
    asm volatile("ldmatrix.sync.aligned.m8n8.x2.shared.b16 {%0,%1}, [%2];"
                 : "=r"(r[0]), "=r"(r[1]) : "r"(addr));
}
static __device__ __forceinline__ void mma_bf16(float* d, const uint32_t* a, const uint32_t* b) {
    asm volatile(
        "mma.sync.aligned.m16n8k16.row.col.f32.bf16.bf16.f32 "
        "{%0,%1,%2,%3}, {%4,%5,%6,%7}, {%8,%9}, {%0,%1,%2,%3};"
        : "+f"(d[0]), "+f"(d[1]), "+f"(d[2]), "+f"(d[3])
        : "r"(a[0]), "r"(a[1]), "r"(a[2]), "r"(a[3]), "r"(b[0]), "r"(b[1]));
}

// ---------------------------------------------------------------------------
// fp32 tiled GEMM + GELU (dense layer): C = GELU(A@B + bias)
// ---------------------------------------------------------------------------
__global__ void dense_gelu_kernel(const float* __restrict__ A,
                                  const float* __restrict__ B,
                                  const float* __restrict__ bias,
                                  float* __restrict__ C,
                                  int M, int N, int K) {
    constexpr int BK = 16;
    __shared__ __align__(16) float As[BK][64 + 4];
    __shared__ __align__(16) float Bs[BK][64];

    const int tx = threadIdx.x, ty = threadIdx.y;
    const int tid = ty * 16 + tx;
    const int m0 = blockIdx.y * 64;
    const int n0 = blockIdx.x * 64;

    float acc[4][4] = {};

    for (int k0 = 0; k0 < K; k0 += BK) {
        #pragma unroll
        for (int e = 0; e < 4; e++) {
            int lin = e * 256 + tid;
            int c = lin & 15, r = lin >> 4;
            As[c][r] = A[(size_t)(m0 + r) * K + k0 + c];
        }
        #pragma unroll
        for (int e = 0; e < 4; e++) {
            int lin = e * 256 + tid;
            int c = lin & 63, r = lin >> 6;
            Bs[r][c] = B[(size_t)(k0 + r) * N + n0 + c];
        }
        __syncthreads();
        #pragma unroll
        for (int kk = 0; kk < BK; kk++) {
            float4 av = *(const float4*)&As[kk][ty * 4];
            float4 bv = *(const float4*)&Bs[kk][tx * 4];
            float a[4] = {av.x, av.y, av.z, av.w};
            float b[4] = {bv.x, bv.y, bv.z, bv.w};
            #pragma unroll
            for (int i = 0; i < 4; i++)
                #pragma unroll
                for (int j = 0; j < 4; j++)
                    acc[i][j] += a[i] * b[j];
        }
        __syncthreads();
    }
    #pragma unroll
    for (int i = 0; i < 4; i++) {
        int row = m0 + ty * 4 + i;
        #pragma unroll
        for (int j = 0; j < 4; j++) {
            int col = n0 + tx * 4 + j;
            float v = acc[i][j] + bias[col];
            v = 0.5f * v * (1.0f + erff(v * 0.70710678118654752f));
            C[(size_t)row * N + col] = v;
        }
    }
}

// ---------------------------------------------------------------------------
// Per-token LN -> ent -> sigmoid -> quantum sim -> probs (written as bf16 hi/lo)
// ---------------------------------------------------------------------------
__global__ void token_quantum_kernel(const float* __restrict__ ln_w,
                                     const float* __restrict__ ln_b,
                                     const float* __restrict__ ent_w,
                                     const float* __restrict__ ent_b) {
    const int t = blockIdx.x;
    const int tid = threadIdx.x;
    const int lane = tid & 31;
    const int wrp = tid >> 5;

    __shared__ float hn[HIDDEN];
    __shared__ float red[16];
    __shared__ float ang[NANG];
    __shared__ float sre[QDIM];
    __shared__ float smi[QDIM];

    const float* hrow = g_H + (size_t)t * HIDDEN;

    float lsum = 0.0f;
    for (int k = tid; k < HIDDEN; k += 256) {
        float v = hrow[k];
        hn[k] = v;
        lsum += v;
    }
    #pragma unroll
    for (int o = 16; o; o >>= 1) lsum += __shfl_xor_sync(0xffffffffu, lsum, o);
    if (lane == 0) red[wrp] = lsum;
    __syncthreads();
    float mean = 0.0f;
    #pragma unroll
    for (int w = 0; w < 8; w++) mean += red[w];
    mean *= (1.0f / HIDDEN);

    float lsq = 0.0f;
    for (int k = tid; k < HIDDEN; k += 256) {
        float d = hn[k] - mean;
        lsq += d * d;
    }
    #pragma unroll
    for (int o = 16; o; o >>= 1) lsq += __shfl_xor_sync(0xffffffffu, lsq, o);
    if (lane == 0) red[8 + wrp] = lsq;
    __syncthreads();
    float var = 0.0f;
    #pragma unroll
    for (int w = 0; w < 8; w++) var += red[8 + w];
    var *= (1.0f / HIDDEN);
    float rstd = rsqrtf(var + 1e-12f);

    for (int k = tid; k < HIDDEN; k += 256)
        hn[k] = ln_w[k] * ((hn[k] - mean) * rstd) + ln_b[k];
    __syncthreads();

    for (int j = wrp; j < NANG; j += 8) {
        float acc = 0.0f;
        for (int k = lane; k < HIDDEN; k += 32)
            acc += hn[k] * ent_w[(size_t)k * NANG + j];
        #pragma unroll
        for (int o = 16; o; o >>= 1) acc += __shfl_xor_sync(0xffffffffu, acc, o);
        if (lane == 0) {
            float z = acc + ent_b[j];
            ang[j] = 6.28318530717958647692f / (1.0f + expf(-z));
        }
    }
    __syncthreads();

    for (int i = tid; i < QDIM; i += 256) {
        sre[i] = (i == 0) ? 1.0f : 0.0f;
        smi[i] = 0.0f;
    }
    __syncthreads();

    #pragma unroll 1
    for (int l = 0; l < 2; l++) {
        #pragma unroll 1
        for (int q = 0; q < 10; q++) {
            float th = ang[l * 10 + q] * 0.5f;
            float sth, cth;
            sincosf(th, &sth, &cth);
            int pos = 9 - q;
            int lowmask = (1 << pos) - 1;
            #pragma unroll
            for (int pp = 0; pp < 2; pp++) {
                int p = tid + pp * 256;
                int i0 = ((p & ~lowmask) << 1) | (p & lowmask);
                int i1 = i0 | (1 << pos);
                float a0r = sre[i0], a0i = smi[i0];
                float a1r = sre[i1], a1i = smi[i1];
                sre[i0] = cth * a0r + sth * a1i;
                smi[i0] = cth * a0i - sth * a1r;
                sre[i1] = cth * a1r + sth * a0i;
                smi[i1] = cth * a1i - sth * a0r;
            }
            __syncthreads();
        }
        #pragma unroll 1
        for (int q = 0; q < 10; q++) {
            int tq = (q + 1) % 10;
            int cpos = 9 - q;
            int tpos = 9 - tq;
            int lo = cpos < tpos ? cpos : tpos;
            int hi = cpos > tpos ? cpos : tpos;
            int x = tid;
            x = ((x >> lo) << (lo + 1)) | (x & ((1 << lo) - 1));
            x = ((x >> hi) << (hi + 1)) | (x & ((1 << hi) - 1));
            int i = x | (1 << cpos);
            int j2 = i | (1 << tpos);
            float tr = sre[i]; sre[i] = sre[j2]; sre[j2] = tr;
            float ti = smi[i]; smi[i] = smi[j2]; smi[j2] = ti;
            __syncthreads();
        }
    }

    for (int i = tid; i < QDIM; i += 256) {
        float r = sre[i], im = smi[i];
        float p = r * r + im * im;
        __nv_bfloat16 h = __float2bfloat16(p);
        g_A_hi[(size_t)t * QDIM + i] = h;
        g_A_lo[(size_t)t * QDIM + i] = __float2bfloat16(p - __bfloat162float(h));
    }
}

// ---------------------------------------------------------------------------
// W [1024, 30522] fp32 -> Wt_hi/lo [30720, 1024] bf16 (transpose + split)
// ---------------------------------------------------------------------------
__global__ void conv_w_kernel(const float* __restrict__ W) {
    __shared__ float tile[32][33];
    int n0 = blockIdx.x * 32;
    int k0 = blockIdx.y * 32;
    int tx = threadIdx.x, ty = threadIdx.y;
    #pragma unroll
    for (int i = 0; i < 4; i++) {
        int k = k0 + ty + 8 * i;
        int n = n0 + tx;
        tile[ty + 8 * i][tx] = (n < VOCAB) ? W[(size_t)k * VOCAB + n] : 0.0f;
    }
    __syncthreads();
    #pragma unroll
    for (int i = 0; i < 4; i++) {
        int n = n0 + ty + 8 * i;
        int k = k0 + tx;
        float v = tile[tx][ty + 8 * i];
        __nv_bfloat16 h = __float2bfloat16(v);
        g_Wt_hi[(size_t)n * QDIM + k] = h;
        g_Wt_lo[(size_t)n * QDIM + k] = __float2bfloat16(v - __bfloat162float(h));
    }
}

// ---------------------------------------------------------------------------
// Proj GEMM via mma.sync bf16 (3-term split): out = P @ W + b
// BM=128, BN=128, BK=32; 8 warps (2x4), warp tile 64x32.
// 4-stage cp.async ring, ONE __syncthreads per chunk, loads issued pre-compute.
// Smem rows: 32 bf16 = 64B data padded to 80B stride -> conflict-free ldmatrix.
// ---------------------------------------------------------------------------
#define BM 128
#define BN 128
#define BKE 32
#define NCHUNK (QDIM / BKE)
#define NSTAGE 4
#define ROWB 80
#define AHI 0
#define ALO (128 * ROWB)
#define BHI (2 * 128 * ROWB)
#define BLO (3 * 128 * ROWB)
#define STAGE (4 * 128 * ROWB)
#define PROJ_SMEM (NSTAGE * STAGE)

__global__ void __launch_bounds__(256, 1)
proj_kernel(const float* __restrict__ bias, float* __restrict__ out) {
    extern __shared__ char dynsm[];
    const uint32_t smem0 = smem_u32(dynsm);

    const int tid = threadIdx.x;
    const int lane = tid & 31;
    const int wid = tid >> 5;
    const int warp_m = wid & 1;   // 0..1
    const int warp_n = wid >> 1;  // 0..3
    const int m0 = blockIdx.x * BM;
    const int n0 = blockIdx.y * BN;

    const __nv_bfloat16* Ahg = g_A_hi + (size_t)m0 * QDIM;
    const __nv_bfloat16* Alg = g_A_lo + (size_t)m0 * QDIM;
    const __nv_bfloat16* Bhg = g_Wt_hi + (size_t)n0 * QDIM;
    const __nv_bfloat16* Blg = g_Wt_lo + (size_t)n0 * QDIM;

    // Issue cp.async loads for chunk c into stage c % NSTAGE.
    auto load_stage = [&](int c) {
        const int k0 = c * BKE;
        const uint32_t sb = smem0 + (c % NSTAGE) * STAGE;
        #pragma unroll
        for (int it = 0; it < 2; it++) {
            int idx = it * 256 + tid;          // 0..511
            int row = idx >> 2, ch = idx & 3;  // 4 x 16B per row
            size_t go = (size_t)row * QDIM + k0 + ch * 8;
            uint32_t so = row * ROWB + ch * 16;
            cp_async16(sb + AHI + so, Ahg + go);
            cp_async16(sb + ALO + so, Alg + go);
            cp_async16(sb + BHI + so, Bhg + go);
            cp_async16(sb + BLO + so, Blg + go);
        }
        cp_commit();
    };

    float acc[4][4][4];
    #pragma unroll
    for (int i = 0; i < 4; i++)
        #pragma unroll
        for (int j = 0; j < 4; j++)
            #pragma unroll
            for (int e = 0; e < 4; e++) acc[i][j][e] = 0.0f;

    load_stage(0);
    load_stage(1);
    load_stage(2);

    const int l16 = lane & 15;
    const int ach = lane >> 4;          // k-half selector for A ldmatrix
    const int bch = (lane >> 3) & 1;    // k-half selector for B ldmatrix
    const int arow = warp_m * 64 + l16;
    const int brow = warp_n * 32 + (lane & 7);

    for (int c = 0; c < NCHUNK; c++) {
        cp_wait2();            // stage c fully landed (<=2 newer groups pending)
        __syncthreads();       // single barrier per chunk: also makes overwrite of
                               // stage (c-1)%4 by load(c+3) safe (all warps past compute(c-1))
        if (c + 3 < NCHUNK) load_stage(c + 3);  // DMA runs under the MMA burst

        const uint32_t sb = smem0 + (c % NSTAGE) * STAGE;
        #pragma unroll
        for (int ks = 0; ks < 2; ks++) {
            uint32_t ahi[4][4], alo[4][4], bhi[4][2], blo[4][2];
            #pragma unroll
            for (int mi = 0; mi < 4; mi++) {
                uint32_t ao = (arow + mi * 16) * ROWB + (ks * 2 + ach) * 16;
                ldsm_x4(ahi[mi], sb + AHI + ao);
                ldsm_x4(alo[mi], sb + ALO + ao);
            }
            #pragma unroll
            for (int ni = 0; ni < 4; ni++) {
                uint32_t bo = (brow + ni * 8) * ROWB + (ks * 2 + bch) * 16;
                ldsm_x2(bhi[ni], sb + BHI + bo);
                ldsm_x2(blo[ni], sb + BLO + bo);
            }
            #pragma unroll
            for (int mi = 0; mi < 4; mi++)
                #pragma unroll
                for (int ni = 0; ni < 4; ni++) {
                    mma_bf16(acc[mi][ni], ahi[mi], bhi[ni]);
                    mma_bf16(acc[mi][ni], ahi[mi], blo[ni]);
                    mma_bf16(acc[mi][ni], alo[mi], bhi[ni]);
                }
        }
    }

    // ---- epilogue ----
    const int qr = lane >> 2;        // 0..7
    const int qc = (lane & 3) * 2;   // 0,2,4,6
    #pragma unroll
    for (int mi = 0; mi < 4; mi++) {
        #pragma unroll
        for (int ni = 0; ni < 4; ni++) {
            int row = m0 + warp_m * 64 + mi * 16 + qr;
            int col = n0 + warp_n * 32 + ni * 8 + qc;
            #pragma unroll
            for (int h = 0; h < 2; h++) {  // h=0: row, h=1: row+8
                int r = row + h * 8;
                float v0 = acc[mi][ni][h * 2 + 0];
                float v1 = acc[mi][ni][h * 2 + 1];
                if (col + 1 < VOCAB) {
                    float2 o;
                    o.x = v0 + bias[col];
                    o.y = v1 + bias[col + 1];
                    *(float2*)(out + (size_t)r * VOCAB + col) = o;
                } else if (col < VOCAB) {
                    out[(size_t)r * VOCAB + col] = v0 + bias[col];
                }
            }
        }
    }
}

// ---------------------------------------------------------------------------
extern "C" void kernel_launch(void* const* d_in, const int* in_sizes, int n_in,
                              void* d_out, int out_size) {
    const float* hidden  = (const float*)d_in[0];
    const float* dense_w = (const float*)d_in[1];
    const float* dense_b = (const float*)d_in[2];
    const float* ln_w    = (const float*)d_in[3];
    const float* ln_b    = (const float*)d_in[4];
    const float* ent_w   = (const float*)d_in[5];
    const float* ent_b   = (const float*)d_in[6];
    const float* proj_w  = (const float*)d_in[7];
    const float* proj_b  = (const float*)d_in[8];
    float* out = (float*)d_out;

    float* Hptr = nullptr;
    cudaGetSymbolAddress((void**)&Hptr, g_H);

    cudaFuncSetAttribute(proj_kernel, cudaFuncAttributeMaxDynamicSharedMemorySize, PROJ_SMEM);

    // 0) W transpose + bf16 split
    conv_w_kernel<<<dim3((VOCAB + 31) / 32, QDIM / 32), dim3(32, 8)>>>(proj_w);

    // 1) dense + GELU
    dense_gelu_kernel<<<dim3(HIDDEN / 64, NTOK / 64), dim3(16, 16)>>>(
        hidden, dense_w, dense_b, Hptr, NTOK, HIDDEN, HIDDEN);

    // 2) LN + ent + sigmoid + quantum sim -> probs (bf16 hi/lo)
    token_quantum_kernel<<<NTOK, 256>>>(ln_w, ln_b, ent_w, ent_b);

    // 3) proj via mma.sync split-bf16 (grid: M fastest for W reuse in L2)
    proj_kernel<<<dim3(NTOK / BM, (VOCAB + BN - 1) / BN), 256, PROJ_SMEM>>>(proj_b, out);
}

// round 8
// speedup vs baseline: 3.0966x; 1.0932x over previous
#include <cuda_runtime.h>
#include <cuda_bf16.h>
#include <math.h>
#include <stdint.h>

#define HIDDEN 768
#define NTOK   4096
#define QDIM   1024
#define VOCAB  30522
#define VOCAB_PAD 30720
#define NANG   20

// ---------------- device scratch (allocation-free) ----------------
__device__ float         g_H[NTOK * HIDDEN];           // post-GELU dense output
__device__ __nv_bfloat16 g_A_hi[NTOK * QDIM];          // probs hi
__device__ __nv_bfloat16 g_A_lo[NTOK * QDIM];          // probs lo
__device__ __nv_bfloat16 g_Wt_hi[VOCAB_PAD * QDIM];    // proj_w^T hi (K-major)
__device__ __nv_bfloat16 g_Wt_lo[VOCAB_PAD * QDIM];    // proj_w^T lo

// ---------------- portable PTX helpers (no sm_103a features) ----------------
static __device__ __forceinline__ uint32_t smem_u32(const void* p) {
    uint32_t a;
    asm("{ .reg .u64 t; cvta.to.shared.u64 t, %1; cvt.u32.u64 %0, t; }" : "=r"(a) : "l"(p));
    return a;
}
static __device__ __forceinline__ void cp_async16(uint32_t dst, const void* src) {
    asm volatile("cp.async.cg.shared.global [%0], [%1], 16;" :: "r"(dst), "l"(src) : "memory");
}
static __device__ __forceinline__ void cp_commit() {
    asm volatile("cp.async.commit_group;" ::: "memory");
}
static __device__ __forceinline__ void cp_wait1() {
    asm volatile("cp.async.wait_group 1;" ::: "memory");
}
static __device__ __forceinline__ void ldsm_x4(uint32_t* r, uint32_t addr) {
    asm volatile("ldmatrix.sync.aligned.m8n8.x4.shared.b16 {%0,%1,%2,%3}, [%4];"
                 : "=r"(r[0]), "=r"(r[1]), "=r"(r[2]), "=r"(r[3]) : "r"(addr));
}
static __device__ __forceinline__ void mma_bf16(float* d, const uint32_t* a, const uint32_t* b) {
    asm volatile(
        "mma.sync.aligned.m16n8k16.row.col.f32.bf16.bf16.f32 "
        "{%0,%1,%2,%3}, {%4,%5,%6,%7}, {%8,%9}, {%0,%1,%2,%3};"
        : "+f"(d[0]), "+f"(d[1]), "+f"(d[2]), "+f"(d[3])
        : "r"(a[0]), "r"(a[1]), "r"(a[2]), "r"(a[3]), "r"(b[0]), "r"(b[1]));
}

// ---------------------------------------------------------------------------
// fp32 tiled GEMM + GELU (dense layer): C = GELU(A@B + bias)
// ---------------------------------------------------------------------------
__global__ void dense_gelu_kernel(const float* __restrict__ A,
                                  const float* __restrict__ B,
                                  const float* __restrict__ bias,
                                  float* __restrict__ C,
                                  int M, int N, int K) {
    constexpr int BK = 16;
    __shared__ __align__(16) float As[BK][64 + 4];
    __shared__ __align__(16) float Bs[BK][64];

    const int tx = threadIdx.x, ty = threadIdx.y;
    const int tid = ty * 16 + tx;
    const int m0 = blockIdx.y * 64;
    const int n0 = blockIdx.x * 64;

    float acc[4][4] = {};

    for (int k0 = 0; k0 < K; k0 += BK) {
        #pragma unroll
        for (int e = 0; e < 4; e++) {
            int lin = e * 256 + tid;
            int c = lin & 15, r = lin >> 4;
            As[c][r] = A[(size_t)(m0 + r) * K + k0 + c];
        }
        #pragma unroll
        for (int e = 0; e < 4; e++) {
            int lin = e * 256 + tid;
            int c = lin & 63, r = lin >> 6;
            Bs[r][c] = B[(size_t)(k0 + r) * N + n0 + c];
        }
        __syncthreads();
        #pragma unroll
        for (int kk = 0; kk < BK; kk++) {
            float4 av = *(const float4*)&As[kk][ty * 4];
            float4 bv = *(const float4*)&Bs[kk][tx * 4];
            float a[4] = {av.x, av.y, av.z, av.w};
            float b[4] = {bv.x, bv.y, bv.z, bv.w};
            #pragma unroll
            for (int i = 0; i < 4; i++)
                #pragma unroll
                for (int j = 0; j < 4; j++)
                    acc[i][j] += a[i] * b[j];
        }
        __syncthreads();
    }
    #pragma unroll
    for (int i = 0; i < 4; i++) {
        int row = m0 + ty * 4 + i;
        #pragma unroll
        for (int j = 0; j < 4; j++) {
            int col = n0 + tx * 4 + j;
            float v = acc[i][j] + bias[col];
            v = 0.5f * v * (1.0f + erff(v * 0.70710678118654752f));
            C[(size_t)row * N + col] = v;
        }
    }
}

// ---------------------------------------------------------------------------
// Per-token LN -> ent -> sigmoid -> quantum sim -> probs (written as bf16 hi/lo)
// ---------------------------------------------------------------------------
__global__ void token_quantum_kernel(const float* __restrict__ ln_w,
                                     const float* __restrict__ ln_b,
                                     const float* __restrict__ ent_w,
                                     const float* __restrict__ ent_b) {
    const int t = blockIdx.x;
    const int tid = threadIdx.x;
    const int lane = tid & 31;
    const int wrp = tid >> 5;

    __shared__ float hn[HIDDEN];
    __shared__ float red[16];
    __shared__ float ang[NANG];
    __shared__ float sre[QDIM];
    __shared__ float smi[QDIM];

    const float* hrow = g_H + (size_t)t * HIDDEN;

    float lsum = 0.0f;
    for (int k = tid; k < HIDDEN; k += 256) {
        float v = hrow[k];
        hn[k] = v;
        lsum += v;
    }
    #pragma unroll
    for (int o = 16; o; o >>= 1) lsum += __shfl_xor_sync(0xffffffffu, lsum, o);
    if (lane == 0) red[wrp] = lsum;
    __syncthreads();
    float mean = 0.0f;
    #pragma unroll
    for (int w = 0; w < 8; w++) mean += red[w];
    mean *= (1.0f / HIDDEN);

    float lsq = 0.0f;
    for (int k = tid; k < HIDDEN; k += 256) {
        float d = hn[k] - mean;
        lsq += d * d;
    }
    #pragma unroll
    for (int o = 16; o; o >>= 1) lsq += __shfl_xor_sync(0xffffffffu, lsq, o);
    if (lane == 0) red[8 + wrp] = lsq;
    __syncthreads();
    float var = 0.0f;
    #pragma unroll
    for (int w = 0; w < 8; w++) var += red[8 + w];
    var *= (1.0f / HIDDEN);
    float rstd = rsqrtf(var + 1e-12f);

    for (int k = tid; k < HIDDEN; k += 256)
        hn[k] = ln_w[k] * ((hn[k] - mean) * rstd) + ln_b[k];
    __syncthreads();

    for (int j = wrp; j < NANG; j += 8) {
        float acc = 0.0f;
        for (int k = lane; k < HIDDEN; k += 32)
            acc += hn[k] * ent_w[(size_t)k * NANG + j];
        #pragma unroll
        for (int o = 16; o; o >>= 1) acc += __shfl_xor_sync(0xffffffffu, acc, o);
        if (lane == 0) {
            float z = acc + ent_b[j];
            ang[j] = 6.28318530717958647692f / (1.0f + expf(-z));
        }
    }
    __syncthreads();

    for (int i = tid; i < QDIM; i += 256) {
        sre[i] = (i == 0) ? 1.0f : 0.0f;
        smi[i] = 0.0f;
    }
    __syncthreads();

    #pragma unroll 1
    for (int l = 0; l < 2; l++) {
        #pragma unroll 1
        for (int q = 0; q < 10; q++) {
            float th = ang[l * 10 + q] * 0.5f;
            float sth, cth;
            sincosf(th, &sth, &cth);
            int pos = 9 - q;
            int lowmask = (1 << pos) - 1;
            #pragma unroll
            for (int pp = 0; pp < 2; pp++) {
                int p = tid + pp * 256;
                int i0 = ((p & ~lowmask) << 1) | (p & lowmask);
                int i1 = i0 | (1 << pos);
                float a0r = sre[i0], a0i = smi[i0];
                float a1r = sre[i1], a1i = smi[i1];
                sre[i0] = cth * a0r + sth * a1i;
                smi[i0] = cth * a0i - sth * a1r;
                sre[i1] = cth * a1r + sth * a0i;
                smi[i1] = cth * a1i - sth * a0r;
            }
            __syncthreads();
        }
        #pragma unroll 1
        for (int q = 0; q < 10; q++) {
            int tq = (q + 1) % 10;
            int cpos = 9 - q;
            int tpos = 9 - tq;
            int lo = cpos < tpos ? cpos : tpos;
            int hi = cpos > tpos ? cpos : tpos;
            int x = tid;
            x = ((x >> lo) << (lo + 1)) | (x & ((1 << lo) - 1));
            x = ((x >> hi) << (hi + 1)) | (x & ((1 << hi) - 1));
            int i = x | (1 << cpos);
            int j2 = i | (1 << tpos);
            float tr = sre[i]; sre[i] = sre[j2]; sre[j2] = tr;
            float ti = smi[i]; smi[i] = smi[j2]; smi[j2] = ti;
            __syncthreads();
        }
    }

    for (int i = tid; i < QDIM; i += 256) {
        float r = sre[i], im = smi[i];
        float p = r * r + im * im;
        __nv_bfloat16 h = __float2bfloat16(p);
        g_A_hi[(size_t)t * QDIM + i] = h;
        g_A_lo[(size_t)t * QDIM + i] = __float2bfloat16(p - __bfloat162float(h));
    }
}

// ---------------------------------------------------------------------------
// W [1024, 30522] fp32 -> Wt_hi/lo [30720, 1024] bf16 (transpose + split)
// ---------------------------------------------------------------------------
__global__ void conv_w_kernel(const float* __restrict__ W) {
    __shared__ float tile[32][33];
    int n0 = blockIdx.x * 32;
    int k0 = blockIdx.y * 32;
    int tx = threadIdx.x, ty = threadIdx.y;
    #pragma unroll
    for (int i = 0; i < 4; i++) {
        int k = k0 + ty + 8 * i;
        int n = n0 + tx;
        tile[ty + 8 * i][tx] = (n < VOCAB) ? W[(size_t)k * VOCAB + n] : 0.0f;
    }
    __syncthreads();
    #pragma unroll
    for (int i = 0; i < 4; i++) {
        int n = n0 + ty + 8 * i;
        int k = k0 + tx;
        float v = tile[tx][ty + 8 * i];
        __nv_bfloat16 h = __float2bfloat16(v);
        g_Wt_hi[(size_t)n * QDIM + k] = h;
        g_Wt_lo[(size_t)n * QDIM + k] = __float2bfloat16(v - __bfloat162float(h));
    }
}

// ---------------------------------------------------------------------------
// Proj GEMM via mma.sync bf16 (3-term split): out = P @ W + b
// BM=128, BN=256, BK=32; 8 warps (2x4), warp tile 64x64.
// 3-stage cp.async ring; B-fragment double-buffered ldmatrix prefetch.
// Smem rows: 32 bf16 = 64B data padded to 80B stride -> conflict-free ldmatrix.
// ---------------------------------------------------------------------------
#define BM 128
#define BN 256
#define BKE 32
#define NCHUNK (QDIM / BKE)
#define NSTAGE 3
#define ROWB 80
#define AHI 0
#define ALO (128 * ROWB)
#define BHI (2 * 128 * ROWB)
#define BLO (2 * 128 * ROWB + 256 * ROWB)
#define STAGE (2 * 128 * ROWB + 2 * 256 * ROWB)
#define PROJ_SMEM (NSTAGE * STAGE)

__global__ void __launch_bounds__(256, 1)
proj_kernel(const float* __restrict__ bias, float* __restrict__ out) {
    extern __shared__ char dynsm[];
    const uint32_t smem0 = smem_u32(dynsm);

    const int tid = threadIdx.x;
    const int lane = tid & 31;
    const int wid = tid >> 5;
    const int warp_m = wid & 1;   // 0..1 -> 64 rows each
    const int warp_n = wid >> 1;  // 0..3 -> 64 cols each
    const int m0 = blockIdx.x * BM;
    const int n0 = blockIdx.y * BN;

    const __nv_bfloat16* Ahg = g_A_hi + (size_t)m0 * QDIM;
    const __nv_bfloat16* Alg = g_A_lo + (size_t)m0 * QDIM;
    const __nv_bfloat16* Bhg = g_Wt_hi + (size_t)n0 * QDIM;
    const __nv_bfloat16* Blg = g_Wt_lo + (size_t)n0 * QDIM;

    // Issue cp.async loads for chunk c into stage c % NSTAGE.
    auto load_stage = [&](int c) {
        const int k0 = c * BKE;
        const uint32_t sb = smem0 + (c % NSTAGE) * STAGE;
        #pragma unroll
        for (int it = 0; it < 2; it++) {        // A: 128 rows x 4 chunks of 16B
            int idx = it * 256 + tid;
            int row = idx >> 2, ch = idx & 3;
            size_t go = (size_t)row * QDIM + k0 + ch * 8;
            uint32_t so = row * ROWB + ch * 16;
            cp_async16(sb + AHI + so, Ahg + go);
            cp_async16(sb + ALO + so, Alg + go);
        }
        #pragma unroll
        for (int it = 0; it < 4; it++) {        // B: 256 rows x 4 chunks of 16B
            int idx = it * 256 + tid;
            int row = idx >> 2, ch = idx & 3;
            size_t go = (size_t)row * QDIM + k0 + ch * 8;
            uint32_t so = row * ROWB + ch * 16;
            cp_async16(sb + BHI + so, Bhg + go);
            cp_async16(sb + BLO + so, Blg + go);
        }
        cp_commit();
    };

    float acc[4][8][4];
    #pragma unroll
    for (int i = 0; i < 4; i++)
        #pragma unroll
        for (int j = 0; j < 8; j++)
            #pragma unroll
            for (int e = 0; e < 4; e++) acc[i][j][e] = 0.0f;

    load_stage(0);
    load_stage(1);

    // A ldmatrix lane mapping (x4: 16 rows x 2 k-halves)
    const int arow = warp_m * 64 + (lane & 15);
    const int ach = lane >> 4;
    // B ldmatrix lane mapping (x4: 2 n-groups of 8 rows x 2 k-halves)
    const int bro = warp_n * 64 + (lane & 7) + ((lane >> 4) & 1) * 8;
    const int bkh = (lane >> 3) & 1;

    for (int c = 0; c < NCHUNK; c++) {
        cp_wait1();            // chunk c landed (only chunk c+1's group may be pending)
        __syncthreads();       // all warps consumed stage (c-1)%3 -> safe to overwrite
        if (c + 2 < NCHUNK) load_stage(c + 2);

        const uint32_t sb = smem0 + (c % NSTAGE) * STAGE;
        #pragma unroll
        for (int ks = 0; ks < 2; ks++) {
            // Load all A fragments for this k-step
            uint32_t ahi[4][4], alo[4][4];
            #pragma unroll
            for (int mi = 0; mi < 4; mi++) {
                uint32_t ao = (arow + mi * 16) * ROWB + (ks * 2 + ach) * 16;
                ldsm_x4(ahi[mi], sb + AHI + ao);
                ldsm_x4(alo[mi], sb + ALO + ao);
            }
            // B pair double-buffer: buffer holds groups {2nj, 2nj+1}
            uint32_t bh[2][4], bl[2][4];
            {
                uint32_t bo = (bro + 0 * 16) * ROWB + (ks * 2 + bkh) * 16;
                ldsm_x4(bh[0], sb + BHI + bo);
                ldsm_x4(bl[0], sb + BLO + bo);
            }
            #pragma unroll
            for (int nj = 0; nj < 4; nj++) {
                const int cur = nj & 1, nxt = cur ^ 1;
                if (nj < 3) {
                    uint32_t bo = (bro + (nj + 1) * 16) * ROWB + (ks * 2 + bkh) * 16;
                    ldsm_x4(bh[nxt], sb + BHI + bo);
                    ldsm_x4(bl[nxt], sb + BLO + bo);
                }
                #pragma unroll
                for (int mi = 0; mi < 4; mi++)
                    #pragma unroll
                    for (int g = 0; g < 2; g++) {
                        float* ac = acc[mi][2 * nj + g];
                        mma_bf16(ac, ahi[mi], &bh[cur][2 * g]);
                        mma_bf16(ac, ahi[mi], &bl[cur][2 * g]);
                        mma_bf16(ac, alo[mi], &bh[cur][2 * g]);
                    }
            }
        }
    }

    // ---- epilogue ----
    const int qr = lane >> 2;        // 0..7
    const int qc = (lane & 3) * 2;   // 0,2,4,6
    #pragma unroll
    for (int mi = 0; mi < 4; mi++) {
        #pragma unroll
        for (int ni = 0; ni < 8; ni++) {
            int row = m0 + warp_m * 64 + mi * 16 + qr;
            int col = n0 + warp_n * 64 + ni * 8 + qc;
            #pragma unroll
            for (int h = 0; h < 2; h++) {  // h=0: row, h=1: row+8
                int r = row + h * 8;
                float v0 = acc[mi][ni][h * 2 + 0];
                float v1 = acc[mi][ni][h * 2 + 1];
                if (col + 1 < VOCAB) {
                    float2 o;
                    o.x = v0 + bias[col];
                    o.y = v1 + bias[col + 1];
                    *(float2*)(out + (size_t)r * VOCAB + col) = o;
                } else if (col < VOCAB) {
                    out[(size_t)r * VOCAB + col] = v0 + bias[col];
                }
            }
        }
    }
}

// ---------------------------------------------------------------------------
extern "C" void kernel_launch(void* const* d_in, const int* in_sizes, int n_in,
                              void* d_out, int out_size) {
    const float* hidden  = (const float*)d_in[0];
    const float* dense_w = (const float*)d_in[1];
    const float* dense_b = (const float*)d_in[2];
    const float* ln_w    = (const float*)d_in[3];
    const float* ln_b    = (const float*)d_in[4];
    const float* ent_w   = (const float*)d_in[5];
    const float* ent_b   = (const float*)d_in[6];
    const float* proj_w  = (const float*)d_in[7];
    const float* proj_b  = (const float*)d_in[8];
    float* out = (float*)d_out;

    float* Hptr = nullptr;
    cudaGetSymbolAddress((void**)&Hptr, g_H);

    cudaFuncSetAttribute(proj_kernel, cudaFuncAttributeMaxDynamicSharedMemorySize, PROJ_SMEM);

    // 0) W transpose + bf16 split
    conv_w_kernel<<<dim3((VOCAB + 31) / 32, QDIM / 32), dim3(32, 8)>>>(proj_w);

    // 1) dense + GELU
    dense_gelu_kernel<<<dim3(HIDDEN / 64, NTOK / 64), dim3(16, 16)>>>(
        hidden, dense_w, dense_b, Hptr, NTOK, HIDDEN, HIDDEN);

    // 2) LN + ent + sigmoid + quantum sim -> probs (bf16 hi/lo)
    token_quantum_kernel<<<NTOK, 256>>>(ln_w, ln_b, ent_w, ent_b);

    // 3) proj via mma.sync split-bf16 (grid: M fastest for W reuse in L2)
    proj_kernel<<<dim3(NTOK / BM, VOCAB_PAD / BN), 256, PROJ_SMEM>>>(proj_b, out);
}

// round 9
// speedup vs baseline: 3.1790x; 1.0266x over previous
#include <cuda_runtime.h>
#include <cuda_bf16.h>
#include <math.h>
#include <stdint.h>

#define HIDDEN 768
#define NTOK   4096
#define QDIM   1024
#define VOCAB  30522
#define VOCAB_PAD 30720
#define NANG   20

// ---------------- device scratch (allocation-free) ----------------
__device__ float         g_H[NTOK * HIDDEN];           // post-GELU dense output
__device__ __nv_bfloat16 g_A_hi[NTOK * QDIM];          // probs hi
__device__ __nv_bfloat16 g_A_lo[NTOK * QDIM];          // probs lo
__device__ __nv_bfloat16 g_Wt_hi[VOCAB_PAD * QDIM];    // proj_w^T hi (K-major)
__device__ __nv_bfloat16 g_Wt_lo[VOCAB_PAD * QDIM];    // proj_w^T lo

// ---------------- portable PTX helpers (no sm_103a features) ----------------
static __device__ __forceinline__ uint32_t smem_u32(const void* p) {
    uint32_t a;
    asm("{ .reg .u64 t; cvta.to.shared.u64 t, %1; cvt.u32.u64 %0, t; }" : "=r"(a) : "l"(p));
    return a;
}
static __device__ __forceinline__ void cp_async16(uint32_t dst, const void* src) {
    asm volatile("cp.async.cg.shared.global [%0], [%1], 16;" :: "r"(dst), "l"(src) : "memory");
}
static __device__ __forceinline__ void cp_commit() {
    asm volatile("cp.async.commit_group;" ::: "memory");
}
static __device__ __forceinline__ void cp_wait1() {
    asm volatile("cp.async.wait_group 1;" ::: "memory");
}
static __device__ __forceinline__ void ldsm_x4(uint32_t* r, uint32_t addr) {
    asm volatile("ldmatrix.sync.aligned.m8n8.x4.shared.b16 {%0,%1,%2,%3}, [%4];"
                 : "=r"(r[0]), "=r"(r[1]), "=r"(r[2]), "=r"(r[3]) : "r"(addr));
}
static __device__ __forceinline__ void mma_bf16(float* d, const uint32_t* a, const uint32_t* b) {
    asm volatile(
        "mma.sync.aligned.m16n8k16.row.col.f32.bf16.bf16.f32 "
        "{%0,%1,%2,%3}, {%4,%5,%6,%7}, {%8,%9}, {%0,%1,%2,%3};"
        : "+f"(d[0]), "+f"(d[1]), "+f"(d[2]), "+f"(d[3])
        : "r"(a[0]), "r"(a[1]), "r"(a[2]), "r"(a[3]), "r"(b[0]), "r"(b[1]));
}

// ---------------------------------------------------------------------------
// fp32 tiled GEMM + GELU (dense layer): C = GELU(A@B + bias)
// ---------------------------------------------------------------------------
__global__ void dense_gelu_kernel(const float* __restrict__ A,
                                  const float* __restrict__ B,
                                  const float* __restrict__ bias,
                                  float* __restrict__ C,
                                  int M, int N, int K) {
    constexpr int BK = 16;
    __shared__ __align__(16) float As[BK][64 + 4];
    __shared__ __align__(16) float Bs[BK][64];

    const int tx = threadIdx.x, ty = threadIdx.y;
    const int tid = ty * 16 + tx;
    const int m0 = blockIdx.y * 64;
    const int n0 = blockIdx.x * 64;

    float acc[4][4] = {};

    for (int k0 = 0; k0 < K; k0 += BK) {
        #pragma unroll
        for (int e = 0; e < 4; e++) {
            int lin = e * 256 + tid;
            int c = lin & 15, r = lin >> 4;
            As[c][r] = A[(size_t)(m0 + r) * K + k0 + c];
        }
        #pragma unroll
        for (int e = 0; e < 4; e++) {
            int lin = e * 256 + tid;
            int c = lin & 63, r = lin >> 6;
            Bs[r][c] = B[(size_t)(k0 + r) * N + n0 + c];
        }
        __syncthreads();
        #pragma unroll
        for (int kk = 0; kk < BK; kk++) {
            float4 av = *(const float4*)&As[kk][ty * 4];
            float4 bv = *(const float4*)&Bs[kk][tx * 4];
            float a[4] = {av.x, av.y, av.z, av.w};
            float b[4] = {bv.x, bv.y, bv.z, bv.w};
            #pragma unroll
            for (int i = 0; i < 4; i++)
                #pragma unroll
                for (int j = 0; j < 4; j++)
                    acc[i][j] += a[i] * b[j];
        }
        __syncthreads();
    }
    #pragma unroll
    for (int i = 0; i < 4; i++) {
        int row = m0 + ty * 4 + i;
        #pragma unroll
        for (int j = 0; j < 4; j++) {
            int col = n0 + tx * 4 + j;
            float v = acc[i][j] + bias[col];
            v = 0.5f * v * (1.0f + erff(v * 0.70710678118654752f));
            C[(size_t)row * N + col] = v;
        }
    }
}

// ---------------------------------------------------------------------------
// Per-token LN -> ent -> sigmoid -> quantum sim -> probs (written as bf16 hi/lo)
// ---------------------------------------------------------------------------
__global__ void token_quantum_kernel(const float* __restrict__ ln_w,
                                     const float* __restrict__ ln_b,
                                     const float* __restrict__ ent_w,
                                     const float* __restrict__ ent_b) {
    const int t = blockIdx.x;
    const int tid = threadIdx.x;
    const int lane = tid & 31;
    const int wrp = tid >> 5;

    __shared__ float hn[HIDDEN];
    __shared__ float red[16];
    __shared__ float ang[NANG];
    __shared__ float sre[QDIM];
    __shared__ float smi[QDIM];

    const float* hrow = g_H + (size_t)t * HIDDEN;

    float lsum = 0.0f;
    for (int k = tid; k < HIDDEN; k += 256) {
        float v = hrow[k];
        hn[k] = v;
        lsum += v;
    }
    #pragma unroll
    for (int o = 16; o; o >>= 1) lsum += __shfl_xor_sync(0xffffffffu, lsum, o);
    if (lane == 0) red[wrp] = lsum;
    __syncthreads();
    float mean = 0.0f;
    #pragma unroll
    for (int w = 0; w < 8; w++) mean += red[w];
    mean *= (1.0f / HIDDEN);

    float lsq = 0.0f;
    for (int k = tid; k < HIDDEN; k += 256) {
        float d = hn[k] - mean;
        lsq += d * d;
    }
    #pragma unroll
    for (int o = 16; o; o >>= 1) lsq += __shfl_xor_sync(0xffffffffu, lsq, o);
    if (lane == 0) red[8 + wrp] = lsq;
    __syncthreads();
    float var = 0.0f;
    #pragma unroll
    for (int w = 0; w < 8; w++) var += red[8 + w];
    var *= (1.0f / HIDDEN);
    float rstd = rsqrtf(var + 1e-12f);

    for (int k = tid; k < HIDDEN; k += 256)
        hn[k] = ln_w[k] * ((hn[k] - mean) * rstd) + ln_b[k];
    __syncthreads();

    for (int j = wrp; j < NANG; j += 8) {
        float acc = 0.0f;
        for (int k = lane; k < HIDDEN; k += 32)
            acc += hn[k] * ent_w[(size_t)k * NANG + j];
        #pragma unroll
        for (int o = 16; o; o >>= 1) acc += __shfl_xor_sync(0xffffffffu, acc, o);
        if (lane == 0) {
            float z = acc + ent_b[j];
            ang[j] = 6.28318530717958647692f / (1.0f + expf(-z));
        }
    }
    __syncthreads();

    for (int i = tid; i < QDIM; i += 256) {
        sre[i] = (i == 0) ? 1.0f : 0.0f;
        smi[i] = 0.0f;
    }
    __syncthreads();

    #pragma unroll 1
    for (int l = 0; l < 2; l++) {
        #pragma unroll 1
        for (int q = 0; q < 10; q++) {
            float th = ang[l * 10 + q] * 0.5f;
            float sth, cth;
            sincosf(th, &sth, &cth);
            int pos = 9 - q;
            int lowmask = (1 << pos) - 1;
            #pragma unroll
            for (int pp = 0; pp < 2; pp++) {
                int p = tid + pp * 256;
                int i0 = ((p & ~lowmask) << 1) | (p & lowmask);
                int i1 = i0 | (1 << pos);
                float a0r = sre[i0], a0i = smi[i0];
                float a1r = sre[i1], a1i = smi[i1];
                sre[i0] = cth * a0r + sth * a1i;
                smi[i0] = cth * a0i - sth * a1r;
                sre[i1] = cth * a1r + sth * a0i;
                smi[i1] = cth * a1i - sth * a0r;
            }
            __syncthreads();
        }
        #pragma unroll 1
        for (int q = 0; q < 10; q++) {
            int tq = (q + 1) % 10;
            int cpos = 9 - q;
            int tpos = 9 - tq;
            int lo = cpos < tpos ? cpos : tpos;
            int hi = cpos > tpos ? cpos : tpos;
            int x = tid;
            x = ((x >> lo) << (lo + 1)) | (x & ((1 << lo) - 1));
            x = ((x >> hi) << (hi + 1)) | (x & ((1 << hi) - 1));
            int i = x | (1 << cpos);
            int j2 = i | (1 << tpos);
            float tr = sre[i]; sre[i] = sre[j2]; sre[j2] = tr;
            float ti = smi[i]; smi[i] = smi[j2]; smi[j2] = ti;
            __syncthreads();
        }
    }

    for (int i = tid; i < QDIM; i += 256) {
        float r = sre[i], im = smi[i];
        float p = r * r + im * im;
        __nv_bfloat16 h = __float2bfloat16(p);
        g_A_hi[(size_t)t * QDIM + i] = h;
        g_A_lo[(size_t)t * QDIM + i] = __float2bfloat16(p - __bfloat162float(h));
    }
}

// ---------------------------------------------------------------------------
// W [1024, 30522] fp32 -> Wt_hi/lo [30720, 1024] bf16 (transpose + split)
// ---------------------------------------------------------------------------
__global__ void conv_w_kernel(const float* __restrict__ W) {
    __shared__ float tile[32][33];
    int n0 = blockIdx.x * 32;
    int k0 = blockIdx.y * 32;
    int tx = threadIdx.x, ty = threadIdx.y;
    #pragma unroll
    for (int i = 0; i < 4; i++) {
        int k = k0 + ty + 8 * i;
        int n = n0 + tx;
        tile[ty + 8 * i][tx] = (n < VOCAB) ? W[(size_t)k * VOCAB + n] : 0.0f;
    }
    __syncthreads();
    #pragma unroll
    for (int i = 0; i < 4; i++) {
        int n = n0 + ty + 8 * i;
        int k = k0 + tx;
        float v = tile[tx][ty + 8 * i];
        __nv_bfloat16 h = __float2bfloat16(v);
        g_Wt_hi[(size_t)n * QDIM + k] = h;
        g_Wt_lo[(size_t)n * QDIM + k] = __float2bfloat16(v - __bfloat162float(h));
    }
}

// ---------------------------------------------------------------------------
// Proj GEMM via mma.sync bf16 (3-term split): out = P @ W + b
// BM=128, BN=256, BK=32; 16 warps (2x8), warp tile 64x32 (4 warps/SMSP).
// 3-stage cp.async ring; B-fragment double-buffered ldmatrix prefetch.
// Smem rows: 32 bf16 = 64B data padded to 80B stride -> conflict-free ldmatrix.
// ---------------------------------------------------------------------------
#define BM 128
#define BN 256
#define BKE 32
#define NCHUNK (QDIM / BKE)
#define NSTAGE 3
#define NTHR 512
#define ROWB 80
#define AHI 0
#define ALO (128 * ROWB)
#define BHI (2 * 128 * ROWB)
#define BLO (2 * 128 * ROWB + 256 * ROWB)
#define STAGE (2 * 128 * ROWB + 2 * 256 * ROWB)
#define PROJ_SMEM (NSTAGE * STAGE)

__global__ void __launch_bounds__(NTHR, 1)
proj_kernel(const float* __restrict__ bias, float* __restrict__ out) {
    extern __shared__ char dynsm[];
    const uint32_t smem0 = smem_u32(dynsm);

    const int tid = threadIdx.x;
    const int lane = tid & 31;
    const int wid = tid >> 5;
    const int warp_m = wid & 1;   // 0..1 -> 64 rows each
    const int warp_n = wid >> 1;  // 0..7 -> 32 cols each
    const int m0 = blockIdx.x * BM;
    const int n0 = blockIdx.y * BN;

    const __nv_bfloat16* Ahg = g_A_hi + (size_t)m0 * QDIM;
    const __nv_bfloat16* Alg = g_A_lo + (size_t)m0 * QDIM;
    const __nv_bfloat16* Bhg = g_Wt_hi + (size_t)n0 * QDIM;
    const __nv_bfloat16* Blg = g_Wt_lo + (size_t)n0 * QDIM;

    // Issue cp.async loads for chunk c into stage c % NSTAGE.
    auto load_stage = [&](int c) {
        const int k0 = c * BKE;
        const uint32_t sb = smem0 + (c % NSTAGE) * STAGE;
        {   // A: 128 rows x 4 chunks of 16B = 512 items, one pass
            int row = tid >> 2, ch = tid & 3;
            size_t go = (size_t)row * QDIM + k0 + ch * 8;
            uint32_t so = row * ROWB + ch * 16;
            cp_async16(sb + AHI + so, Ahg + go);
            cp_async16(sb + ALO + so, Alg + go);
        }
        #pragma unroll
        for (int it = 0; it < 2; it++) {  // B: 256 rows x 4 chunks = 1024 items
            int idx = it * NTHR + tid;
            int row = idx >> 2, ch = idx & 3;
            size_t go = (size_t)row * QDIM + k0 + ch * 8;
            uint32_t so = row * ROWB + ch * 16;
            cp_async16(sb + BHI + so, Bhg + go);
            cp_async16(sb + BLO + so, Blg + go);
        }
        cp_commit();
    };

    float acc[4][4][4];
    #pragma unroll
    for (int i = 0; i < 4; i++)
        #pragma unroll
        for (int j = 0; j < 4; j++)
            #pragma unroll
            for (int e = 0; e < 4; e++) acc[i][j][e] = 0.0f;

    load_stage(0);
    load_stage(1);

    // A ldmatrix lane mapping (x4: 16 rows x 2 k-halves)
    const int arow = warp_m * 64 + (lane & 15);
    const int ach = lane >> 4;
    // B ldmatrix lane mapping (x4: 2 n-groups of 8 rows x 2 k-halves)
    const int bro = warp_n * 32 + (lane & 7) + ((lane >> 4) & 1) * 8;
    const int bkh = (lane >> 3) & 1;

    for (int c = 0; c < NCHUNK; c++) {
        cp_wait1();            // chunk c landed (only chunk c+1's group may be pending)
        __syncthreads();       // all warps consumed stage (c-1)%3 -> safe to overwrite
        if (c + 2 < NCHUNK) load_stage(c + 2);

        const uint32_t sb = smem0 + (c % NSTAGE) * STAGE;
        #pragma unroll
        for (int ks = 0; ks < 2; ks++) {
            // Load all A fragments for this k-step
            uint32_t ahi[4][4], alo[4][4];
            #pragma unroll
            for (int mi = 0; mi < 4; mi++) {
                uint32_t ao = (arow + mi * 16) * ROWB + (ks * 2 + ach) * 16;
                ldsm_x4(ahi[mi], sb + AHI + ao);
                ldsm_x4(alo[mi], sb + ALO + ao);
            }
            // B double-buffer: each x4 covers 2 n-groups (16 cols); 2 buffers
            uint32_t bh[2][4], bl[2][4];
            {
                uint32_t bo = bro * ROWB + (ks * 2 + bkh) * 16;
                ldsm_x4(bh[0], sb + BHI + bo);
                ldsm_x4(bl[0], sb + BLO + bo);
            }
            #pragma unroll
            for (int nj = 0; nj < 2; nj++) {
                const int cur = nj & 1, nxt = cur ^ 1;
                if (nj < 1) {
                    uint32_t bo = (bro + 16) * ROWB + (ks * 2 + bkh) * 16;
                    ldsm_x4(bh[nxt], sb + BHI + bo);
                    ldsm_x4(bl[nxt], sb + BLO + bo);
                }
                #pragma unroll
                for (int mi = 0; mi < 4; mi++)
                    #pragma unroll
                    for (int g = 0; g < 2; g++) {
                        float* ac = acc[mi][2 * nj + g];
                        mma_bf16(ac, ahi[mi], &bh[cur][2 * g]);
                        mma_bf16(ac, ahi[mi], &bl[cur][2 * g]);
                        mma_bf16(ac, alo[mi], &bh[cur][2 * g]);
                    }
            }
        }
    }

    // ---- epilogue ----
    const int qr = lane >> 2;        // 0..7
    const int qc = (lane & 3) * 2;   // 0,2,4,6
    #pragma unroll
    for (int mi = 0; mi < 4; mi++) {
        #pragma unroll
        for (int ni = 0; ni < 4; ni++) {
            int row = m0 + warp_m * 64 + mi * 16 + qr;
            int col = n0 + warp_n * 32 + ni * 8 + qc;
            #pragma unroll
            for (int h = 0; h < 2; h++) {  // h=0: row, h=1: row+8
                int r = row + h * 8;
                float v0 = acc[mi][ni][h * 2 + 0];
                float v1 = acc[mi][ni][h * 2 + 1];
                if (col + 1 < VOCAB) {
                    float2 o;
                    o.x = v0 + bias[col];
                    o.y = v1 + bias[col + 1];
                    *(float2*)(out + (size_t)r * VOCAB + col) = o;
                } else if (col < VOCAB) {
                    out[(size_t)r * VOCAB + col] = v0 + bias[col];
                }
            }
        }
    }
}

// ---------------------------------------------------------------------------
extern "C" void kernel_launch(void* const* d_in, const int* in_sizes, int n_in,
                              void* d_out, int out_size) {
    const float* hidden  = (const float*)d_in[0];
    const float* dense_w = (const float*)d_in[1];
    const float* dense_b = (const float*)d_in[2];
    const float* ln_w    = (const float*)d_in[3];
    const float* ln_b    = (const float*)d_in[4];
    const float* ent_w   = (const float*)d_in[5];
    const float* ent_b   = (const float*)d_in[6];
    const float* proj_w  = (const float*)d_in[7];
    const float* proj_b  = (const float*)d_in[8];
    float* out = (float*)d_out;

    float* Hptr = nullptr;
    cudaGetSymbolAddress((void**)&Hptr, g_H);

    cudaFuncSetAttribute(proj_kernel, cudaFuncAttributeMaxDynamicSharedMemorySize, PROJ_SMEM);

    // 0) W transpose + bf16 split
    conv_w_kernel<<<dim3((VOCAB + 31) / 32, QDIM / 32), dim3(32, 8)>>>(proj_w);

    // 1) dense + GELU
    dense_gelu_kernel<<<dim3(HIDDEN / 64, NTOK / 64), dim3(16, 16)>>>(
        hidden, dense_w, dense_b, Hptr, NTOK, HIDDEN, HIDDEN);

    // 2) LN + ent + sigmoid + quantum sim -> probs (bf16 hi/lo)
    token_quantum_kernel<<<NTOK, 256>>>(ln_w, ln_b, ent_w, ent_b);

    // 3) proj via mma.sync split-bf16 (grid: M fastest for W reuse in L2)
    proj_kernel<<<dim3(NTOK / BM, VOCAB_PAD / BN), NTHR, PROJ_SMEM>>>(proj_b, out);
}

// round 10
// speedup vs baseline: 4.1001x; 1.2898x over previous
#include <cuda_runtime.h>
#include <cuda_bf16.h>
#include <cuda_fp16.h>
#include <math.h>
#include <stdint.h>

#define HIDDEN 768
#define NTOK   4096
#define QDIM   1024
#define VOCAB  30522
#define VOCAB_PAD 30720
#define NANG   20

// ---------------- device scratch (allocation-free) ----------------
__device__ float  g_H[NTOK * HIDDEN];          // post-GELU dense output
__device__ __half g_A_h[NTOK * QDIM];          // probs hi (fp16)
__device__ __half g_A_l[NTOK * QDIM];          // probs lo (fp16 residual)
__device__ __half g_Wt_h[VOCAB_PAD * QDIM];    // proj_w^T fp16 (K-major)

// ---------------- portable PTX helpers (no sm_103a features) ----------------
static __device__ __forceinline__ uint32_t smem_u32(const void* p) {
    uint32_t a;
    asm("{ .reg .u64 t; cvta.to.shared.u64 t, %1; cvt.u32.u64 %0, t; }" : "=r"(a) : "l"(p));
    return a;
}
static __device__ __forceinline__ void cp_async16(uint32_t dst, const void* src) {
    asm volatile("cp.async.cg.shared.global [%0], [%1], 16;" :: "r"(dst), "l"(src) : "memory");
}
static __device__ __forceinline__ void cp_commit() {
    asm volatile("cp.async.commit_group;" ::: "memory");
}
static __device__ __forceinline__ void cp_wait1() {
    asm volatile("cp.async.wait_group 1;" ::: "memory");
}
static __device__ __forceinline__ void ldsm_x4(uint32_t* r, uint32_t addr) {
    asm volatile("ldmatrix.sync.aligned.m8n8.x4.shared.b16 {%0,%1,%2,%3}, [%4];"
                 : "=r"(r[0]), "=r"(r[1]), "=r"(r[2]), "=r"(r[3]) : "r"(addr));
}
static __device__ __forceinline__ void mma_f16(float* d, const uint32_t* a, const uint32_t* b) {
    asm volatile(
        "mma.sync.aligned.m16n8k16.row.col.f32.f16.f16.f32 "
        "{%0,%1,%2,%3}, {%4,%5,%6,%7}, {%8,%9}, {%0,%1,%2,%3};"
        : "+f"(d[0]), "+f"(d[1]), "+f"(d[2]), "+f"(d[3])
        : "r"(a[0]), "r"(a[1]), "r"(a[2]), "r"(a[3]), "r"(b[0]), "r"(b[1]));
}

// ---------------------------------------------------------------------------
// fp32 tiled GEMM + GELU (dense layer): C = GELU(A@B + bias)
// ---------------------------------------------------------------------------
__global__ void dense_gelu_kernel(const float* __restrict__ A,
                                  const float* __restrict__ B,
                                  const float* __restrict__ bias,
                                  float* __restrict__ C,
                                  int M, int N, int K) {
    constexpr int BK = 16;
    __shared__ __align__(16) float As[BK][64 + 4];
    __shared__ __align__(16) float Bs[BK][64];

    const int tx = threadIdx.x, ty = threadIdx.y;
    const int tid = ty * 16 + tx;
    const int m0 = blockIdx.y * 64;
    const int n0 = blockIdx.x * 64;

    float acc[4][4] = {};

    for (int k0 = 0; k0 < K; k0 += BK) {
        #pragma unroll
        for (int e = 0; e < 4; e++) {
            int lin = e * 256 + tid;
            int c = lin & 15, r = lin >> 4;
            As[c][r] = A[(size_t)(m0 + r) * K + k0 + c];
        }
        #pragma unroll
        for (int e = 0; e < 4; e++) {
            int lin = e * 256 + tid;
            int c = lin & 63, r = lin >> 6;
            Bs[r][c] = B[(size_t)(k0 + r) * N + n0 + c];
        }
        __syncthreads();
        #pragma unroll
        for (int kk = 0; kk < BK; kk++) {
            float4 av = *(const float4*)&As[kk][ty * 4];
            float4 bv = *(const float4*)&Bs[kk][tx * 4];
            float a[4] = {av.x, av.y, av.z, av.w};
            float b[4] = {bv.x, bv.y, bv.z, bv.w};
            #pragma unroll
            for (int i = 0; i < 4; i++)
                #pragma unroll
                for (int j = 0; j < 4; j++)
                    acc[i][j] += a[i] * b[j];
        }
        __syncthreads();
    }
    #pragma unroll
    for (int i = 0; i < 4; i++) {
        int row = m0 + ty * 4 + i;
        #pragma unroll
        for (int j = 0; j < 4; j++) {
            int col = n0 + tx * 4 + j;
            float v = acc[i][j] + bias[col];
            v = 0.5f * v * (1.0f + erff(v * 0.70710678118654752f));
            C[(size_t)row * N + col] = v;
        }
    }
}

// ---------------------------------------------------------------------------
// Per-token LN -> ent -> sigmoid -> quantum sim -> probs (written as fp16 hi/lo)
// ---------------------------------------------------------------------------
__global__ void token_quantum_kernel(const float* __restrict__ ln_w,
                                     const float* __restrict__ ln_b,
                                     const float* __restrict__ ent_w,
                                     const float* __restrict__ ent_b) {
    const int t = blockIdx.x;
    const int tid = threadIdx.x;
    const int lane = tid & 31;
    const int wrp = tid >> 5;

    __shared__ float hn[HIDDEN];
    __shared__ float red[16];
    __shared__ float ang[NANG];
    __shared__ float sre[QDIM];
    __shared__ float smi[QDIM];

    const float* hrow = g_H + (size_t)t * HIDDEN;

    float lsum = 0.0f;
    for (int k = tid; k < HIDDEN; k += 256) {
        float v = hrow[k];
        hn[k] = v;
        lsum += v;
    }
    #pragma unroll
    for (int o = 16; o; o >>= 1) lsum += __shfl_xor_sync(0xffffffffu, lsum, o);
    if (lane == 0) red[wrp] = lsum;
    __syncthreads();
    float mean = 0.0f;
    #pragma unroll
    for (int w = 0; w < 8; w++) mean += red[w];
    mean *= (1.0f / HIDDEN);

    float lsq = 0.0f;
    for (int k = tid; k < HIDDEN; k += 256) {
        float d = hn[k] - mean;
        lsq += d * d;
    }
    #pragma unroll
    for (int o = 16; o; o >>= 1) lsq += __shfl_xor_sync(0xffffffffu, lsq, o);
    if (lane == 0) red[8 + wrp] = lsq;
    __syncthreads();
    float var = 0.0f;
    #pragma unroll
    for (int w = 0; w < 8; w++) var += red[8 + w];
    var *= (1.0f / HIDDEN);
    float rstd = rsqrtf(var + 1e-12f);

    for (int k = tid; k < HIDDEN; k += 256)
        hn[k] = ln_w[k] * ((hn[k] - mean) * rstd) + ln_b[k];
    __syncthreads();

    for (int j = wrp; j < NANG; j += 8) {
        float acc = 0.0f;
        for (int k = lane; k < HIDDEN; k += 32)
            acc += hn[k] * ent_w[(size_t)k * NANG + j];
        #pragma unroll
        for (int o = 16; o; o >>= 1) acc += __shfl_xor_sync(0xffffffffu, acc, o);
        if (lane == 0) {
            float z = acc + ent_b[j];
            ang[j] = 6.28318530717958647692f / (1.0f + expf(-z));
        }
    }
    __syncthreads();

    for (int i = tid; i < QDIM; i += 256) {
        sre[i] = (i == 0) ? 1.0f : 0.0f;
        smi[i] = 0.0f;
    }
    __syncthreads();

    #pragma unroll 1
    for (int l = 0; l < 2; l++) {
        #pragma unroll 1
        for (int q = 0; q < 10; q++) {
            float th = ang[l * 10 + q] * 0.5f;
            float sth, cth;
            sincosf(th, &sth, &cth);
            int pos = 9 - q;
            int lowmask = (1 << pos) - 1;
            #pragma unroll
            for (int pp = 0; pp < 2; pp++) {
                int p = tid + pp * 256;
                int i0 = ((p & ~lowmask) << 1) | (p & lowmask);
                int i1 = i0 | (1 << pos);
                float a0r = sre[i0], a0i = smi[i0];
                float a1r = sre[i1], a1i = smi[i1];
                sre[i0] = cth * a0r + sth * a1i;
                smi[i0] = cth * a0i - sth * a1r;
                sre[i1] = cth * a1r + sth * a0i;
                smi[i1] = cth * a1i - sth * a0r;
            }
            __syncthreads();
        }
        #pragma unroll 1
        for (int q = 0; q < 10; q++) {
            int tq = (q + 1) % 10;
            int cpos = 9 - q;
            int tpos = 9 - tq;
            int lo = cpos < tpos ? cpos : tpos;
            int hi = cpos > tpos ? cpos : tpos;
            int x = tid;
            x = ((x >> lo) << (lo + 1)) | (x & ((1 << lo) - 1));
            x = ((x >> hi) << (hi + 1)) | (x & ((1 << hi) - 1));
            int i = x | (1 << cpos);
            int j2 = i | (1 << tpos);
            float tr = sre[i]; sre[i] = sre[j2]; sre[j2] = tr;
            float ti = smi[i]; smi[i] = smi[j2]; smi[j2] = ti;
            __syncthreads();
        }
    }

    for (int i = tid; i < QDIM; i += 256) {
        float r = sre[i], im = smi[i];
        float p = r * r + im * im;
        __half h = __float2half_rn(p);
        g_A_h[(size_t)t * QDIM + i] = h;
        g_A_l[(size_t)t * QDIM + i] = __float2half_rn(p - __half2float(h));
    }
}

// ---------------------------------------------------------------------------
// W [1024, 30522] fp32 -> Wt_h [30720, 1024] fp16 (transpose)
// ---------------------------------------------------------------------------
__global__ void conv_w_kernel(const float* __restrict__ W) {
    __shared__ float tile[32][33];
    int n0 = blockIdx.x * 32;
    int k0 = blockIdx.y * 32;
    int tx = threadIdx.x, ty = threadIdx.y;
    #pragma unroll
    for (int i = 0; i < 4; i++) {
        int k = k0 + ty + 8 * i;
        int n = n0 + tx;
        tile[ty + 8 * i][tx] = (n < VOCAB) ? W[(size_t)k * VOCAB + n] : 0.0f;
    }
    __syncthreads();
    #pragma unroll
    for (int i = 0; i < 4; i++) {
        int n = n0 + ty + 8 * i;
        int k = k0 + tx;
        g_Wt_h[(size_t)n * QDIM + k] = __float2half_rn(tile[tx][ty + 8 * i]);
    }
}

// ---------------------------------------------------------------------------
// Proj GEMM via mma.sync fp16 (2-term split): out = (Ah+Al) @ B + bias
// BM=128, BN=256, BK=32; 16 warps (2x8), warp tile 64x32 (4 warps/SMSP).
// 3-stage cp.async ring. Smem rows 64B data padded to 80B -> conflict-free ldsm.
// ---------------------------------------------------------------------------
#define BM 128
#define BN 256
#define BKE 32
#define NCHUNK (QDIM / BKE)
#define NSTAGE 3
#define NTHR 512
#define ROWB 80
#define AHI 0
#define ALO (128 * ROWB)
#define BHI (2 * 128 * ROWB)
#define STAGE (2 * 128 * ROWB + 256 * ROWB)
#define PROJ_SMEM (NSTAGE * STAGE)

__global__ void __launch_bounds__(NTHR, 1)
proj_kernel(const float* __restrict__ bias, float* __restrict__ out) {
    extern __shared__ char dynsm[];
    const uint32_t smem0 = smem_u32(dynsm);

    const int tid = threadIdx.x;
    const int lane = tid & 31;
    const int wid = tid >> 5;
    const int warp_m = wid & 1;   // 0..1 -> 64 rows each
    const int warp_n = wid >> 1;  // 0..7 -> 32 cols each
    const int m0 = blockIdx.x * BM;
    const int n0 = blockIdx.y * BN;

    const __half* Ahg = g_A_h + (size_t)m0 * QDIM;
    const __half* Alg = g_A_l + (size_t)m0 * QDIM;
    const __half* Bhg = g_Wt_h + (size_t)n0 * QDIM;

    // Issue cp.async loads for chunk c into stage c % NSTAGE.
    auto load_stage = [&](int c) {
        const int k0 = c * BKE;
        const uint32_t sb = smem0 + (c % NSTAGE) * STAGE;
        {   // A: 128 rows x 4 chunks of 16B = 512 items, one pass (hi+lo)
            int row = tid >> 2, ch = tid & 3;
            size_t go = (size_t)row * QDIM + k0 + ch * 8;
            uint32_t so = row * ROWB + ch * 16;
            cp_async16(sb + AHI + so, Ahg + go);
            cp_async16(sb + ALO + so, Alg + go);
        }
        #pragma unroll
        for (int it = 0; it < 2; it++) {  // B: 256 rows x 4 chunks = 1024 items
            int idx = it * NTHR + tid;
            int row = idx >> 2, ch = idx & 3;
            size_t go = (size_t)row * QDIM + k0 + ch * 8;
            uint32_t so = row * ROWB + ch * 16;
            cp_async16(sb + BHI + so, Bhg + go);
        }
        cp_commit();
    };

    float acc[4][4][4];
    #pragma unroll
    for (int i = 0; i < 4; i++)
        #pragma unroll
        for (int j = 0; j < 4; j++)
            #pragma unroll
            for (int e = 0; e < 4; e++) acc[i][j][e] = 0.0f;

    load_stage(0);
    load_stage(1);

    // A ldmatrix lane mapping (x4: 16 rows x 2 k-halves)
    const int arow = warp_m * 64 + (lane & 15);
    const int ach = lane >> 4;
    // B ldmatrix lane mapping (x4: 2 n-groups of 8 rows x 2 k-halves)
    const int bro = warp_n * 32 + (lane & 7) + ((lane >> 4) & 1) * 8;
    const int bkh = (lane >> 3) & 1;

    for (int c = 0; c < NCHUNK; c++) {
        cp_wait1();            // chunk c landed (only chunk c+1's group may be pending)
        __syncthreads();       // all warps consumed stage (c-1)%3 -> safe to overwrite
        if (c + 2 < NCHUNK) load_stage(c + 2);

        const uint32_t sb = smem0 + (c % NSTAGE) * STAGE;
        #pragma unroll
        for (int ks = 0; ks < 2; ks++) {
            // Load all A fragments for this k-step
            uint32_t ahi[4][4], alo[4][4];
            #pragma unroll
            for (int mi = 0; mi < 4; mi++) {
                uint32_t ao = (arow + mi * 16) * ROWB + (ks * 2 + ach) * 16;
                ldsm_x4(ahi[mi], sb + AHI + ao);
                ldsm_x4(alo[mi], sb + ALO + ao);
            }
            // B double-buffer: each x4 covers 2 n-groups (16 cols); 2 buffers
            uint32_t bh[2][4];
            {
                uint32_t bo = bro * ROWB + (ks * 2 + bkh) * 16;
                ldsm_x4(bh[0], sb + BHI + bo);
            }
            #pragma unroll
            for (int nj = 0; nj < 2; nj++) {
                const int cur = nj & 1, nxt = cur ^ 1;
                if (nj < 1) {
                    uint32_t bo = (bro + 16) * ROWB + (ks * 2 + bkh) * 16;
                    ldsm_x4(bh[nxt], sb + BHI + bo);
                }
                #pragma unroll
                for (int mi = 0; mi < 4; mi++)
                    #pragma unroll
                    for (int g = 0; g < 2; g++) {
                        float* ac = acc[mi][2 * nj + g];
                        mma_f16(ac, ahi[mi], &bh[cur][2 * g]);
                        mma_f16(ac, alo[mi], &bh[cur][2 * g]);
                    }
            }
        }
    }

    // ---- epilogue ----
    const int qr = lane >> 2;        // 0..7
    const int qc = (lane & 3) * 2;   // 0,2,4,6
    #pragma unroll
    for (int mi = 0; mi < 4; mi++) {
        #pragma unroll
        for (int ni = 0; ni < 4; ni++) {
            int row = m0 + warp_m * 64 + mi * 16 + qr;
            int col = n0 + warp_n * 32 + ni * 8 + qc;
            #pragma unroll
            for (int h = 0; h < 2; h++) {  // h=0: row, h=1: row+8
                int r = row + h * 8;
                float v0 = acc[mi][ni][h * 2 + 0];
                float v1 = acc[mi][ni][h * 2 + 1];
                if (col + 1 < VOCAB) {
                    float2 o;
                    o.x = v0 + bias[col];
                    o.y = v1 + bias[col + 1];
                    *(float2*)(out + (size_t)r * VOCAB + col) = o;
                } else if (col < VOCAB) {
                    out[(size_t)r * VOCAB + col] = v0 + bias[col];
                }
            }
        }
    }
}

// ---------------------------------------------------------------------------
extern "C" void kernel_launch(void* const* d_in, const int* in_sizes, int n_in,
                              void* d_out, int out_size) {
    const float* hidden  = (const float*)d_in[0];
    const float* dense_w = (const float*)d_in[1];
    const float* dense_b = (const float*)d_in[2];
    const float* ln_w    = (const float*)d_in[3];
    const float* ln_b    = (const float*)d_in[4];
    const float* ent_w   = (const float*)d_in[5];
    const float* ent_b   = (const float*)d_in[6];
    const float* proj_w  = (const float*)d_in[7];
    const float* proj_b  = (const float*)d_in[8];
    float* out = (float*)d_out;

    float* Hptr = nullptr;
    cudaGetSymbolAddress((void**)&Hptr, g_H);

    cudaFuncSetAttribute(proj_kernel, cudaFuncAttributeMaxDynamicSharedMemorySize, PROJ_SMEM);

    // 0) W transpose to fp16 (K-major)
    conv_w_kernel<<<dim3((VOCAB + 31) / 32, QDIM / 32), dim3(32, 8)>>>(proj_w);

    // 1) dense + GELU
    dense_gelu_kernel<<<dim3(HIDDEN / 64, NTOK / 64), dim3(16, 16)>>>(
        hidden, dense_w, dense_b, Hptr, NTOK, HIDDEN, HIDDEN);

    // 2) LN + ent + sigmoid + quantum sim -> probs (fp16 hi/lo)
    token_quantum_kernel<<<NTOK, 256>>>(ln_w, ln_b, ent_w, ent_b);

    // 3) proj via mma.sync fp16 2-term split
    proj_kernel<<<dim3(NTOK / BM, VOCAB_PAD / BN), NTHR, PROJ_SMEM>>>(proj_b, out);
}

// round 11
// speedup vs baseline: 5.8579x; 1.4287x over previous
#include <cuda_runtime.h>
#include <cuda_bf16.h>
#include <cuda_fp16.h>
#include <math.h>
#include <stdint.h>

#define HIDDEN 768
#define NTOK   4096
#define QDIM   1024
#define VOCAB  30522
#define VOCAB_PAD 30720
#define NANG   20

// ---------------- device scratch (allocation-free) ----------------
__device__ float  g_H[NTOK * HIDDEN];          // post-GELU dense output
__device__ __half g_A_h[NTOK * QDIM];          // probs (fp16)
__device__ __half g_Wt_h[VOCAB_PAD * QDIM];    // proj_w^T fp16 (K-major)

// ---------------- portable PTX helpers (no sm_103a features) ----------------
static __device__ __forceinline__ uint32_t smem_u32(const void* p) {
    uint32_t a;
    asm("{ .reg .u64 t; cvta.to.shared.u64 t, %1; cvt.u32.u64 %0, t; }" : "=r"(a) : "l"(p));
    return a;
}
static __device__ __forceinline__ void cp_async16(uint32_t dst, const void* src) {
    asm volatile("cp.async.cg.shared.global [%0], [%1], 16;" :: "r"(dst), "l"(src) : "memory");
}
static __device__ __forceinline__ void cp_commit() {
    asm volatile("cp.async.commit_group;" ::: "memory");
}
static __device__ __forceinline__ void cp_wait2() {
    asm volatile("cp.async.wait_group 2;" ::: "memory");
}
static __device__ __forceinline__ void ldsm_x4(uint32_t* r, uint32_t addr) {
    asm volatile("ldmatrix.sync.aligned.m8n8.x4.shared.b16 {%0,%1,%2,%3}, [%4];"
                 : "=r"(r[0]), "=r"(r[1]), "=r"(r[2]), "=r"(r[3]) : "r"(addr));
}
static __device__ __forceinline__ void mma_f16(float* d, const uint32_t* a, const uint32_t* b) {
    asm volatile(
        "mma.sync.aligned.m16n8k16.row.col.f32.f16.f16.f32 "
        "{%0,%1,%2,%3}, {%4,%5,%6,%7}, {%8,%9}, {%0,%1,%2,%3};"
        : "+f"(d[0]), "+f"(d[1]), "+f"(d[2]), "+f"(d[3])
        : "r"(a[0]), "r"(a[1]), "r"(a[2]), "r"(a[3]), "r"(b[0]), "r"(b[1]));
}

// ---------------------------------------------------------------------------
// fp32 tiled GEMM + GELU (dense layer): C = GELU(A@B + bias)
// ---------------------------------------------------------------------------
__global__ void dense_gelu_kernel(const float* __restrict__ A,
                                  const float* __restrict__ B,
                                  const float* __restrict__ bias,
                                  float* __restrict__ C,
                                  int M, int N, int K) {
    constexpr int BK = 16;
    __shared__ __align__(16) float As[BK][64 + 4];
    __shared__ __align__(16) float Bs[BK][64];

    const int tx = threadIdx.x, ty = threadIdx.y;
    const int tid = ty * 16 + tx;
    const int m0 = blockIdx.y * 64;
    const int n0 = blockIdx.x * 64;

    float acc[4][4] = {};

    for (int k0 = 0; k0 < K; k0 += BK) {
        #pragma unroll
        for (int e = 0; e < 4; e++) {
            int lin = e * 256 + tid;
            int c = lin & 15, r = lin >> 4;
            As[c][r] = A[(size_t)(m0 + r) * K + k0 + c];
        }
        #pragma unroll
        for (int e = 0; e < 4; e++) {
            int lin = e * 256 + tid;
            int c = lin & 63, r = lin >> 6;
            Bs[r][c] = B[(size_t)(k0 + r) * N + n0 + c];
        }
        __syncthreads();
        #pragma unroll
        for (int kk = 0; kk < BK; kk++) {
            float4 av = *(const float4*)&As[kk][ty * 4];
            float4 bv = *(const float4*)&Bs[kk][tx * 4];
            float a[4] = {av.x, av.y, av.z, av.w};
            float b[4] = {bv.x, bv.y, bv.z, bv.w};
            #pragma unroll
            for (int i = 0; i < 4; i++)
                #pragma unroll
                for (int j = 0; j < 4; j++)
                    acc[i][j] += a[i] * b[j];
        }
        __syncthreads();
    }
    #pragma unroll
    for (int i = 0; i < 4; i++) {
        int row = m0 + ty * 4 + i;
        #pragma unroll
        for (int j = 0; j < 4; j++) {
            int col = n0 + tx * 4 + j;
            float v = acc[i][j] + bias[col];
            v = 0.5f * v * (1.0f + erff(v * 0.70710678118654752f));
            C[(size_t)row * N + col] = v;
        }
    }
}

// ---------------------------------------------------------------------------
// Per-token LN -> ent -> sigmoid -> quantum sim -> probs (fp16)
// ---------------------------------------------------------------------------
__global__ void token_quantum_kernel(const float* __restrict__ ln_w,
                                     const float* __restrict__ ln_b,
                                     const float* __restrict__ ent_w,
                                     const float* __restrict__ ent_b) {
    const int t = blockIdx.x;
    const int tid = threadIdx.x;
    const int lane = tid & 31;
    const int wrp = tid >> 5;

    __shared__ float hn[HIDDEN];
    __shared__ float red[16];
    __shared__ float ang[NANG];
    __shared__ float sre[QDIM];
    __shared__ float smi[QDIM];

    const float* hrow = g_H + (size_t)t * HIDDEN;

    float lsum = 0.0f;
    for (int k = tid; k < HIDDEN; k += 256) {
        float v = hrow[k];
        hn[k] = v;
        lsum += v;
    }
    #pragma unroll
    for (int o = 16; o; o >>= 1) lsum += __shfl_xor_sync(0xffffffffu, lsum, o);
    if (lane == 0) red[wrp] = lsum;
    __syncthreads();
    float mean = 0.0f;
    #pragma unroll
    for (int w = 0; w < 8; w++) mean += red[w];
    mean *= (1.0f / HIDDEN);

    float lsq = 0.0f;
    for (int k = tid; k < HIDDEN; k += 256) {
        float d = hn[k] - mean;
        lsq += d * d;
    }
    #pragma unroll
    for (int o = 16; o; o >>= 1) lsq += __shfl_xor_sync(0xffffffffu, lsq, o);
    if (lane == 0) red[8 + wrp] = lsq;
    __syncthreads();
    float var = 0.0f;
    #pragma unroll
    for (int w = 0; w < 8; w++) var += red[8 + w];
    var *= (1.0f / HIDDEN);
    float rstd = rsqrtf(var + 1e-12f);

    for (int k = tid; k < HIDDEN; k += 256)
        hn[k] = ln_w[k] * ((hn[k] - mean) * rstd) + ln_b[k];
    __syncthreads();

    for (int j = wrp; j < NANG; j += 8) {
        float acc = 0.0f;
        for (int k = lane; k < HIDDEN; k += 32)
            acc += hn[k] * ent_w[(size_t)k * NANG + j];
        #pragma unroll
        for (int o = 16; o; o >>= 1) acc += __shfl_xor_sync(0xffffffffu, acc, o);
        if (lane == 0) {
            float z = acc + ent_b[j];
            ang[j] = 6.28318530717958647692f / (1.0f + expf(-z));
        }
    }
    __syncthreads();

    for (int i = tid; i < QDIM; i += 256) {
        sre[i] = (i == 0) ? 1.0f : 0.0f;
        smi[i] = 0.0f;
    }
    __syncthreads();

    #pragma unroll 1
    for (int l = 0; l < 2; l++) {
        #pragma unroll 1
        for (int q = 0; q < 10; q++) {
            float th = ang[l * 10 + q] * 0.5f;
            float sth, cth;
            sincosf(th, &sth, &cth);
            int pos = 9 - q;
            int lowmask = (1 << pos) - 1;
            #pragma unroll
            for (int pp = 0; pp < 2; pp++) {
                int p = tid + pp * 256;
                int i0 = ((p & ~lowmask) << 1) | (p & lowmask);
                int i1 = i0 | (1 << pos);
                float a0r = sre[i0], a0i = smi[i0];
                float a1r = sre[i1], a1i = smi[i1];
                sre[i0] = cth * a0r + sth * a1i;
                smi[i0] = cth * a0i - sth * a1r;
                sre[i1] = cth * a1r + sth * a0i;
                smi[i1] = cth * a1i - sth * a0r;
            }
            __syncthreads();
        }
        #pragma unroll 1
        for (int q = 0; q < 10; q++) {
            int tq = (q + 1) % 10;
            int cpos = 9 - q;
            int tpos = 9 - tq;
            int lo = cpos < tpos ? cpos : tpos;
            int hi = cpos > tpos ? cpos : tpos;
            int x = tid;
            x = ((x >> lo) << (lo + 1)) | (x & ((1 << lo) - 1));
            x = ((x >> hi) << (hi + 1)) | (x & ((1 << hi) - 1));
            int i = x | (1 << cpos);
            int j2 = i | (1 << tpos);
            float tr = sre[i]; sre[i] = sre[j2]; sre[j2] = tr;
            float ti = smi[i]; smi[i] = smi[j2]; smi[j2] = ti;
            __syncthreads();
        }
    }

    for (int i = tid; i < QDIM; i += 256) {
        float r = sre[i], im = smi[i];
        g_A_h[(size_t)t * QDIM + i] = __float2half_rn(r * r + im * im);
    }
}

// ---------------------------------------------------------------------------
// W [1024, 30522] fp32 -> Wt_h [30720, 1024] fp16 (transpose)
// ---------------------------------------------------------------------------
__global__ void conv_w_kernel(const float* __restrict__ W) {
    __shared__ float tile[32][33];
    int n0 = blockIdx.x * 32;
    int k0 = blockIdx.y * 32;
    int tx = threadIdx.x, ty = threadIdx.y;
    #pragma unroll
    for (int i = 0; i < 4; i++) {
        int k = k0 + ty + 8 * i;
        int n = n0 + tx;
        tile[ty + 8 * i][tx] = (n < VOCAB) ? W[(size_t)k * VOCAB + n] : 0.0f;
    }
    __syncthreads();
    #pragma unroll
    for (int i = 0; i < 4; i++) {
        int n = n0 + ty + 8 * i;
        int k = k0 + tx;
        g_Wt_h[(size_t)n * QDIM + k] = __float2half_rn(tile[tx][ty + 8 * i]);
    }
}

// ---------------------------------------------------------------------------
// Proj GEMM via mma.sync fp16 (single term): out = A @ B + bias
// BM=128, BN=256, BK=32; 16 warps (2x8), warp tile 64x32 (4 warps/SMSP).
// 4-stage cp.async ring, 3-deep prefetch. 80B row stride -> conflict-free ldsm.
// ---------------------------------------------------------------------------
#define BM 128
#define BN 256
#define BKE 32
#define NCHUNK (QDIM / BKE)
#define NSTAGE 4
#define NTHR 512
#define ROWB 80
#define AHI 0
#define BHI (128 * ROWB)
#define STAGE (128 * ROWB + 256 * ROWB)
#define PROJ_SMEM (NSTAGE * STAGE)

__global__ void __launch_bounds__(NTHR, 1)
proj_kernel(const float* __restrict__ bias, float* __restrict__ out) {
    extern __shared__ char dynsm[];
    const uint32_t smem0 = smem_u32(dynsm);

    const int tid = threadIdx.x;
    const int lane = tid & 31;
    const int wid = tid >> 5;
    const int warp_m = wid & 1;   // 0..1 -> 64 rows each
    const int warp_n = wid >> 1;  // 0..7 -> 32 cols each
    const int m0 = blockIdx.x * BM;
    const int n0 = blockIdx.y * BN;

    const __half* Ahg = g_A_h + (size_t)m0 * QDIM;
    const __half* Bhg = g_Wt_h + (size_t)n0 * QDIM;

    // Issue cp.async loads for chunk c into stage c % NSTAGE.
    auto load_stage = [&](int c) {
        const int k0 = c * BKE;
        const uint32_t sb = smem0 + (c % NSTAGE) * STAGE;
        {   // A: 128 rows x 4 chunks of 16B = 512 items, one pass
            int row = tid >> 2, ch = tid & 3;
            size_t go = (size_t)row * QDIM + k0 + ch * 8;
            uint32_t so = row * ROWB + ch * 16;
            cp_async16(sb + AHI + so, Ahg + go);
        }
        #pragma unroll
        for (int it = 0; it < 2; it++) {  // B: 256 rows x 4 chunks = 1024 items
            int idx = it * NTHR + tid;
            int row = idx >> 2, ch = idx & 3;
            size_t go = (size_t)row * QDIM + k0 + ch * 8;
            uint32_t so = row * ROWB + ch * 16;
            cp_async16(sb + BHI + so, Bhg + go);
        }
        cp_commit();
    };

    float acc[4][4][4];
    #pragma unroll
    for (int i = 0; i < 4; i++)
        #pragma unroll
        for (int j = 0; j < 4; j++)
            #pragma unroll
            for (int e = 0; e < 4; e++) acc[i][j][e] = 0.0f;

    load_stage(0);
    load_stage(1);
    load_stage(2);

    // A ldmatrix lane mapping (x4: 16 rows x 2 k-halves)
    const int arow = warp_m * 64 + (lane & 15);
    const int ach = lane >> 4;
    // B ldmatrix lane mapping (x4: 2 n-groups of 8 rows x 2 k-halves)
    const int bro = warp_n * 32 + (lane & 7) + ((lane >> 4) & 1) * 8;
    const int bkh = (lane >> 3) & 1;

    for (int c = 0; c < NCHUNK; c++) {
        cp_wait2();            // chunk c landed (chunks c+1, c+2 may be pending)
        __syncthreads();       // all warps consumed stage (c-1)%4 -> safe to overwrite
        if (c + 3 < NCHUNK) load_stage(c + 3);

        const uint32_t sb = smem0 + (c % NSTAGE) * STAGE;
        #pragma unroll
        for (int ks = 0; ks < 2; ks++) {
            uint32_t ahi[4][4];
            #pragma unroll
            for (int mi = 0; mi < 4; mi++) {
                uint32_t ao = (arow + mi * 16) * ROWB + (ks * 2 + ach) * 16;
                ldsm_x4(ahi[mi], sb + AHI + ao);
            }
            uint32_t bh[2][4];
            {
                uint32_t bo = bro * ROWB + (ks * 2 + bkh) * 16;
                ldsm_x4(bh[0], sb + BHI + bo);
            }
            #pragma unroll
            for (int nj = 0; nj < 2; nj++) {
                const int cur = nj & 1, nxt = cur ^ 1;
                if (nj < 1) {
                    uint32_t bo = (bro + 16) * ROWB + (ks * 2 + bkh) * 16;
                    ldsm_x4(bh[nxt], sb + BHI + bo);
                }
                #pragma unroll
                for (int mi = 0; mi < 4; mi++)
                    #pragma unroll
                    for (int g = 0; g < 2; g++)
                        mma_f16(acc[mi][2 * nj + g], ahi[mi], &bh[cur][2 * g]);
            }
        }
    }

    // ---- epilogue ----
    const int qr = lane >> 2;        // 0..7
    const int qc = (lane & 3) * 2;   // 0,2,4,6
    #pragma unroll
    for (int mi = 0; mi < 4; mi++) {
        #pragma unroll
        for (int ni = 0; ni < 4; ni++) {
            int row = m0 + warp_m * 64 + mi * 16 + qr;
            int col = n0 + warp_n * 32 + ni * 8 + qc;
            #pragma unroll
            for (int h = 0; h < 2; h++) {  // h=0: row, h=1: row+8
                int r = row + h * 8;
                float v0 = acc[mi][ni][h * 2 + 0];
                float v1 = acc[mi][ni][h * 2 + 1];
                if (col + 1 < VOCAB) {
                    float2 o;
                    o.x = v0 + bias[col];
                    o.y = v1 + bias[col + 1];
                    *(float2*)(out + (size_t)r * VOCAB + col) = o;
                } else if (col < VOCAB) {
                    out[(size_t)r * VOCAB + col] = v0 + bias[col];
                }
            }
        }
    }
}

// ---------------------------------------------------------------------------
extern "C" void kernel_launch(void* const* d_in, const int* in_sizes, int n_in,
                              void* d_out, int out_size) {
    const float* hidden  = (const float*)d_in[0];
    const float* dense_w = (const float*)d_in[1];
    const float* dense_b = (const float*)d_in[2];
    const float* ln_w    = (const float*)d_in[3];
    const float* ln_b    = (const float*)d_in[4];
    const float* ent_w   = (const float*)d_in[5];
    const float* ent_b   = (const float*)d_in[6];
    const float* proj_w  = (const float*)d_in[7];
    const float* proj_b  = (const float*)d_in[8];
    float* out = (float*)d_out;

    float* Hptr = nullptr;
    cudaGetSymbolAddress((void**)&Hptr, g_H);

    cudaFuncSetAttribute(proj_kernel, cudaFuncAttributeMaxDynamicSharedMemorySize, PROJ_SMEM);

    // 0) W transpose to fp16 (K-major)
    conv_w_kernel<<<dim3((VOCAB + 31) / 32, QDIM / 32), dim3(32, 8)>>>(proj_w);

    // 1) dense + GELU
    dense_gelu_kernel<<<dim3(HIDDEN / 64, NTOK / 64), dim3(16, 16)>>>(
        hidden, dense_w, dense_b, Hptr, NTOK, HIDDEN, HIDDEN);

    // 2) LN + ent + sigmoid + quantum sim -> probs (fp16)
    token_quantum_kernel<<<NTOK, 256>>>(ln_w, ln_b, ent_w, ent_b);

    // 3) proj via mma.sync fp16 single-term
    proj_kernel<<<dim3(NTOK / BM, VOCAB_PAD / BN), NTHR, PROJ_SMEM>>>(proj_b, out);
}

// round 12
// speedup vs baseline: 6.4784x; 1.1059x over previous
#include <cuda_runtime.h>
#include <cuda_bf16.h>
#include <cuda_fp16.h>
#include <math.h>
#include <stdint.h>

#define HIDDEN 768
#define NTOK   4096
#define QDIM   1024
#define VOCAB  30522
#define VOCAB_PAD 30720
#define NANG   20

// ---------------- device scratch (allocation-free) ----------------
__device__ float  g_H[NTOK * HIDDEN];          // post-GELU dense output
__device__ __half g_A_h[NTOK * QDIM];          // probs (fp16)
__device__ __half g_Wt_h[VOCAB_PAD * QDIM];    // proj_w^T fp16 (K-major)

// ---------------- portable PTX helpers (no sm_103a features) ----------------
static __device__ __forceinline__ uint32_t smem_u32(const void* p) {
    uint32_t a;
    asm("{ .reg .u64 t; cvta.to.shared.u64 t, %1; cvt.u32.u64 %0, t; }" : "=r"(a) : "l"(p));
    return a;
}
static __device__ __forceinline__ void cp_async16(uint32_t dst, const void* src) {
    asm volatile("cp.async.cg.shared.global [%0], [%1], 16;" :: "r"(dst), "l"(src) : "memory");
}
static __device__ __forceinline__ void cp_commit() {
    asm volatile("cp.async.commit_group;" ::: "memory");
}
static __device__ __forceinline__ void cp_wait2() {
    asm volatile("cp.async.wait_group 2;" ::: "memory");
}
static __device__ __forceinline__ void ldsm_x4(uint32_t* r, uint32_t addr) {
    asm volatile("ldmatrix.sync.aligned.m8n8.x4.shared.b16 {%0,%1,%2,%3}, [%4];"
                 : "=r"(r[0]), "=r"(r[1]), "=r"(r[2]), "=r"(r[3]) : "r"(addr));
}
static __device__ __forceinline__ void mma_f16(float* d, const uint32_t* a, const uint32_t* b) {
    asm volatile(
        "mma.sync.aligned.m16n8k16.row.col.f32.f16.f16.f32 "
        "{%0,%1,%2,%3}, {%4,%5,%6,%7}, {%8,%9}, {%0,%1,%2,%3};"
        : "+f"(d[0]), "+f"(d[1]), "+f"(d[2]), "+f"(d[3])
        : "r"(a[0]), "r"(a[1]), "r"(a[2]), "r"(a[3]), "r"(b[0]), "r"(b[1]));
}

// ---------------------------------------------------------------------------
// fp32 tiled GEMM + GELU (dense layer): C = GELU(A@B + bias)
// ---------------------------------------------------------------------------
__global__ void dense_gelu_kernel(const float* __restrict__ A,
                                  const float* __restrict__ B,
                                  const float* __restrict__ bias,
                                  float* __restrict__ C,
                                  int M, int N, int K) {
    constexpr int BK = 16;
    __shared__ __align__(16) float As[BK][64 + 4];
    __shared__ __align__(16) float Bs[BK][64];

    const int tx = threadIdx.x, ty = threadIdx.y;
    const int tid = ty * 16 + tx;
    const int m0 = blockIdx.y * 64;
    const int n0 = blockIdx.x * 64;

    float acc[4][4] = {};

    for (int k0 = 0; k0 < K; k0 += BK) {
        #pragma unroll
        for (int e = 0; e < 4; e++) {
            int lin = e * 256 + tid;
            int c = lin & 15, r = lin >> 4;
            As[c][r] = A[(size_t)(m0 + r) * K + k0 + c];
        }
        #pragma unroll
        for (int e = 0; e < 4; e++) {
            int lin = e * 256 + tid;
            int c = lin & 63, r = lin >> 6;
            Bs[r][c] = B[(size_t)(k0 + r) * N + n0 + c];
        }
        __syncthreads();
        #pragma unroll
        for (int kk = 0; kk < BK; kk++) {
            float4 av = *(const float4*)&As[kk][ty * 4];
            float4 bv = *(const float4*)&Bs[kk][tx * 4];
            float a[4] = {av.x, av.y, av.z, av.w};
            float b[4] = {bv.x, bv.y, bv.z, bv.w};
            #pragma unroll
            for (int i = 0; i < 4; i++)
                #pragma unroll
                for (int j = 0; j < 4; j++)
                    acc[i][j] += a[i] * b[j];
        }
        __syncthreads();
    }
    #pragma unroll
    for (int i = 0; i < 4; i++) {
        int row = m0 + ty * 4 + i;
        #pragma unroll
        for (int j = 0; j < 4; j++) {
            int col = n0 + tx * 4 + j;
            float v = acc[i][j] + bias[col];
            v = 0.5f * v * (1.0f + erff(v * 0.70710678118654752f));
            C[(size_t)row * N + col] = v;
        }
    }
}

// ---------------------------------------------------------------------------
// Per-token LN -> ent -> sigmoid -> quantum sim -> probs (fp16)
// ---------------------------------------------------------------------------
__global__ void token_quantum_kernel(const float* __restrict__ ln_w,
                                     const float* __restrict__ ln_b,
                                     const float* __restrict__ ent_w,
                                     const float* __restrict__ ent_b) {
    const int t = blockIdx.x;
    const int tid = threadIdx.x;
    const int lane = tid & 31;
    const int wrp = tid >> 5;

    __shared__ float hn[HIDDEN];
    __shared__ float red[16];
    __shared__ float ang[NANG];
    __shared__ float sre[QDIM];
    __shared__ float smi[QDIM];

    const float* hrow = g_H + (size_t)t * HIDDEN;

    float lsum = 0.0f;
    for (int k = tid; k < HIDDEN; k += 256) {
        float v = hrow[k];
        hn[k] = v;
        lsum += v;
    }
    #pragma unroll
    for (int o = 16; o; o >>= 1) lsum += __shfl_xor_sync(0xffffffffu, lsum, o);
    if (lane == 0) red[wrp] = lsum;
    __syncthreads();
    float mean = 0.0f;
    #pragma unroll
    for (int w = 0; w < 8; w++) mean += red[w];
    mean *= (1.0f / HIDDEN);

    float lsq = 0.0f;
    for (int k = tid; k < HIDDEN; k += 256) {
        float d = hn[k] - mean;
        lsq += d * d;
    }
    #pragma unroll
    for (int o = 16; o; o >>= 1) lsq += __shfl_xor_sync(0xffffffffu, lsq, o);
    if (lane == 0) red[8 + wrp] = lsq;
    __syncthreads();
    float var = 0.0f;
    #pragma unroll
    for (int w = 0; w < 8; w++) var += red[8 + w];
    var *= (1.0f / HIDDEN);
    float rstd = rsqrtf(var + 1e-12f);

    for (int k = tid; k < HIDDEN; k += 256)
        hn[k] = ln_w[k] * ((hn[k] - mean) * rstd) + ln_b[k];
    __syncthreads();

    for (int j = wrp; j < NANG; j += 8) {
        float acc = 0.0f;
        for (int k = lane; k < HIDDEN; k += 32)
            acc += hn[k] * ent_w[(size_t)k * NANG + j];
        #pragma unroll
        for (int o = 16; o; o >>= 1) acc += __shfl_xor_sync(0xffffffffu, acc, o);
        if (lane == 0) {
            float z = acc + ent_b[j];
            ang[j] = 6.28318530717958647692f / (1.0f + expf(-z));
        }
    }
    __syncthreads();

    for (int i = tid; i < QDIM; i += 256) {
        sre[i] = (i == 0) ? 1.0f : 0.0f;
        smi[i] = 0.0f;
    }
    __syncthreads();

    #pragma unroll 1
    for (int l = 0; l < 2; l++) {
        #pragma unroll 1
        for (int q = 0; q < 10; q++) {
            float th = ang[l * 10 + q] * 0.5f;
            float sth, cth;
            sincosf(th, &sth, &cth);
            int pos = 9 - q;
            int lowmask = (1 << pos) - 1;
            #pragma unroll
            for (int pp = 0; pp < 2; pp++) {
                int p = tid + pp * 256;
                int i0 = ((p & ~lowmask) << 1) | (p & lowmask);
                int i1 = i0 | (1 << pos);
                float a0r = sre[i0], a0i = smi[i0];
                float a1r = sre[i1], a1i = smi[i1];
                sre[i0] = cth * a0r + sth * a1i;
                smi[i0] = cth * a0i - sth * a1r;
                sre[i1] = cth * a1r + sth * a0i;
                smi[i1] = cth * a1i - sth * a0r;
            }
            __syncthreads();
        }
        #pragma unroll 1
        for (int q = 0; q < 10; q++) {
            int tq = (q + 1) % 10;
            int cpos = 9 - q;
            int tpos = 9 - tq;
            int lo = cpos < tpos ? cpos : tpos;
            int hi = cpos > tpos ? cpos : tpos;
            int x = tid;
            x = ((x >> lo) << (lo + 1)) | (x & ((1 << lo) - 1));
            x = ((x >> hi) << (hi + 1)) | (x & ((1 << hi) - 1));
            int i = x | (1 << cpos);
            int j2 = i | (1 << tpos);
            float tr = sre[i]; sre[i] = sre[j2]; sre[j2] = tr;
            float ti = smi[i]; smi[i] = smi[j2]; smi[j2] = ti;
            __syncthreads();
        }
    }

    for (int i = tid; i < QDIM; i += 256) {
        float r = sre[i], im = smi[i];
        g_A_h[(size_t)t * QDIM + i] = __float2half_rn(r * r + im * im);
    }
}

// ---------------------------------------------------------------------------
// W [1024, 30522] fp32 -> Wt_h [30720, 1024] fp16 (transpose)
// ---------------------------------------------------------------------------
__global__ void conv_w_kernel(const float* __restrict__ W) {
    __shared__ float tile[32][33];
    int n0 = blockIdx.x * 32;
    int k0 = blockIdx.y * 32;
    int tx = threadIdx.x, ty = threadIdx.y;
    #pragma unroll
    for (int i = 0; i < 4; i++) {
        int k = k0 + ty + 8 * i;
        int n = n0 + tx;
        tile[ty + 8 * i][tx] = (n < VOCAB) ? W[(size_t)k * VOCAB + n] : 0.0f;
    }
    __syncthreads();
    #pragma unroll
    for (int i = 0; i < 4; i++) {
        int n = n0 + ty + 8 * i;
        int k = k0 + tx;
        g_Wt_h[(size_t)n * QDIM + k] = __float2half_rn(tile[tx][ty + 8 * i]);
    }
}

// ---------------------------------------------------------------------------
// Proj GEMM via mma.sync fp16 (single term): out = A @ B + bias
// BM=128, BN=128, BK=32; 8 warps (2x4), warp tile 64x32; 2 CTAs/SM.
// Two independent CTAs per SM de-phase-lock LDSM vs MMA bursts.
// 4-stage cp.async ring, 3-deep prefetch. 80B row stride -> conflict-free ldsm.
// ---------------------------------------------------------------------------
#define BM 128
#define BN 128
#define BKE 32
#define NCHUNK (QDIM / BKE)
#define NSTAGE 4
#define NTHR 256
#define ROWB 80
#define AHI 0
#define BHI (128 * ROWB)
#define STAGE (128 * ROWB + 128 * ROWB)
#define PROJ_SMEM (NSTAGE * STAGE)

__global__ void __launch_bounds__(NTHR, 2)
proj_kernel(const float* __restrict__ bias, float* __restrict__ out) {
    extern __shared__ char dynsm[];
    const uint32_t smem0 = smem_u32(dynsm);

    const int tid = threadIdx.x;
    const int lane = tid & 31;
    const int wid = tid >> 5;
    const int warp_m = wid & 1;   // 0..1 -> 64 rows each
    const int warp_n = wid >> 1;  // 0..3 -> 32 cols each
    const int m0 = blockIdx.x * BM;
    const int n0 = blockIdx.y * BN;

    const __half* Ahg = g_A_h + (size_t)m0 * QDIM;
    const __half* Bhg = g_Wt_h + (size_t)n0 * QDIM;

    // Issue cp.async loads for chunk c into stage c % NSTAGE.
    auto load_stage = [&](int c) {
        const int k0 = c * BKE;
        const uint32_t sb = smem0 + (c % NSTAGE) * STAGE;
        #pragma unroll
        for (int it = 0; it < 2; it++) {  // A: 128 rows x 4 chunks of 16B
            int idx = it * NTHR + tid;
            int row = idx >> 2, ch = idx & 3;
            size_t go = (size_t)row * QDIM + k0 + ch * 8;
            uint32_t so = row * ROWB + ch * 16;
            cp_async16(sb + AHI + so, Ahg + go);
        }
        #pragma unroll
        for (int it = 0; it < 2; it++) {  // B: 128 rows x 4 chunks of 16B
            int idx = it * NTHR + tid;
            int row = idx >> 2, ch = idx & 3;
            size_t go = (size_t)row * QDIM + k0 + ch * 8;
            uint32_t so = row * ROWB + ch * 16;
            cp_async16(sb + BHI + so, Bhg + go);
        }
        cp_commit();
    };

    float acc[4][4][4];
    #pragma unroll
    for (int i = 0; i < 4; i++)
        #pragma unroll
        for (int j = 0; j < 4; j++)
            #pragma unroll
            for (int e = 0; e < 4; e++) acc[i][j][e] = 0.0f;

    load_stage(0);
    load_stage(1);
    load_stage(2);

    // A ldmatrix lane mapping (x4: 16 rows x 2 k-halves)
    const int arow = warp_m * 64 + (lane & 15);
    const int ach = lane >> 4;
    // B ldmatrix lane mapping (x4: 2 n-groups of 8 rows x 2 k-halves)
    const int bro = warp_n * 32 + (lane & 7) + ((lane >> 4) & 1) * 8;
    const int bkh = (lane >> 3) & 1;

    for (int c = 0; c < NCHUNK; c++) {
        cp_wait2();            // chunk c landed (chunks c+1, c+2 may be pending)
        __syncthreads();       // all warps consumed stage (c-1)%4 -> safe to overwrite
        if (c + 3 < NCHUNK) load_stage(c + 3);

        const uint32_t sb = smem0 + (c % NSTAGE) * STAGE;
        #pragma unroll
        for (int ks = 0; ks < 2; ks++) {
            uint32_t ahi[4][4];
            #pragma unroll
            for (int mi = 0; mi < 4; mi++) {
                uint32_t ao = (arow + mi * 16) * ROWB + (ks * 2 + ach) * 16;
                ldsm_x4(ahi[mi], sb + AHI + ao);
            }
            uint32_t bh[2][4];
            {
                uint32_t bo = bro * ROWB + (ks * 2 + bkh) * 16;
                ldsm_x4(bh[0], sb + BHI + bo);
            }
            #pragma unroll
            for (int nj = 0; nj < 2; nj++) {
                const int cur = nj & 1, nxt = cur ^ 1;
                if (nj < 1) {
                    uint32_t bo = (bro + 16) * ROWB + (ks * 2 + bkh) * 16;
                    ldsm_x4(bh[nxt], sb + BHI + bo);
                }
                #pragma unroll
                for (int mi = 0; mi < 4; mi++)
                    #pragma unroll
                    for (int g = 0; g < 2; g++)
                        mma_f16(acc[mi][2 * nj + g], ahi[mi], &bh[cur][2 * g]);
            }
        }
    }

    // ---- epilogue ----
    const int qr = lane >> 2;        // 0..7
    const int qc = (lane & 3) * 2;   // 0,2,4,6
    #pragma unroll
    for (int mi = 0; mi < 4; mi++) {
        #pragma unroll
        for (int ni = 0; ni < 4; ni++) {
            int row = m0 + warp_m * 64 + mi * 16 + qr;
            int col = n0 + warp_n * 32 + ni * 8 + qc;
            #pragma unroll
            for (int h = 0; h < 2; h++) {  // h=0: row, h=1: row+8
                int r = row + h * 8;
                float v0 = acc[mi][ni][h * 2 + 0];
                float v1 = acc[mi][ni][h * 2 + 1];
                if (col + 1 < VOCAB) {
                    float2 o;
                    o.x = v0 + bias[col];
                    o.y = v1 + bias[col + 1];
                    *(float2*)(out + (size_t)r * VOCAB + col) = o;
                } else if (col < VOCAB) {
                    out[(size_t)r * VOCAB + col] = v0 + bias[col];
                }
            }
        }
    }
}

// ---------------------------------------------------------------------------
extern "C" void kernel_launch(void* const* d_in, const int* in_sizes, int n_in,
                              void* d_out, int out_size) {
    const float* hidden  = (const float*)d_in[0];
    const float* dense_w = (const float*)d_in[1];
    const float* dense_b = (const float*)d_in[2];
    const float* ln_w    = (const float*)d_in[3];
    const float* ln_b    = (const float*)d_in[4];
    const float* ent_w   = (const float*)d_in[5];
    const float* ent_b   = (const float*)d_in[6];
    const float* proj_w  = (const float*)d_in[7];
    const float* proj_b  = (const float*)d_in[8];
    float* out = (float*)d_out;

    float* Hptr = nullptr;
    cudaGetSymbolAddress((void**)&Hptr, g_H);

    cudaFuncSetAttribute(proj_kernel, cudaFuncAttributeMaxDynamicSharedMemorySize, PROJ_SMEM);

    // 0) W transpose to fp16 (K-major)
    conv_w_kernel<<<dim3((VOCAB + 31) / 32, QDIM / 32), dim3(32, 8)>>>(proj_w);

    // 1) dense + GELU
    dense_gelu_kernel<<<dim3(HIDDEN / 64, NTOK / 64), dim3(16, 16)>>>(
        hidden, dense_w, dense_b, Hptr, NTOK, HIDDEN, HIDDEN);

    // 2) LN + ent + sigmoid + quantum sim -> probs (fp16)
    token_quantum_kernel<<<NTOK, 256>>>(ln_w, ln_b, ent_w, ent_b);

    // 3) proj via mma.sync fp16 single-term, 2 CTAs/SM
    proj_kernel<<<dim3(NTOK / BM, VOCAB_PAD / BN), NTHR, PROJ_SMEM>>>(proj_b, out);
}

// round 14
// speedup vs baseline: 7.4879x; 1.1558x over previous
#include <cuda_runtime.h>
#include <cuda_bf16.h>
#include <cuda_fp16.h>
#include <math.h>
#include <stdint.h>

#define HIDDEN 768
#define NTOK   4096
#define QDIM   1024
#define VOCAB  30522
#define VOCAB_PAD 30720
#define NANG   20

// ---------------- device scratch (allocation-free) ----------------
__device__ float  g_H[NTOK * HIDDEN];           // post-GELU dense output (fp32)
__device__ __half g_A_h[NTOK * QDIM];           // probs (fp16)
__device__ __half g_Wt_h[VOCAB_PAD * QDIM];     // proj_w^T fp16 (K-major)
__device__ __half g_Dh_hi[NTOK * HIDDEN];       // hidden fp16 hi
__device__ __half g_Dh_lo[NTOK * HIDDEN];       // hidden fp16 lo
__device__ __half g_Dw_hi[HIDDEN * HIDDEN];     // dense_w^T fp16 hi (K-major)
__device__ __half g_Dw_lo[HIDDEN * HIDDEN];     // dense_w^T fp16 lo
__device__ float  g_entT[NANG * HIDDEN];        // ent_w^T (coalesced reads)

// ---------------- portable PTX helpers (no sm_103a features) ----------------
static __device__ __forceinline__ uint32_t smem_u32(const void* p) {
    uint32_t a;
    asm("{ .reg .u64 t; cvta.to.shared.u64 t, %1; cvt.u32.u64 %0, t; }" : "=r"(a) : "l"(p));
    return a;
}
static __device__ __forceinline__ void cp_async16(uint32_t dst, const void* src) {
    asm volatile("cp.async.cg.shared.global [%0], [%1], 16;" :: "r"(dst), "l"(src) : "memory");
}
static __device__ __forceinline__ void cp_commit() {
    asm volatile("cp.async.commit_group;" ::: "memory");
}
static __device__ __forceinline__ void cp_wait2() {
    asm volatile("cp.async.wait_group 2;" ::: "memory");
}
static __device__ __forceinline__ void ldsm_x4(uint32_t* r, uint32_t addr) {
    asm volatile("ldmatrix.sync.aligned.m8n8.x4.shared.b16 {%0,%1,%2,%3}, [%4];"
                 : "=r"(r[0]), "=r"(r[1]), "=r"(r[2]), "=r"(r[3]) : "r"(addr));
}
static __device__ __forceinline__ void mma_f16(float* d, const uint32_t* a, const uint32_t* b) {
    asm volatile(
        "mma.sync.aligned.m16n8k16.row.col.f32.f16.f16.f32 "
        "{%0,%1,%2,%3}, {%4,%5,%6,%7}, {%8,%9}, {%0,%1,%2,%3};"
        : "+f"(d[0]), "+f"(d[1]), "+f"(d[2]), "+f"(d[3])
        : "r"(a[0]), "r"(a[1]), "r"(a[2]), "r"(a[3]), "r"(b[0]), "r"(b[1]));
}

// ---------------------------------------------------------------------------
// Small conversion kernels
// ---------------------------------------------------------------------------
__global__ void conv_h_kernel(const float* __restrict__ X) {  // hidden -> fp16 hi/lo
    int i = blockIdx.x * 256 + threadIdx.x;
    if (i < NTOK * HIDDEN) {
        float v = X[i];
        __half h = __float2half_rn(v);
        g_Dh_hi[i] = h;
        g_Dh_lo[i] = __float2half_rn(v - __half2float(h));
    }
}
__global__ void conv_dw_kernel(const float* __restrict__ W) { // dense_w [K,N] -> W^T hi/lo
    __shared__ float tile[32][33];
    int n0 = blockIdx.x * 32;
    int k0 = blockIdx.y * 32;
    int tx = threadIdx.x, ty = threadIdx.y;
    #pragma unroll
    for (int i = 0; i < 4; i++)
        tile[ty + 8 * i][tx] = W[(size_t)(k0 + ty + 8 * i) * HIDDEN + n0 + tx];
    __syncthreads();
    #pragma unroll
    for (int i = 0; i < 4; i++) {
        int n = n0 + ty + 8 * i;
        int k = k0 + tx;
        float v = tile[tx][ty + 8 * i];
        __half h = __float2half_rn(v);
        g_Dw_hi[(size_t)n * HIDDEN + k] = h;
        g_Dw_lo[(size_t)n * HIDDEN + k] = __float2half_rn(v - __half2float(h));
    }
}
__global__ void conv_entT_kernel(const float* __restrict__ E) { // ent_w [768,20] -> [20][768]
    int i = blockIdx.x * 256 + threadIdx.x;
    if (i < HIDDEN * NANG) {
        int k = i / NANG, j = i % NANG;
        g_entT[j * HIDDEN + k] = E[i];
    }
}
__global__ void conv_w_kernel(const float* __restrict__ W) {   // proj_w -> W^T fp16
    __shared__ float tile[32][33];
    int n0 = blockIdx.x * 32;
    int k0 = blockIdx.y * 32;
    int tx = threadIdx.x, ty = threadIdx.y;
    #pragma unroll
    for (int i = 0; i < 4; i++) {
        int k = k0 + ty + 8 * i;
        int n = n0 + tx;
        tile[ty + 8 * i][tx] = (n < VOCAB) ? W[(size_t)k * VOCAB + n] : 0.0f;
    }
    __syncthreads();
    #pragma unroll
    for (int i = 0; i < 4; i++) {
        int n = n0 + ty + 8 * i;
        int k = k0 + tx;
        g_Wt_h[(size_t)n * QDIM + k] = __float2half_rn(tile[tx][ty + 8 * i]);
    }
}

// ---------------------------------------------------------------------------
// Dense GEMM via mma.sync fp16 3-term split + GELU: g_H = GELU(X@W + b)
// BM=128, BN=128, BKE=32; 8 warps (2x4), warp tile 64x32; 4-stage ring
// (4 stages REQUIRED for 3-deep prefetch: (c+3)%4 != c%4).
// ---------------------------------------------------------------------------
#define DROWB 80
#define DAHI 0
#define DALO (128 * DROWB)
#define DBHI (2 * 128 * DROWB)
#define DBLO (3 * 128 * DROWB)
#define DSTAGE (4 * 128 * DROWB)
#define DNSTAGE 4
#define DENSE_SMEM (DNSTAGE * DSTAGE)
#define DNCHUNK (HIDDEN / 32)

__global__ void __launch_bounds__(256, 1)
dense_mma_kernel(const float* __restrict__ bias, float* __restrict__ out) {
    extern __shared__ char dynsm[];
    const uint32_t smem0 = smem_u32(dynsm);

    const int tid = threadIdx.x;
    const int lane = tid & 31;
    const int wid = tid >> 5;
    const int warp_m = wid & 1;
    const int warp_n = wid >> 1;
    const int m0 = blockIdx.x * 128;
    const int n0 = blockIdx.y * 128;

    const __half* Ah = g_Dh_hi + (size_t)m0 * HIDDEN;
    const __half* Al = g_Dh_lo + (size_t)m0 * HIDDEN;
    const __half* Bh = g_Dw_hi + (size_t)n0 * HIDDEN;
    const __half* Bl = g_Dw_lo + (size_t)n0 * HIDDEN;

    auto load_stage = [&](int c) {
        const int k0 = c * 32;
        const uint32_t sb = smem0 + (c % DNSTAGE) * DSTAGE;
        #pragma unroll
        for (int it = 0; it < 2; it++) {
            int idx = it * 256 + tid;
            int row = idx >> 2, ch = idx & 3;
            size_t go = (size_t)row * HIDDEN + k0 + ch * 8;
            uint32_t so = row * DROWB + ch * 16;
            cp_async16(sb + DAHI + so, Ah + go);
            cp_async16(sb + DALO + so, Al + go);
            cp_async16(sb + DBHI + so, Bh + go);
            cp_async16(sb + DBLO + so, Bl + go);
        }
        cp_commit();
    };

    float acc[4][4][4];
    #pragma unroll
    for (int i = 0; i < 4; i++)
        #pragma unroll
        for (int j = 0; j < 4; j++)
            #pragma unroll
            for (int e = 0; e < 4; e++) acc[i][j][e] = 0.0f;

    load_stage(0);
    load_stage(1);
    load_stage(2);

    const int arow = warp_m * 64 + (lane & 15);
    const int ach = lane >> 4;
    const int bro = warp_n * 32 + (lane & 7) + ((lane >> 4) & 1) * 8;
    const int bkh = (lane >> 3) & 1;

    for (int c = 0; c < DNCHUNK; c++) {
        cp_wait2();
        __syncthreads();
        if (c + 3 < DNCHUNK) load_stage(c + 3);

        const uint32_t sb = smem0 + (c % DNSTAGE) * DSTAGE;
        #pragma unroll
        for (int ks = 0; ks < 2; ks++) {
            uint32_t ahi[4][4], alo[4][4];
            #pragma unroll
            for (int mi = 0; mi < 4; mi++) {
                uint32_t ao = (arow + mi * 16) * DROWB + (ks * 2 + ach) * 16;
                ldsm_x4(ahi[mi], sb + DAHI + ao);
                ldsm_x4(alo[mi], sb + DALO + ao);
            }
            uint32_t bh[2][4], bl[2][4];
            {
                uint32_t bo = bro * DROWB + (ks * 2 + bkh) * 16;
                ldsm_x4(bh[0], sb + DBHI + bo);
                ldsm_x4(bl[0], sb + DBLO + bo);
            }
            #pragma unroll
            for (int nj = 0; nj < 2; nj++) {
                const int cur = nj & 1, nxt = cur ^ 1;
                if (nj < 1) {
                    uint32_t bo = (bro + 16) * DROWB + (ks * 2 + bkh) * 16;
                    ldsm_x4(bh[nxt], sb + DBHI + bo);
                    ldsm_x4(bl[nxt], sb + DBLO + bo);
                }
                #pragma unroll
                for (int mi = 0; mi < 4; mi++)
                    #pragma unroll
                    for (int g = 0; g < 2; g++) {
                        float* ac = acc[mi][2 * nj + g];
                        mma_f16(ac, ahi[mi], &bh[cur][2 * g]);
                        mma_f16(ac, ahi[mi], &bl[cur][2 * g]);
                        mma_f16(ac, alo[mi], &bh[cur][2 * g]);
                    }
            }
        }
    }

    const int qr = lane >> 2;
    const int qc = (lane & 3) * 2;
    #pragma unroll
    for (int mi = 0; mi < 4; mi++) {
        #pragma unroll
        for (int ni = 0; ni < 4; ni++) {
            int row = m0 + warp_m * 64 + mi * 16 + qr;
            int col = n0 + warp_n * 32 + ni * 8 + qc;
            #pragma unroll
            for (int h = 0; h < 2; h++) {
                int r = row + h * 8;
                float v0 = acc[mi][ni][h * 2 + 0] + bias[col];
                float v1 = acc[mi][ni][h * 2 + 1] + bias[col + 1];
                v0 = 0.5f * v0 * (1.0f + erff(v0 * 0.70710678118654752f));
                v1 = 0.5f * v1 * (1.0f + erff(v1 * 0.70710678118654752f));
                float2 o = {v0, v1};
                *(float2*)(out + (size_t)r * HIDDEN + col) = o;
            }
        }
    }
}

// ---------------------------------------------------------------------------
// Warp-per-token: LN -> ent -> sigmoid -> quantum sim in registers -> probs.
// 32 complex amps/lane; qubit bits 0-4 = register idx, bits 5-9 = lane idx.
// RX: b_x = c*a_x - i*s*a_{x^bit} (symmetric -> shfl_xor works per side).
// CNOT: b_x = a_{x ^ (cbit(x)<<tpos)} -> predicated partner select.
// ---------------------------------------------------------------------------
__global__ void token_quantum_kernel(const float* __restrict__ ln_w,
                                     const float* __restrict__ ln_b,
                                     const float* __restrict__ ent_b) {
    const int lane = threadIdx.x & 31;
    const int wtok = threadIdx.x >> 5;            // 0..7
    const int t = blockIdx.x * 8 + wtok;

    __shared__ float sang[8][NANG];

    // ---- load h row (24 per lane), LN ----
    float hv[24];
    float s1 = 0.0f;
    const float* hrow = g_H + (size_t)t * HIDDEN;
    #pragma unroll
    for (int i = 0; i < 24; i++) { hv[i] = hrow[lane + 32 * i]; s1 += hv[i]; }
    #pragma unroll
    for (int o = 16; o; o >>= 1) s1 += __shfl_xor_sync(0xffffffffu, s1, o);
    float mean = s1 * (1.0f / HIDDEN);
    float s2 = 0.0f;
    #pragma unroll
    for (int i = 0; i < 24; i++) { float d = hv[i] - mean; s2 += d * d; }
    #pragma unroll
    for (int o = 16; o; o >>= 1) s2 += __shfl_xor_sync(0xffffffffu, s2, o);
    float rstd = rsqrtf(s2 * (1.0f / HIDDEN) + 1e-12f);
    #pragma unroll
    for (int i = 0; i < 24; i++)
        hv[i] = ln_w[lane + 32 * i] * ((hv[i] - mean) * rstd) + ln_b[lane + 32 * i];

    // ---- ent projection (coalesced via g_entT) + sigmoid*2pi ----
    #pragma unroll 1
    for (int j = 0; j < NANG; j++) {
        float z = 0.0f;
        const float* ew = g_entT + (size_t)j * HIDDEN;
        #pragma unroll
        for (int i = 0; i < 24; i++) z += hv[i] * ew[lane + 32 * i];
        #pragma unroll
        for (int o = 16; o; o >>= 1) z += __shfl_xor_sync(0xffffffffu, z, o);
        if (lane == 0)
            sang[wtok][j] = 6.28318530717958647692f / (1.0f + expf(-(z + ent_b[j])));
    }
    __syncwarp();

    // ---- state in registers ----
    float re[32], im[32];
    #pragma unroll
    for (int j = 0; j < 32; j++) {
        re[j] = (lane == 0 && j == 0) ? 1.0f : 0.0f;
        im[j] = 0.0f;
    }

    #pragma unroll 1
    for (int l = 0; l < 2; l++) {
        // --- RX gates, qubit q at bit position 9-q ---
        #pragma unroll
        for (int q = 0; q < 10; q++) {
            const int pos = 9 - q;
            float th = sang[wtok][l * 10 + q] * 0.5f;
            float sv, cv;
            sincosf(th, &sv, &cv);
            if (pos >= 5) {
                const int lm = 1 << (pos - 5);
                #pragma unroll
                for (int j = 0; j < 32; j++) {
                    float pr = __shfl_xor_sync(0xffffffffu, re[j], lm);
                    float pi = __shfl_xor_sync(0xffffffffu, im[j], lm);
                    float nr = cv * re[j] + sv * pi;
                    float ni = cv * im[j] - sv * pr;
                    re[j] = nr; im[j] = ni;
                }
            } else {
                const int bit = 1 << pos;
                #pragma unroll
                for (int j = 0; j < 32; j++) {
                    if ((j & bit) == 0) {
                        const int j1 = j | bit;
                        float a0r = re[j], a0i = im[j], a1r = re[j1], a1i = im[j1];
                        re[j]  = cv * a0r + sv * a1i;
                        im[j]  = cv * a0i - sv * a1r;
                        re[j1] = cv * a1r + sv * a0i;
                        im[j1] = cv * a1i - sv * a0r;
                    }
                }
            }
        }
        // --- CNOT ring: control q (cpos=9-q), target (q+1)%10 (tpos) ---
        #pragma unroll
        for (int q = 0; q < 10; q++) {
            const int tq = (q + 1) % 10;
            const int cpos = 9 - q;
            const int tpos = 9 - tq;
            if (tpos >= 5) {
                const int lm = 1 << (tpos - 5);
                #pragma unroll
                for (int j = 0; j < 32; j++) {
                    float pr = __shfl_xor_sync(0xffffffffu, re[j], lm);
                    float pi = __shfl_xor_sync(0xffffffffu, im[j], lm);
                    int cb = (cpos >= 5) ? ((lane >> (cpos - 5)) & 1) : ((j >> cpos) & 1);
                    if (cb) { re[j] = pr; im[j] = pi; }
                }
            } else {
                const int tb = 1 << tpos;
                if (cpos >= 5) {
                    const int cb = (lane >> (cpos - 5)) & 1;
                    #pragma unroll
                    for (int j = 0; j < 32; j++) {
                        if ((j & tb) == 0) {
                            const int j1 = j | tb;
                            float tr = re[j], ti = im[j];
                            if (cb) {
                                re[j] = re[j1]; im[j] = im[j1];
                                re[j1] = tr;    im[j1] = ti;
                            }
                        }
                    }
                } else {
                    #pragma unroll
                    for (int j = 0; j < 32; j++) {
                        if (((j >> cpos) & 1) && ((j & tb) == 0)) {
                            const int j1 = j | tb;
                            float tr = re[j]; re[j] = re[j1]; re[j1] = tr;
                            float ti = im[j]; im[j] = im[j1]; im[j1] = ti;
                        }
                    }
                }
            }
        }
    }

    // ---- probs (fp16, coalesced 64B per lane) ----
    __half2* outp = (__half2*)(g_A_h + (size_t)t * QDIM + lane * 32);
    #pragma unroll
    for (int j = 0; j < 32; j += 2) {
        float p0 = re[j] * re[j] + im[j] * im[j];
        float p1 = re[j + 1] * re[j + 1] + im[j + 1] * im[j + 1];
        outp[j >> 1] = __floats2half2_rn(p0, p1);
    }
}

// ---------------------------------------------------------------------------
// Proj GEMM via mma.sync fp16 (single term): out = A @ B + bias
// BM=128, BN=128, BKE=32; 8 warps, warp tile 64x32; 2 CTAs/SM; 4-stage ring.
// ---------------------------------------------------------------------------
#define BM 128
#define BN 128
#define BKE 32
#define NCHUNK (QDIM / BKE)
#define NSTAGE 4
#define NTHR 256
#define ROWB 80
#define AHI 0
#define BHI (128 * ROWB)
#define STAGE (128 * ROWB + 128 * ROWB)
#define PROJ_SMEM (NSTAGE * STAGE)

__global__ void __launch_bounds__(NTHR, 2)
proj_kernel(const float* __restrict__ bias, float* __restrict__ out) {
    extern __shared__ char dynsm[];
    const uint32_t smem0 = smem_u32(dynsm);

    const int tid = threadIdx.x;
    const int lane = tid & 31;
    const int wid = tid >> 5;
    const int warp_m = wid & 1;
    const int warp_n = wid >> 1;
    const int m0 = blockIdx.x * BM;
    const int n0 = blockIdx.y * BN;

    const __half* Ahg = g_A_h + (size_t)m0 * QDIM;
    const __half* Bhg = g_Wt_h + (size_t)n0 * QDIM;

    auto load_stage = [&](int c) {
        const int k0 = c * BKE;
        const uint32_t sb = smem0 + (c % NSTAGE) * STAGE;
        #pragma unroll
        for (int it = 0; it < 2; it++) {
            int idx = it * NTHR + tid;
            int row = idx >> 2, ch = idx & 3;
            size_t go = (size_t)row * QDIM + k0 + ch * 8;
            uint32_t so = row * ROWB + ch * 16;
            cp_async16(sb + AHI + so, Ahg + go);
        }
        #pragma unroll
        for (int it = 0; it < 2; it++) {
            int idx = it * NTHR + tid;
            int row = idx >> 2, ch = idx & 3;
            size_t go = (size_t)row * QDIM + k0 + ch * 8;
            uint32_t so = row * ROWB + ch * 16;
            cp_async16(sb + BHI + so, Bhg + go);
        }
        cp_commit();
    };

    float acc[4][4][4];
    #pragma unroll
    for (int i = 0; i < 4; i++)
        #pragma unroll
        for (int j = 0; j < 4; j++)
            #pragma unroll
            for (int e = 0; e < 4; e++) acc[i][j][e] = 0.0f;

    load_stage(0);
    load_stage(1);
    load_stage(2);

    const int arow = warp_m * 64 + (lane & 15);
    const int ach = lane >> 4;
    const int bro = warp_n * 32 + (lane & 7) + ((lane >> 4) & 1) * 8;
    const int bkh = (lane >> 3) & 1;

    for (int c = 0; c < NCHUNK; c++) {
        cp_wait2();
        __syncthreads();
        if (c + 3 < NCHUNK) load_stage(c + 3);

        const uint32_t sb = smem0 + (c % NSTAGE) * STAGE;
        #pragma unroll
        for (int ks = 0; ks < 2; ks++) {
            uint32_t ahi[4][4];
            #pragma unroll
            for (int mi = 0; mi < 4; mi++) {
                uint32_t ao = (arow + mi * 16) * ROWB + (ks * 2 + ach) * 16;
                ldsm_x4(ahi[mi], sb + AHI + ao);
            }
            uint32_t bh[2][4];
            {
                uint32_t bo = bro * ROWB + (ks * 2 + bkh) * 16;
                ldsm_x4(bh[0], sb + BHI + bo);
            }
            #pragma unroll
            for (int nj = 0; nj < 2; nj++) {
                const int cur = nj & 1, nxt = cur ^ 1;
                if (nj < 1) {
                    uint32_t bo = (bro + 16) * ROWB + (ks * 2 + bkh) * 16;
                    ldsm_x4(bh[nxt], sb + BHI + bo);
                }
                #pragma unroll
                for (int mi = 0; mi < 4; mi++)
                    #pragma unroll
                    for (int g = 0; g < 2; g++)
                        mma_f16(acc[mi][2 * nj + g], ahi[mi], &bh[cur][2 * g]);
            }
        }
    }

    const int qr = lane >> 2;
    const int qc = (lane & 3) * 2;
    #pragma unroll
    for (int mi = 0; mi < 4; mi++) {
        #pragma unroll
        for (int ni = 0; ni < 4; ni++) {
            int row = m0 + warp_m * 64 + mi * 16 + qr;
            int col = n0 + warp_n * 32 + ni * 8 + qc;
            #pragma unroll
            for (int h = 0; h < 2; h++) {
                int r = row + h * 8;
                float v0 = acc[mi][ni][h * 2 + 0];
                float v1 = acc[mi][ni][h * 2 + 1];
                if (col + 1 < VOCAB) {
                    float2 o;
                    o.x = v0 + bias[col];
                    o.y = v1 + bias[col + 1];
                    *(float2*)(out + (size_t)r * VOCAB + col) = o;
                } else if (col < VOCAB) {
                    out[(size_t)r * VOCAB + col] = v0 + bias[col];
                }
            }
        }
    }
}

// ---------------------------------------------------------------------------
extern "C" void kernel_launch(void* const* d_in, const int* in_sizes, int n_in,
                              void* d_out, int out_size) {
    const float* hidden  = (const float*)d_in[0];
    const float* dense_w = (const float*)d_in[1];
    const float* dense_b = (const float*)d_in[2];
    const float* ln_w    = (const float*)d_in[3];
    const float* ln_b    = (const float*)d_in[4];
    const float* ent_w   = (const float*)d_in[5];
    const float* ent_b   = (const float*)d_in[6];
    const float* proj_w  = (const float*)d_in[7];
    const float* proj_b  = (const float*)d_in[8];
    float* out = (float*)d_out;

    float* Hptr = nullptr;
    cudaGetSymbolAddress((void**)&Hptr, g_H);

    cudaFuncSetAttribute(proj_kernel, cudaFuncAttributeMaxDynamicSharedMemorySize, PROJ_SMEM);
    cudaFuncSetAttribute(dense_mma_kernel, cudaFuncAttributeMaxDynamicSharedMemorySize, DENSE_SMEM);

    // 0) conversions (independent)
    conv_w_kernel<<<dim3((VOCAB + 31) / 32, QDIM / 32), dim3(32, 8)>>>(proj_w);
    conv_h_kernel<<<(NTOK * HIDDEN + 255) / 256, 256>>>(hidden);
    conv_dw_kernel<<<dim3(HIDDEN / 32, HIDDEN / 32), dim3(32, 8)>>>(dense_w);
    conv_entT_kernel<<<(HIDDEN * NANG + 255) / 256, 256>>>(ent_w);

    // 1) dense + GELU via fp16 3-term HMMA
    dense_mma_kernel<<<dim3(NTOK / 128, HIDDEN / 128), 256, DENSE_SMEM>>>(dense_b, Hptr);

    // 2) warp-per-token LN + ent + quantum sim -> probs (fp16)
    token_quantum_kernel<<<NTOK / 8, 256>>>(ln_w, ln_b, ent_b);

    // 3) proj via mma.sync fp16 single-term, 2 CTAs/SM
    proj_kernel<<<dim3(NTOK / BM, VOCAB_PAD / BN), NTHR, PROJ_SMEM>>>(proj_b, out);
}

// round 15
// speedup vs baseline: 9.5423x; 1.2744x over previous
#include <cuda_runtime.h>
#include <cuda_bf16.h>
#include <cuda_fp16.h>
#include <math.h>
#include <stdint.h>

#define HIDDEN 768
#define NTOK   4096
#define QDIM   1024
#define VOCAB  30522
#define VOCAB_PAD 30720
#define NANG   20

// ---------------- device scratch (allocation-free) ----------------
__device__ float  g_H[NTOK * HIDDEN];           // post-GELU dense output (fp32)
__device__ __half g_A_h[NTOK * QDIM];           // probs (fp16)
__device__ __half g_Wt_h[VOCAB_PAD * QDIM];     // proj_w^T fp16 (K-major)
__device__ __half g_Dh_hi[NTOK * HIDDEN];       // hidden fp16 hi
__device__ __half g_Dh_lo[NTOK * HIDDEN];       // hidden fp16 lo
__device__ __half g_Dw_hi[HIDDEN * HIDDEN];     // dense_w^T fp16 hi (K-major)
__device__ __half g_Dw_lo[HIDDEN * HIDDEN];     // dense_w^T fp16 lo
__device__ float  g_entT[NANG * HIDDEN];        // ent_w^T (coalesced reads)

// ---------------- portable PTX helpers (no sm_103a features) ----------------
static __device__ __forceinline__ uint32_t smem_u32(const void* p) {
    uint32_t a;
    asm("{ .reg .u64 t; cvta.to.shared.u64 t, %1; cvt.u32.u64 %0, t; }" : "=r"(a) : "l"(p));
    return a;
}
static __device__ __forceinline__ void cp_async16(uint32_t dst, const void* src) {
    asm volatile("cp.async.cg.shared.global [%0], [%1], 16;" :: "r"(dst), "l"(src) : "memory");
}
static __device__ __forceinline__ void cp_commit() {
    asm volatile("cp.async.commit_group;" ::: "memory");
}
static __device__ __forceinline__ void cp_wait1() {
    asm volatile("cp.async.wait_group 1;" ::: "memory");
}
static __device__ __forceinline__ void cp_wait2() {
    asm volatile("cp.async.wait_group 2;" ::: "memory");
}
static __device__ __forceinline__ void ldsm_x4(uint32_t* r, uint32_t addr) {
    asm volatile("ldmatrix.sync.aligned.m8n8.x4.shared.b16 {%0,%1,%2,%3}, [%4];"
                 : "=r"(r[0]), "=r"(r[1]), "=r"(r[2]), "=r"(r[3]) : "r"(addr));
}
static __device__ __forceinline__ void mma_f16(float* d, const uint32_t* a, const uint32_t* b) {
    asm volatile(
        "mma.sync.aligned.m16n8k16.row.col.f32.f16.f16.f32 "
        "{%0,%1,%2,%3}, {%4,%5,%6,%7}, {%8,%9}, {%0,%1,%2,%3};"
        : "+f"(d[0]), "+f"(d[1]), "+f"(d[2]), "+f"(d[3])
        : "r"(a[0]), "r"(a[1]), "r"(a[2]), "r"(a[3]), "r"(b[0]), "r"(b[1]));
}
// 128B-row XOR swizzle: 16B-column c at row r maps to c ^ (r & 7)
static __device__ __forceinline__ uint32_t swz(uint32_t row, uint32_t c16) {
    return row * 128u + ((c16 ^ (row & 7u)) * 16u);
}

// ---------------------------------------------------------------------------
// Small conversion kernels
// ---------------------------------------------------------------------------
__global__ void conv_h_kernel(const float* __restrict__ X) {  // hidden -> fp16 hi/lo
    int i = blockIdx.x * 256 + threadIdx.x;
    if (i < NTOK * HIDDEN) {
        float v = X[i];
        __half h = __float2half_rn(v);
        g_Dh_hi[i] = h;
        g_Dh_lo[i] = __float2half_rn(v - __half2float(h));
    }
}
__global__ void conv_dw_kernel(const float* __restrict__ W) { // dense_w [K,N] -> W^T hi/lo
    __shared__ float tile[32][33];
    int n0 = blockIdx.x * 32;
    int k0 = blockIdx.y * 32;
    int tx = threadIdx.x, ty = threadIdx.y;
    #pragma unroll
    for (int i = 0; i < 4; i++)
        tile[ty + 8 * i][tx] = W[(size_t)(k0 + ty + 8 * i) * HIDDEN + n0 + tx];
    __syncthreads();
    #pragma unroll
    for (int i = 0; i < 4; i++) {
        int n = n0 + ty + 8 * i;
        int k = k0 + tx;
        float v = tile[tx][ty + 8 * i];
        __half h = __float2half_rn(v);
        g_Dw_hi[(size_t)n * HIDDEN + k] = h;
        g_Dw_lo[(size_t)n * HIDDEN + k] = __float2half_rn(v - __half2float(h));
    }
}
__global__ void conv_entT_kernel(const float* __restrict__ E) { // ent_w [768,20] -> [20][768]
    int i = blockIdx.x * 256 + threadIdx.x;
    if (i < HIDDEN * NANG) {
        int k = i / NANG, j = i % NANG;
        g_entT[j * HIDDEN + k] = E[i];
    }
}
__global__ void conv_w_kernel(const float* __restrict__ W) {   // proj_w -> W^T fp16
    __shared__ float tile[32][33];
    int n0 = blockIdx.x * 32;
    int k0 = blockIdx.y * 32;
    int tx = threadIdx.x, ty = threadIdx.y;
    #pragma unroll
    for (int i = 0; i < 4; i++) {
        int k = k0 + ty + 8 * i;
        int n = n0 + tx;
        tile[ty + 8 * i][tx] = (n < VOCAB) ? W[(size_t)k * VOCAB + n] : 0.0f;
    }
    __syncthreads();
    #pragma unroll
    for (int i = 0; i < 4; i++) {
        int n = n0 + ty + 8 * i;
        int k = k0 + tx;
        g_Wt_h[(size_t)n * QDIM + k] = __float2half_rn(tile[tx][ty + 8 * i]);
    }
}

// ---------------------------------------------------------------------------
// Dense GEMM via mma.sync fp16 3-term split + GELU: g_H = GELU(X@W + b)
// BM=128, BN=128, BKE=32; 8 warps (2x4), warp tile 64x32; 4-stage ring.
// ---------------------------------------------------------------------------
#define DROWB 80
#define DAHI 0
#define DALO (128 * DROWB)
#define DBHI (2 * 128 * DROWB)
#define DBLO (3 * 128 * DROWB)
#define DSTAGE (4 * 128 * DROWB)
#define DNSTAGE 4
#define DENSE_SMEM (DNSTAGE * DSTAGE)
#define DNCHUNK (HIDDEN / 32)

__global__ void __launch_bounds__(256, 1)
dense_mma_kernel(const float* __restrict__ bias, float* __restrict__ out) {
    extern __shared__ char dynsm[];
    const uint32_t smem0 = smem_u32(dynsm);

    const int tid = threadIdx.x;
    const int lane = tid & 31;
    const int wid = tid >> 5;
    const int warp_m = wid & 1;
    const int warp_n = wid >> 1;
    const int m0 = blockIdx.x * 128;
    const int n0 = blockIdx.y * 128;

    const __half* Ah = g_Dh_hi + (size_t)m0 * HIDDEN;
    const __half* Al = g_Dh_lo + (size_t)m0 * HIDDEN;
    const __half* Bh = g_Dw_hi + (size_t)n0 * HIDDEN;
    const __half* Bl = g_Dw_lo + (size_t)n0 * HIDDEN;

    auto load_stage = [&](int c) {
        const int k0 = c * 32;
        const uint32_t sb = smem0 + (c % DNSTAGE) * DSTAGE;
        #pragma unroll
        for (int it = 0; it < 2; it++) {
            int idx = it * 256 + tid;
            int row = idx >> 2, ch = idx & 3;
            size_t go = (size_t)row * HIDDEN + k0 + ch * 8;
            uint32_t so = row * DROWB + ch * 16;
            cp_async16(sb + DAHI + so, Ah + go);
            cp_async16(sb + DALO + so, Al + go);
            cp_async16(sb + DBHI + so, Bh + go);
            cp_async16(sb + DBLO + so, Bl + go);
        }
        cp_commit();
    };

    float acc[4][4][4];
    #pragma unroll
    for (int i = 0; i < 4; i++)
        #pragma unroll
        for (int j = 0; j < 4; j++)
            #pragma unroll
            for (int e = 0; e < 4; e++) acc[i][j][e] = 0.0f;

    load_stage(0);
    load_stage(1);
    load_stage(2);

    const int arow = warp_m * 64 + (lane & 15);
    const int ach = lane >> 4;
    const int bro = warp_n * 32 + (lane & 7) + ((lane >> 4) & 1) * 8;
    const int bkh = (lane >> 3) & 1;

    for (int c = 0; c < DNCHUNK; c++) {
        cp_wait2();
        __syncthreads();
        if (c + 3 < DNCHUNK) load_stage(c + 3);

        const uint32_t sb = smem0 + (c % DNSTAGE) * DSTAGE;
        #pragma unroll
        for (int ks = 0; ks < 2; ks++) {
            uint32_t ahi[4][4], alo[4][4];
            #pragma unroll
            for (int mi = 0; mi < 4; mi++) {
                uint32_t ao = (arow + mi * 16) * DROWB + (ks * 2 + ach) * 16;
                ldsm_x4(ahi[mi], sb + DAHI + ao);
                ldsm_x4(alo[mi], sb + DALO + ao);
            }
            uint32_t bh[2][4], bl[2][4];
            {
                uint32_t bo = bro * DROWB + (ks * 2 + bkh) * 16;
                ldsm_x4(bh[0], sb + DBHI + bo);
                ldsm_x4(bl[0], sb + DBLO + bo);
            }
            #pragma unroll
            for (int nj = 0; nj < 2; nj++) {
                const int cur = nj & 1, nxt = cur ^ 1;
                if (nj < 1) {
                    uint32_t bo = (bro + 16) * DROWB + (ks * 2 + bkh) * 16;
                    ldsm_x4(bh[nxt], sb + DBHI + bo);
                    ldsm_x4(bl[nxt], sb + DBLO + bo);
                }
                #pragma unroll
                for (int mi = 0; mi < 4; mi++)
                    #pragma unroll
                    for (int g = 0; g < 2; g++) {
                        float* ac = acc[mi][2 * nj + g];
                        mma_f16(ac, ahi[mi], &bh[cur][2 * g]);
                        mma_f16(ac, ahi[mi], &bl[cur][2 * g]);
                        mma_f16(ac, alo[mi], &bh[cur][2 * g]);
                    }
            }
        }
    }

    const int qr = lane >> 2;
    const int qc = (lane & 3) * 2;
    #pragma unroll
    for (int mi = 0; mi < 4; mi++) {
        #pragma unroll
        for (int ni = 0; ni < 4; ni++) {
            int row = m0 + warp_m * 64 + mi * 16 + qr;
            int col = n0 + warp_n * 32 + ni * 8 + qc;
            #pragma unroll
            for (int h = 0; h < 2; h++) {
                int r = row + h * 8;
                float v0 = acc[mi][ni][h * 2 + 0] + bias[col];
                float v1 = acc[mi][ni][h * 2 + 1] + bias[col + 1];
                v0 = 0.5f * v0 * (1.0f + erff(v0 * 0.70710678118654752f));
                v1 = 0.5f * v1 * (1.0f + erff(v1 * 0.70710678118654752f));
                float2 o = {v0, v1};
                *(float2*)(out + (size_t)r * HIDDEN + col) = o;
            }
        }
    }
}

// ---------------------------------------------------------------------------
// Warp-per-token quantum kernel (unchanged from R14, passing)
// ---------------------------------------------------------------------------
__global__ void token_quantum_kernel(const float* __restrict__ ln_w,
                                     const float* __restrict__ ln_b,
                                     const float* __restrict__ ent_b) {
    const int lane = threadIdx.x & 31;
    const int wtok = threadIdx.x >> 5;
    const int t = blockIdx.x * 8 + wtok;

    __shared__ float sang[8][NANG];

    float hv[24];
    float s1 = 0.0f;
    const float* hrow = g_H + (size_t)t * HIDDEN;
    #pragma unroll
    for (int i = 0; i < 24; i++) { hv[i] = hrow[lane + 32 * i]; s1 += hv[i]; }
    #pragma unroll
    for (int o = 16; o; o >>= 1) s1 += __shfl_xor_sync(0xffffffffu, s1, o);
    float mean = s1 * (1.0f / HIDDEN);
    float s2 = 0.0f;
    #pragma unroll
    for (int i = 0; i < 24; i++) { float d = hv[i] - mean; s2 += d * d; }
    #pragma unroll
    for (int o = 16; o; o >>= 1) s2 += __shfl_xor_sync(0xffffffffu, s2, o);
    float rstd = rsqrtf(s2 * (1.0f / HIDDEN) + 1e-12f);
    #pragma unroll
    for (int i = 0; i < 24; i++)
        hv[i] = ln_w[lane + 32 * i] * ((hv[i] - mean) * rstd) + ln_b[lane + 32 * i];

    #pragma unroll 1
    for (int j = 0; j < NANG; j++) {
        float z = 0.0f;
        const float* ew = g_entT + (size_t)j * HIDDEN;
        #pragma unroll
        for (int i = 0; i < 24; i++) z += hv[i] * ew[lane + 32 * i];
        #pragma unroll
        for (int o = 16; o; o >>= 1) z += __shfl_xor_sync(0xffffffffu, z, o);
        if (lane == 0)
            sang[wtok][j] = 6.28318530717958647692f / (1.0f + expf(-(z + ent_b[j])));
    }
    __syncwarp();

    float re[32], im[32];
    #pragma unroll
    for (int j = 0; j < 32; j++) {
        re[j] = (lane == 0 && j == 0) ? 1.0f : 0.0f;
        im[j] = 0.0f;
    }

    #pragma unroll 1
    for (int l = 0; l < 2; l++) {
        #pragma unroll
        for (int q = 0; q < 10; q++) {
            const int pos = 9 - q;
            float th = sang[wtok][l * 10 + q] * 0.5f;
            float sv, cv;
            sincosf(th, &sv, &cv);
            if (pos >= 5) {
                const int lm = 1 << (pos - 5);
                #pragma unroll
                for (int j = 0; j < 32; j++) {
                    float pr = __shfl_xor_sync(0xffffffffu, re[j], lm);
                    float pi = __shfl_xor_sync(0xffffffffu, im[j], lm);
                    float nr = cv * re[j] + sv * pi;
                    float ni = cv * im[j] - sv * pr;
                    re[j] = nr; im[j] = ni;
                }
            } else {
                const int bit = 1 << pos;
                #pragma unroll
                for (int j = 0; j < 32; j++) {
                    if ((j & bit) == 0) {
                        const int j1 = j | bit;
                        float a0r = re[j], a0i = im[j], a1r = re[j1], a1i = im[j1];
                        re[j]  = cv * a0r + sv * a1i;
                        im[j]  = cv * a0i - sv * a1r;
                        re[j1] = cv * a1r + sv * a0i;
                        im[j1] = cv * a1i - sv * a0r;
                    }
                }
            }
        }
        #pragma unroll
        for (int q = 0; q < 10; q++) {
            const int tq = (q + 1) % 10;
            const int cpos = 9 - q;
            const int tpos = 9 - tq;
            if (tpos >= 5) {
                const int lm = 1 << (tpos - 5);
                #pragma unroll
                for (int j = 0; j < 32; j++) {
                    float pr = __shfl_xor_sync(0xffffffffu, re[j], lm);
                    float pi = __shfl_xor_sync(0xffffffffu, im[j], lm);
                    int cb = (cpos >= 5) ? ((lane >> (cpos - 5)) & 1) : ((j >> cpos) & 1);
                    if (cb) { re[j] = pr; im[j] = pi; }
                }
            } else {
                const int tb = 1 << tpos;
                if (cpos >= 5) {
                    const int cb = (lane >> (cpos - 5)) & 1;
                    #pragma unroll
                    for (int j = 0; j < 32; j++) {
                        if ((j & tb) == 0) {
                            const int j1 = j | tb;
                            float tr = re[j], ti = im[j];
                            if (cb) {
                                re[j] = re[j1]; im[j] = im[j1];
                                re[j1] = tr;    im[j1] = ti;
                            }
                        }
                    }
                } else {
                    #pragma unroll
                    for (int j = 0; j < 32; j++) {
                        if (((j >> cpos) & 1) && ((j & tb) == 0)) {
                            const int j1 = j | tb;
                            float tr = re[j]; re[j] = re[j1]; re[j1] = tr;
                            float ti = im[j]; im[j] = im[j1]; im[j1] = ti;
                        }
                    }
                }
            }
        }
    }

    __half2* outp = (__half2*)(g_A_h + (size_t)t * QDIM + lane * 32);
    #pragma unroll
    for (int j = 0; j < 32; j += 2) {
        float p0 = re[j] * re[j] + im[j] * im[j];
        float p1 = re[j + 1] * re[j + 1] + im[j + 1] * im[j + 1];
        outp[j >> 1] = __floats2half2_rn(p0, p1);
    }
}

// ---------------------------------------------------------------------------
// Proj GEMM via mma.sync fp16: out = A @ B + bias
// BM=128, BN=128, BKE=64 (16 chunks, half the barriers); 8 warps, warp tile
// 64x32; 2 CTAs/SM; 3-stage ring (32KB/stage), 128B swizzled rows.
// Loader-warp specialization: warps 0-3 issue cp.async -> systematic stagger
// between warp halves each chunk (de-phases LDSM vs MMA bursts).
// ---------------------------------------------------------------------------
#define BM 128
#define BN 128
#define BKE 64
#define NCHUNK (QDIM / BKE)
#define NSTAGE 3
#define NTHR 256
#define AHI 0
#define BHI 16384
#define STAGE 32768
#define PROJ_SMEM (NSTAGE * STAGE)

__global__ void __launch_bounds__(NTHR, 2)
proj_kernel(const float* __restrict__ bias, float* __restrict__ out) {
    extern __shared__ char dynsm[];
    const uint32_t smem0 = smem_u32(dynsm);

    const int tid = threadIdx.x;
    const int lane = tid & 31;
    const int wid = tid >> 5;
    const int warp_m = wid & 1;
    const int warp_n = wid >> 1;
    const int m0 = blockIdx.x * BM;
    const int n0 = blockIdx.y * BN;

    const __half* Ahg = g_A_h + (size_t)m0 * QDIM;
    const __half* Bhg = g_Wt_h + (size_t)n0 * QDIM;

    // Loader warps (0-3, tid<128) fill stage c%3 for chunk c: 128 rows x 8
    // 16B-chunks each for A and B, swizzled.
    auto load_stage = [&](int c) {
        const int k0 = c * BKE;
        const uint32_t sb = smem0 + (c % NSTAGE) * STAGE;
        #pragma unroll
        for (int it = 0; it < 8; it++) {
            int idx = it * 128 + tid;          // tid < 128
            int row = idx >> 3, ch = idx & 7;
            size_t go = (size_t)row * QDIM + k0 + ch * 8;
            uint32_t so = swz(row, ch);
            cp_async16(sb + AHI + so, Ahg + go);
            cp_async16(sb + BHI + so, Bhg + go);
        }
        cp_commit();
    };

    float acc[4][4][4];
    #pragma unroll
    for (int i = 0; i < 4; i++)
        #pragma unroll
        for (int j = 0; j < 4; j++)
            #pragma unroll
            for (int e = 0; e < 4; e++) acc[i][j][e] = 0.0f;

    if (tid < 128) {
        load_stage(0);
        load_stage(1);
    }

    const int arow = warp_m * 64 + (lane & 15);
    const int ach = lane >> 4;
    const int bro = warp_n * 32 + (lane & 7) + ((lane >> 4) & 1) * 8;
    const int bkh = (lane >> 3) & 1;

    for (int c = 0; c < NCHUNK; c++) {
        cp_wait1();            // loaders: chunk c landed; others: no-op
        __syncthreads();       // visibility + stage (c-1)%3 free for overwrite
        if (c + 2 < NCHUNK && tid < 128) load_stage(c + 2);

        const uint32_t sb = smem0 + (c % NSTAGE) * STAGE;
        #pragma unroll
        for (int ks = 0; ks < 4; ks++) {
            uint32_t ahi[4][4];
            #pragma unroll
            for (int mi = 0; mi < 4; mi++)
                ldsm_x4(ahi[mi], sb + AHI + swz(arow + mi * 16, ks * 2 + ach));
            uint32_t bh[2][4];
            ldsm_x4(bh[0], sb + BHI + swz(bro, ks * 2 + bkh));
            #pragma unroll
            for (int nj = 0; nj < 2; nj++) {
                const int cur = nj & 1, nxt = cur ^ 1;
                if (nj < 1)
                    ldsm_x4(bh[nxt], sb + BHI + swz(bro + 16, ks * 2 + bkh));
                #pragma unroll
                for (int mi = 0; mi < 4; mi++)
                    #pragma unroll
                    for (int g = 0; g < 2; g++)
                        mma_f16(acc[mi][2 * nj + g], ahi[mi], &bh[cur][2 * g]);
            }
        }
    }

    const int qr = lane >> 2;
    const int qc = (lane & 3) * 2;
    #pragma unroll
    for (int mi = 0; mi < 4; mi++) {
        #pragma unroll
        for (int ni = 0; ni < 4; ni++) {
            int row = m0 + warp_m * 64 + mi * 16 + qr;
            int col = n0 + warp_n * 32 + ni * 8 + qc;
            #pragma unroll
            for (int h = 0; h < 2; h++) {
                int r = row + h * 8;
                float v0 = acc[mi][ni][h * 2 + 0];
                float v1 = acc[mi][ni][h * 2 + 1];
                if (col + 1 < VOCAB) {
                    float2 o;
                    o.x = v0 + bias[col];
                    o.y = v1 + bias[col + 1];
                    *(float2*)(out + (size_t)r * VOCAB + col) = o;
                } else if (col < VOCAB) {
                    out[(size_t)r * VOCAB + col] = v0 + bias[col];
                }
            }
        }
    }
}

// ---------------------------------------------------------------------------
extern "C" void kernel_launch(void* const* d_in, const int* in_sizes, int n_in,
                              void* d_out, int out_size) {
    const float* hidden  = (const float*)d_in[0];
    const float* dense_w = (const float*)d_in[1];
    const float* dense_b = (const float*)d_in[2];
    const float* ln_w    = (const float*)d_in[3];
    const float* ln_b    = (const float*)d_in[4];
    const float* ent_w   = (const float*)d_in[5];
    const float* ent_b   = (const float*)d_in[6];
    const float* proj_w  = (const float*)d_in[7];
    const float* proj_b  = (const float*)d_in[8];
    float* out = (float*)d_out;

    float* Hptr = nullptr;
    cudaGetSymbolAddress((void**)&Hptr, g_H);

    cudaFuncSetAttribute(proj_kernel, cudaFuncAttributeMaxDynamicSharedMemorySize, PROJ_SMEM);
    cudaFuncSetAttribute(dense_mma_kernel, cudaFuncAttributeMaxDynamicSharedMemorySize, DENSE_SMEM);

    // 0) conversions (independent)
    conv_w_kernel<<<dim3((VOCAB + 31) / 32, QDIM / 32), dim3(32, 8)>>>(proj_w);
    conv_h_kernel<<<(NTOK * HIDDEN + 255) / 256, 256>>>(hidden);
    conv_dw_kernel<<<dim3(HIDDEN / 32, HIDDEN / 32), dim3(32, 8)>>>(dense_w);
    conv_entT_kernel<<<(HIDDEN * NANG + 255) / 256, 256>>>(ent_w);

    // 1) dense + GELU via fp16 3-term HMMA
    dense_mma_kernel<<<dim3(NTOK / 128, HIDDEN / 128), 256, DENSE_SMEM>>>(dense_b, Hptr);

    // 2) warp-per-token LN + ent + quantum sim -> probs (fp16)
    token_quantum_kernel<<<NTOK / 8, 256>>>(ln_w, ln_b, ent_b);

    // 3) proj via mma.sync fp16, BKE=64, loader-warp specialization, 2 CTAs/SM
    proj_kernel<<<dim3(NTOK / BM, VOCAB_PAD / BN), NTHR, PROJ_SMEM>>>(proj_b, out);
}

// round 17
// speedup vs baseline: 9.6791x; 1.0143x over previous
#include <cuda_runtime.h>
#include <cuda_bf16.h>
#include <cuda_fp16.h>
#include <math.h>
#include <stdint.h>

#define HIDDEN 768
#define NTOK   4096
#define QDIM   1024
#define VOCAB  30522
#define VOCAB_PAD 30720
#define NANG   20

// ---------------- device scratch (allocation-free) ----------------
__device__ float  g_H[NTOK * HIDDEN];           // post-GELU dense output (fp32)
__device__ __half g_A_h[NTOK * QDIM];           // probs (fp16)
__device__ __half g_Wt_h[VOCAB_PAD * QDIM];     // proj_w^T fp16 (K-major)
__device__ __half g_Dh_hi[NTOK * HIDDEN];       // hidden fp16 hi
__device__ __half g_Dh_lo[NTOK * HIDDEN];       // hidden fp16 lo
__device__ __half g_Dw_hi[HIDDEN * HIDDEN];     // dense_w^T fp16 hi (K-major)
__device__ __half g_Dw_lo[HIDDEN * HIDDEN];     // dense_w^T fp16 lo
__device__ float  g_entT[NANG * HIDDEN];        // ent_w^T (coalesced reads)

// ---------------- portable PTX helpers (no sm_103a features) ----------------
static __device__ __forceinline__ uint32_t smem_u32(const void* p) {
    uint32_t a;
    asm("{ .reg .u64 t; cvta.to.shared.u64 t, %1; cvt.u32.u64 %0, t; }" : "=r"(a) : "l"(p));
    return a;
}
static __device__ __forceinline__ void cp_async16(uint32_t dst, const void* src) {
    asm volatile("cp.async.cg.shared.global [%0], [%1], 16;" :: "r"(dst), "l"(src) : "memory");
}
static __device__ __forceinline__ void cp_commit() {
    asm volatile("cp.async.commit_group;" ::: "memory");
}
static __device__ __forceinline__ void cp_wait2() {
    asm volatile("cp.async.wait_group 2;" ::: "memory");
}
static __device__ __forceinline__ void ldsm_x4(uint32_t* r, uint32_t addr) {
    asm volatile("ldmatrix.sync.aligned.m8n8.x4.shared.b16 {%0,%1,%2,%3}, [%4];"
                 : "=r"(r[0]), "=r"(r[1]), "=r"(r[2]), "=r"(r[3]) : "r"(addr));
}
static __device__ __forceinline__ void mma_f16(float* d, const uint32_t* a, const uint32_t* b) {
    asm volatile(
        "mma.sync.aligned.m16n8k16.row.col.f32.f16.f16.f32 "
        "{%0,%1,%2,%3}, {%4,%5,%6,%7}, {%8,%9}, {%0,%1,%2,%3};"
        : "+f"(d[0]), "+f"(d[1]), "+f"(d[2]), "+f"(d[3])
        : "r"(a[0]), "r"(a[1]), "r"(a[2]), "r"(a[3]), "r"(b[0]), "r"(b[1]));
}
// 128B-row XOR swizzle: 16B-column c at row r maps to c ^ (r & 7)
static __device__ __forceinline__ uint32_t swz(uint32_t row, uint32_t c16) {
    return row * 128u + ((c16 ^ (row & 7u)) * 16u);
}
// ---- mbarrier (sm_80/sm_90 portable; NOT an 'a'-suffix feature) ----
static __device__ __forceinline__ void mbar_init(uint32_t mbar, uint32_t cnt) {
    asm volatile("mbarrier.init.shared.b64 [%0], %1;" :: "r"(mbar), "r"(cnt) : "memory");
}
static __device__ __forceinline__ void mbar_arrive(uint32_t mbar) {
    asm volatile("{ .reg .b64 t; mbarrier.arrive.shared.b64 t, [%0]; }"
                 :: "r"(mbar) : "memory");
}
// CRITICAL: .noinc — default variant increments the pending count before the
// completion-arrive (net zero on the phase -> deadlock with fixed init count).
static __device__ __forceinline__ void cp_async_mbar_arrive(uint32_t mbar) {
    asm volatile("cp.async.mbarrier.arrive.noinc.shared.b64 [%0];" :: "r"(mbar) : "memory");
}
static __device__ __forceinline__ void mbar_wait(uint32_t mbar, uint32_t parity) {
    asm volatile(
        "{\n\t.reg .pred P;\n\t"
        "WL_%=:\n\t"
        "mbarrier.try_wait.parity.acquire.cta.shared::cta.b64 P, [%0], %1, 0x989680;\n\t"
        "@P bra.uni WD_%=;\n\t"
        "bra.uni WL_%=;\n\t"
        "WD_%=:\n\t}"
        :: "r"(mbar), "r"(parity) : "memory");
}

// ---------------------------------------------------------------------------
// Small conversion kernels (unchanged, passing)
// ---------------------------------------------------------------------------
__global__ void conv_h_kernel(const float* __restrict__ X) {  // hidden -> fp16 hi/lo
    int i = blockIdx.x * 256 + threadIdx.x;
    if (i < NTOK * HIDDEN) {
        float v = X[i];
        __half h = __float2half_rn(v);
        g_Dh_hi[i] = h;
        g_Dh_lo[i] = __float2half_rn(v - __half2float(h));
    }
}
__global__ void conv_dw_kernel(const float* __restrict__ W) { // dense_w [K,N] -> W^T hi/lo
    __shared__ float tile[32][33];
    int n0 = blockIdx.x * 32;
    int k0 = blockIdx.y * 32;
    int tx = threadIdx.x, ty = threadIdx.y;
    #pragma unroll
    for (int i = 0; i < 4; i++)
        tile[ty + 8 * i][tx] = W[(size_t)(k0 + ty + 8 * i) * HIDDEN + n0 + tx];
    __syncthreads();
    #pragma unroll
    for (int i = 0; i < 4; i++) {
        int n = n0 + ty + 8 * i;
        int k = k0 + tx;
        float v = tile[tx][ty + 8 * i];
        __half h = __float2half_rn(v);
        g_Dw_hi[(size_t)n * HIDDEN + k] = h;
        g_Dw_lo[(size_t)n * HIDDEN + k] = __float2half_rn(v - __half2float(h));
    }
}
__global__ void conv_entT_kernel(const float* __restrict__ E) { // ent_w [768,20] -> [20][768]
    int i = blockIdx.x * 256 + threadIdx.x;
    if (i < HIDDEN * NANG) {
        int k = i / NANG, j = i % NANG;
        g_entT[j * HIDDEN + k] = E[i];
    }
}
__global__ void conv_w_kernel(const float* __restrict__ W) {   // proj_w -> W^T fp16
    __shared__ float tile[32][33];
    int n0 = blockIdx.x * 32;
    int k0 = blockIdx.y * 32;
    int tx = threadIdx.x, ty = threadIdx.y;
    #pragma unroll
    for (int i = 0; i < 4; i++) {
        int k = k0 + ty + 8 * i;
        int n = n0 + tx;
        tile[ty + 8 * i][tx] = (n < VOCAB) ? W[(size_t)k * VOCAB + n] : 0.0f;
    }
    __syncthreads();
    #pragma unroll
    for (int i = 0; i < 4; i++) {
        int n = n0 + ty + 8 * i;
        int k = k0 + tx;
        g_Wt_h[(size_t)n * QDIM + k] = __float2half_rn(tile[tx][ty + 8 * i]);
    }
}

// ---------------------------------------------------------------------------
// Dense GEMM via mma.sync fp16 3-term split + GELU (unchanged, passing)
// ---------------------------------------------------------------------------
#define DROWB 80
#define DAHI 0
#define DALO (128 * DROWB)
#define DBHI (2 * 128 * DROWB)
#define DBLO (3 * 128 * DROWB)
#define DSTAGE (4 * 128 * DROWB)
#define DNSTAGE 4
#define DENSE_SMEM (DNSTAGE * DSTAGE)
#define DNCHUNK (HIDDEN / 32)

__global__ void __launch_bounds__(256, 1)
dense_mma_kernel(const float* __restrict__ bias, float* __restrict__ out) {
    extern __shared__ char dynsm[];
    const uint32_t smem0 = smem_u32(dynsm);

    const int tid = threadIdx.x;
    const int lane = tid & 31;
    const int wid = tid >> 5;
    const int warp_m = wid & 1;
    const int warp_n = wid >> 1;
    const int m0 = blockIdx.x * 128;
    const int n0 = blockIdx.y * 128;

    const __half* Ah = g_Dh_hi + (size_t)m0 * HIDDEN;
    const __half* Al = g_Dh_lo + (size_t)m0 * HIDDEN;
    const __half* Bh = g_Dw_hi + (size_t)n0 * HIDDEN;
    const __half* Bl = g_Dw_lo + (size_t)n0 * HIDDEN;

    auto load_stage = [&](int c) {
        const int k0 = c * 32;
        const uint32_t sb = smem0 + (c % DNSTAGE) * DSTAGE;
        #pragma unroll
        for (int it = 0; it < 2; it++) {
            int idx = it * 256 + tid;
            int row = idx >> 2, ch = idx & 3;
            size_t go = (size_t)row * HIDDEN + k0 + ch * 8;
            uint32_t so = row * DROWB + ch * 16;
            cp_async16(sb + DAHI + so, Ah + go);
            cp_async16(sb + DALO + so, Al + go);
            cp_async16(sb + DBHI + so, Bh + go);
            cp_async16(sb + DBLO + so, Bl + go);
        }
        cp_commit();
    };

    float acc[4][4][4];
    #pragma unroll
    for (int i = 0; i < 4; i++)
        #pragma unroll
        for (int j = 0; j < 4; j++)
            #pragma unroll
            for (int e = 0; e < 4; e++) acc[i][j][e] = 0.0f;

    load_stage(0);
    load_stage(1);
    load_stage(2);

    const int arow = warp_m * 64 + (lane & 15);
    const int ach = lane >> 4;
    const int bro = warp_n * 32 + (lane & 7) + ((lane >> 4) & 1) * 8;
    const int bkh = (lane >> 3) & 1;

    for (int c = 0; c < DNCHUNK; c++) {
        cp_wait2();
        __syncthreads();
        if (c + 3 < DNCHUNK) load_stage(c + 3);

        const uint32_t sb = smem0 + (c % DNSTAGE) * DSTAGE;
        #pragma unroll
        for (int ks = 0; ks < 2; ks++) {
            uint32_t ahi[4][4], alo[4][4];
            #pragma unroll
            for (int mi = 0; mi < 4; mi++) {
                uint32_t ao = (arow + mi * 16) * DROWB + (ks * 2 + ach) * 16;
                ldsm_x4(ahi[mi], sb + DAHI + ao);
                ldsm_x4(alo[mi], sb + DALO + ao);
            }
            uint32_t bh[2][4], bl[2][4];
            {
                uint32_t bo = bro * DROWB + (ks * 2 + bkh) * 16;
                ldsm_x4(bh[0], sb + DBHI + bo);
                ldsm_x4(bl[0], sb + DBLO + bo);
            }
            #pragma unroll
            for (int nj = 0; nj < 2; nj++) {
                const int cur = nj & 1, nxt = cur ^ 1;
                if (nj < 1) {
                    uint32_t bo = (bro + 16) * DROWB + (ks * 2 + bkh) * 16;
                    ldsm_x4(bh[nxt], sb + DBHI + bo);
                    ldsm_x4(bl[nxt], sb + DBLO + bo);
                }
                #pragma unroll
                for (int mi = 0; mi < 4; mi++)
                    #pragma unroll
                    for (int g = 0; g < 2; g++) {
                        float* ac = acc[mi][2 * nj + g];
                        mma_f16(ac, ahi[mi], &bh[cur][2 * g]);
                        mma_f16(ac, ahi[mi], &bl[cur][2 * g]);
                        mma_f16(ac, alo[mi], &bh[cur][2 * g]);
                    }
            }
        }
    }

    const int qr = lane >> 2;
    const int qc = (lane & 3) * 2;
    #pragma unroll
    for (int mi = 0; mi < 4; mi++) {
        #pragma unroll
        for (int ni = 0; ni < 4; ni++) {
            int row = m0 + warp_m * 64 + mi * 16 + qr;
            int col = n0 + warp_n * 32 + ni * 8 + qc;
            #pragma unroll
            for (int h = 0; h < 2; h++) {
                int r = row + h * 8;
                float v0 = acc[mi][ni][h * 2 + 0] + bias[col];
                float v1 = acc[mi][ni][h * 2 + 1] + bias[col + 1];
                v0 = 0.5f * v0 * (1.0f + erff(v0 * 0.70710678118654752f));
                v1 = 0.5f * v1 * (1.0f + erff(v1 * 0.70710678118654752f));
                float2 o = {v0, v1};
                *(float2*)(out + (size_t)r * HIDDEN + col) = o;
            }
        }
    }
}

// ---------------------------------------------------------------------------
// Warp-per-token quantum kernel (unchanged, passing)
// ---------------------------------------------------------------------------
__global__ void token_quantum_kernel(const float* __restrict__ ln_w,
                                     const float* __restrict__ ln_b,
                                     const float* __restrict__ ent_b) {
    const int lane = threadIdx.x & 31;
    const int wtok = threadIdx.x >> 5;
    const int t = blockIdx.x * 8 + wtok;

    __shared__ float sang[8][NANG];

    float hv[24];
    float s1 = 0.0f;
    const float* hrow = g_H + (size_t)t * HIDDEN;
    #pragma unroll
    for (int i = 0; i < 24; i++) { hv[i] = hrow[lane + 32 * i]; s1 += hv[i]; }
    #pragma unroll
    for (int o = 16; o; o >>= 1) s1 += __shfl_xor_sync(0xffffffffu, s1, o);
    float mean = s1 * (1.0f / HIDDEN);
    float s2 = 0.0f;
    #pragma unroll
    for (int i = 0; i < 24; i++) { float d = hv[i] - mean; s2 += d * d; }
    #pragma unroll
    for (int o = 16; o; o >>= 1) s2 += __shfl_xor_sync(0xffffffffu, s2, o);
    float rstd = rsqrtf(s2 * (1.0f / HIDDEN) + 1e-12f);
    #pragma unroll
    for (int i = 0; i < 24; i++)
        hv[i] = ln_w[lane + 32 * i] * ((hv[i] - mean) * rstd) + ln_b[lane + 32 * i];

    #pragma unroll 1
    for (int j = 0; j < NANG; j++) {
        float z = 0.0f;
        const float* ew = g_entT + (size_t)j * HIDDEN;
        #pragma unroll
        for (int i = 0; i < 24; i++) z += hv[i] * ew[lane + 32 * i];
        #pragma unroll
        for (int o = 16; o; o >>= 1) z += __shfl_xor_sync(0xffffffffu, z, o);
        if (lane == 0)
            sang[wtok][j] = 6.28318530717958647692f / (1.0f + expf(-(z + ent_b[j])));
    }
    __syncwarp();

    float re[32], im[32];
    #pragma unroll
    for (int j = 0; j < 32; j++) {
        re[j] = (lane == 0 && j == 0) ? 1.0f : 0.0f;
        im[j] = 0.0f;
    }

    #pragma unroll 1
    for (int l = 0; l < 2; l++) {
        #pragma unroll
        for (int q = 0; q < 10; q++) {
            const int pos = 9 - q;
            float th = sang[wtok][l * 10 + q] * 0.5f;
            float sv, cv;
            sincosf(th, &sv, &cv);
            if (pos >= 5) {
                const int lm = 1 << (pos - 5);
                #pragma unroll
                for (int j = 0; j < 32; j++) {
                    float pr = __shfl_xor_sync(0xffffffffu, re[j], lm);
                    float pi = __shfl_xor_sync(0xffffffffu, im[j], lm);
                    float nr = cv * re[j] + sv * pi;
                    float ni = cv * im[j] - sv * pr;
                    re[j] = nr; im[j] = ni;
                }
            } else {
                const int bit = 1 << pos;
                #pragma unroll
                for (int j = 0; j < 32; j++) {
                    if ((j & bit) == 0) {
                        const int j1 = j | bit;
                        float a0r = re[j], a0i = im[j], a1r = re[j1], a1i = im[j1];
                        re[j]  = cv * a0r + sv * a1i;
                        im[j]  = cv * a0i - sv * a1r;
                        re[j1] = cv * a1r + sv * a0i;
                        im[j1] = cv * a1i - sv * a0r;
                    }
                }
            }
        }
        #pragma unroll
        for (int q = 0; q < 10; q++) {
            const int tq = (q + 1) % 10;
            const int cpos = 9 - q;
            const int tpos = 9 - tq;
            if (tpos >= 5) {
                const int lm = 1 << (tpos - 5);
                #pragma unroll
                for (int j = 0; j < 32; j++) {
                    float pr = __shfl_xor_sync(0xffffffffu, re[j], lm);
                    float pi = __shfl_xor_sync(0xffffffffu, im[j], lm);
                    int cb = (cpos >= 5) ? ((lane >> (cpos - 5)) & 1) : ((j >> cpos) & 1);
                    if (cb) { re[j] = pr; im[j] = pi; }
                }
            } else {
                const int tb = 1 << tpos;
                if (cpos >= 5) {
                    const int cb = (lane >> (cpos - 5)) & 1;
                    #pragma unroll
                    for (int j = 0; j < 32; j++) {
                        if ((j & tb) == 0) {
                            const int j1 = j | tb;
                            float tr = re[j], ti = im[j];
                            if (cb) {
                                re[j] = re[j1]; im[j] = im[j1];
                                re[j1] = tr;    im[j1] = ti;
                            }
                        }
                    }
                } else {
                    #pragma unroll
                    for (int j = 0; j < 32; j++) {
                        if (((j >> cpos) & 1) && ((j & tb) == 0)) {
                            const int j1 = j | tb;
                            float tr = re[j]; re[j] = re[j1]; re[j1] = tr;
                            float ti = im[j]; im[j] = im[j1]; im[j1] = ti;
                        }
                    }
                }
            }
        }
    }

    __half2* outp = (__half2*)(g_A_h + (size_t)t * QDIM + lane * 32);
    #pragma unroll
    for (int j = 0; j < 32; j += 2) {
        float p0 = re[j] * re[j] + im[j] * im[j];
        float p1 = re[j + 1] * re[j + 1] + im[j + 1] * im[j + 1];
        outp[j >> 1] = __floats2half2_rn(p0, p1);
    }
}

// ---------------------------------------------------------------------------
// Proj GEMM via mma.sync fp16: out = A @ B + bias
// BM=128, BN=128, BKE=64; 8 warps, warp tile 64x32; 2 CTAs/SM; 3-stage ring.
// mbarrier producer/consumer flow control — no __syncthreads in the mainloop.
// full[s] (count 128): loader threads arm via cp.async.mbarrier.arrive.NOINC
// (fires on HW completion; .noinc is load-bearing — default variant nets zero).
// free[s] (count 256): all threads arrive after consuming a stage.
// ---------------------------------------------------------------------------
#define BM 128
#define BN 128
#define BKE 64
#define NCHUNK (QDIM / BKE)
#define NSTAGE 3
#define NTHR 256
#define AHI 0
#define BHI 16384
#define STAGE 32768
#define MBAR_OFF (NSTAGE * STAGE)
#define PROJ_SMEM (NSTAGE * STAGE + 64)

__global__ void __launch_bounds__(NTHR, 2)
proj_kernel(const float* __restrict__ bias, float* __restrict__ out) {
    extern __shared__ char dynsm[];
    const uint32_t smem0 = smem_u32(dynsm);
    const uint32_t mb_full = smem0 + MBAR_OFF;       // 3 x 8B
    const uint32_t mb_free = smem0 + MBAR_OFF + 24;  // 3 x 8B

    const int tid = threadIdx.x;
    const int lane = tid & 31;
    const int wid = tid >> 5;
    const int warp_m = wid & 1;
    const int warp_n = wid >> 1;
    const int m0 = blockIdx.x * BM;
    const int n0 = blockIdx.y * BN;

    const __half* Ahg = g_A_h + (size_t)m0 * QDIM;
    const __half* Bhg = g_Wt_h + (size_t)n0 * QDIM;

    if (tid == 0) {
        #pragma unroll
        for (int s = 0; s < NSTAGE; s++) {
            mbar_init(mb_full + s * 8, 128);  // loader threads
            mbar_init(mb_free + s * 8, 256);  // all threads
        }
    }
    __syncthreads();

    // Loader threads (tid<128) fill stage c%3 for chunk c, then arm full[] via
    // cp.async completion-arrive (.noinc).
    auto load_stage = [&](int c) {
        const int k0 = c * BKE;
        const uint32_t sb = smem0 + (c % NSTAGE) * STAGE;
        #pragma unroll
        for (int it = 0; it < 8; it++) {
            int idx = it * 128 + tid;          // tid < 128
            int row = idx >> 3, ch = idx & 7;
            size_t go = (size_t)row * QDIM + k0 + ch * 8;
            uint32_t so = swz(row, ch);
            cp_async16(sb + AHI + so, Ahg + go);
            cp_async16(sb + BHI + so, Bhg + go);
        }
        cp_async_mbar_arrive(mb_full + (c % NSTAGE) * 8);
    };

    float acc[4][4][4];
    #pragma unroll
    for (int i = 0; i < 4; i++)
        #pragma unroll
        for (int j = 0; j < 4; j++)
            #pragma unroll
            for (int e = 0; e < 4; e++) acc[i][j][e] = 0.0f;

    if (tid < 128) {
        load_stage(0);
        load_stage(1);
    }

    const int arow = warp_m * 64 + (lane & 15);
    const int ach = lane >> 4;
    const int bro = warp_n * 32 + (lane & 7) + ((lane >> 4) & 1) * 8;
    const int bkh = (lane >> 3) & 1;

    for (int c = 0; c < NCHUNK; c++) {
        // Loader role: issue chunk c+2 into stage (c+2)%3 once that stage's
        // previous use (chunk c-1) has been fully consumed.
        if (tid < 128 && c + 2 < NCHUNK) {
            const int cn = c + 2;
            if (cn >= NSTAGE)
                mbar_wait(mb_free + (cn % NSTAGE) * 8, (uint32_t)((cn / 3 - 1) & 1));
            load_stage(cn);
        }

        // Consumer role: wait for chunk c's data (per-warp, no CTA barrier).
        mbar_wait(mb_full + (c % NSTAGE) * 8, (uint32_t)((c / 3) & 1));

        const uint32_t sb = smem0 + (c % NSTAGE) * STAGE;
        #pragma unroll
        for (int ks = 0; ks < 4; ks++) {
            uint32_t ahi[4][4];
            #pragma unroll
            for (int mi = 0; mi < 4; mi++)
                ldsm_x4(ahi[mi], sb + AHI + swz(arow + mi * 16, ks * 2 + ach));
            uint32_t bh[2][4];
            ldsm_x4(bh[0], sb + BHI + swz(bro, ks * 2 + bkh));
            #pragma unroll
            for (int nj = 0; nj < 2; nj++) {
                const int cur = nj & 1, nxt = cur ^ 1;
                if (nj < 1)
                    ldsm_x4(bh[nxt], sb + BHI + swz(bro + 16, ks * 2 + bkh));
                #pragma unroll
                for (int mi = 0; mi < 4; mi++)
                    #pragma unroll
                    for (int g = 0; g < 2; g++)
                        mma_f16(acc[mi][2 * nj + g], ahi[mi], &bh[cur][2 * g]);
            }
        }
        // Stage c consumed by this thread.
        mbar_arrive(mb_free + (c % NSTAGE) * 8);
    }

    const int qr = lane >> 2;
    const int qc = (lane & 3) * 2;
    #pragma unroll
    for (int mi = 0; mi < 4; mi++) {
        #pragma unroll
        for (int ni = 0; ni < 4; ni++) {
            int row = m0 + warp_m * 64 + mi * 16 + qr;
            int col = n0 + warp_n * 32 + ni * 8 + qc;
            #pragma unroll
            for (int h = 0; h < 2; h++) {
                int r = row + h * 8;
                float v0 = acc[mi][ni][h * 2 + 0];
                float v1 = acc[mi][ni][h * 2 + 1];
                if (col + 1 < VOCAB) {
                    float2 o;
                    o.x = v0 + bias[col];
                    o.y = v1 + bias[col + 1];
                    *(float2*)(out + (size_t)r * VOCAB + col) = o;
                } else if (col < VOCAB) {
                    out[(size_t)r * VOCAB + col] = v0 + bias[col];
                }
            }
        }
    }
}

// ---------------------------------------------------------------------------
extern "C" void kernel_launch(void* const* d_in, const int* in_sizes, int n_in,
                              void* d_out, int out_size) {
    const float* hidden  = (const float*)d_in[0];
    const float* dense_w = (const float*)d_in[1];
    const float* dense_b = (const float*)d_in[2];
    const float* ln_w    = (const float*)d_in[3];
    const float* ln_b    = (const float*)d_in[4];
    const float* ent_w   = (const float*)d_in[5];
    const float* ent_b   = (const float*)d_in[6];
    const float* proj_w  = (const float*)d_in[7];
    const float* proj_b  = (const float*)d_in[8];
    float* out = (float*)d_out;

    float* Hptr = nullptr;
    cudaGetSymbolAddress((void**)&Hptr, g_H);

    cudaFuncSetAttribute(proj_kernel, cudaFuncAttributeMaxDynamicSharedMemorySize, PROJ_SMEM);
    cudaFuncSetAttribute(dense_mma_kernel, cudaFuncAttributeMaxDynamicSharedMemorySize, DENSE_SMEM);

    // 0) conversions (independent)
    conv_w_kernel<<<dim3((VOCAB + 31) / 32, QDIM / 32), dim3(32, 8)>>>(proj_w);
    conv_h_kernel<<<(NTOK * HIDDEN + 255) / 256, 256>>>(hidden);
    conv_dw_kernel<<<dim3(HIDDEN / 32, HIDDEN / 32), dim3(32, 8)>>>(dense_w);
    conv_entT_kernel<<<(HIDDEN * NANG + 255) / 256, 256>>>(ent_w);

    // 1) dense + GELU via fp16 3-term HMMA
    dense_mma_kernel<<<dim3(NTOK / 128, HIDDEN / 128), 256, DENSE_SMEM>>>(dense_b, Hptr);

    // 2) warp-per-token LN + ent + quantum sim -> probs (fp16)
    token_quantum_kernel<<<NTOK / 8, 256>>>(ln_w, ln_b, ent_b);

    // 3) proj via mma.sync fp16, mbarrier producer/consumer pipeline, 2 CTAs/SM
    proj_kernel<<<dim3(NTOK / BM, VOCAB_PAD / BN), NTHR, PROJ_SMEM>>>(proj_b, out);
}